// round 10
// baseline (speedup 1.0000x reference)
#include <cuda_runtime.h>
#include <cuda_fp16.h>
#include <cstdint>

#define NN 100000
#define NE 1600000
#define NB_SCAN 98   // ceil(NN/1024)

// ---------------- scratch (device globals; no allocation allowed) ----------
__device__ float g_h1[(size_t)NN * 512];   // h1 as fp16 (aliased)
__device__ float g_h2[(size_t)NN * 256];   // xh (fp16) first, then h2 fp16
__device__ float g_hA[(size_t)NN * 64];    // fp16 node features (aliased)
__device__ float g_hB[(size_t)NN * 64];    // fp16 agg (aliased)
__device__ float g_degf[NN];
__device__ float g_nrm[2 * NN];      // [0..NN)=norm_src, [NN..2NN)=norm_dst
__device__ int   g_cnt[NN];
__device__ int   g_rowptr[NN];
__device__ int   g_cursor[NN];
__device__ int   g_bsum[128];
__device__ int   g_col[NE];
// transposed fp16 weights: Wt[n][k] = W[k][n]
__device__ __half g_w1t[512 * 512];
__device__ __half g_w2t[256 * 512];
__device__ __half g_w3t[64 * 256];
__device__ __half g_wgt[4][64 * 64];   // Wg1..Wg4 (Wg4 zero-padded)

// ---------------- utility kernels -------------------------------------------
__global__ void zero_fi(float* __restrict__ pf, int* __restrict__ pi, int n) {
    int i = blockIdx.x * blockDim.x + threadIdx.x;
    if (i < n) { pf[i] = 0.0f; pi[i] = 0; }
}
__global__ void deg_hist_kernel(const int* __restrict__ src, const int* __restrict__ dst,
                                float* __restrict__ degf, int* __restrict__ cnt) {
    int e = blockIdx.x * blockDim.x + threadIdx.x;
    if (e < NE) {
        atomicAdd(&degf[src[e]], 1.0f);
        atomicAdd(&cnt[dst[e]], 1);
    }
}

__device__ __forceinline__ uint32_t packh2(float lo, float hi) {
    uint32_t r;
    asm("cvt.rn.f16x2.f32 %0, %1, %2;" : "=r"(r) : "f"(hi), "f"(lo));
    return r;
}

__global__ void cvt_f2h(const float* __restrict__ in, __half* __restrict__ out, int n4) {
    int i = blockIdx.x * blockDim.x + threadIdx.x;
    if (i < n4) {
        float4 v = ((const float4*)in)[i];
        uint2 o;
        o.x = packh2(v.x, v.y);
        o.y = packh2(v.z, v.w);
        ((uint2*)out)[i] = o;
    }
}

// W [K,N] fp32 -> Wt [Npad,K] fp16
__global__ void wcvt_kernel(const float* __restrict__ W, __half* __restrict__ Wt,
                            int K, int N, int Npad) {
    int i = blockIdx.x * blockDim.x + threadIdx.x;
    if (i < Npad * K) {
        int n = i / K, k = i % K;
        Wt[i] = (n < N) ? __float2half(W[(size_t)k * N + n]) : __half(0.f);
    }
}
// merged convert: W3 [256,64] -> w3t [64,256]  +  four GC weights -> g_wgt
__global__ void wcvt3g_kernel(const float* __restrict__ W3, __half* __restrict__ w3t,
                              const float* __restrict__ Wg1, const float* __restrict__ Wg2,
                              const float* __restrict__ Wg3, const float* __restrict__ Wg4,
                              __half* __restrict__ Wt) {
    int i = blockIdx.x * blockDim.x + threadIdx.x;
    if (i < 64 * 256) {
        int n = i / 256, k = i % 256;
        w3t[i] = __float2half(W3[(size_t)k * 64 + n]);
    } else if (i < 64 * 256 + 4 * 64 * 64) {
        int j = i - 64 * 256;
        int which = j >> 12;
        int r = j & 4095;
        int n = r >> 6, k = r & 63;
        const float* W = (which == 0) ? Wg1 : (which == 1) ? Wg2 : (which == 2) ? Wg3 : Wg4;
        int N = (which == 3) ? 40 : 64;
        Wt[j] = (n < N) ? __float2half(W[(size_t)k * N + n]) : __half(0.f);
    }
}

// ---------------- CSR build (scan1 also computes norms) ----------------------
__global__ void scan1(const int* __restrict__ cnt, int* __restrict__ excl,
                      int* __restrict__ bsum, const float* __restrict__ degf,
                      float* __restrict__ nrm) {
    __shared__ int sh[1024];
    int tid = threadIdx.x;
    int i = blockIdx.x * 1024 + tid;
    int v = (i < NN) ? cnt[i] : 0;
    if (i < NN) {
        nrm[i] = rsqrtf(fmaxf(degf[i], 1.0f));
        nrm[NN + i] = rsqrtf(fmaxf((float)v, 1.0f));
    }
    sh[tid] = v;
    __syncthreads();
    for (int off = 1; off < 1024; off <<= 1) {
        int t = (tid >= off) ? sh[tid - off] : 0;
        __syncthreads();
        sh[tid] += t;
        __syncthreads();
    }
    if (i < NN) excl[i] = sh[tid] - v;
    if (tid == 1023) bsum[blockIdx.x] = sh[1023];
}
__global__ void scan2(int* __restrict__ bsum) {
    __shared__ int sh[128];
    int tid = threadIdx.x;
    int v = (tid < NB_SCAN) ? bsum[tid] : 0;
    sh[tid] = v;
    __syncthreads();
    for (int off = 1; off < 128; off <<= 1) {
        int t = (tid >= off) ? sh[tid - off] : 0;
        __syncthreads();
        sh[tid] += t;
        __syncthreads();
    }
    if (tid < NB_SCAN) bsum[tid] = sh[tid] - v;
}
__global__ void scan3(int* __restrict__ excl, const int* __restrict__ bsum,
                      int* __restrict__ cursor) {
    int i = blockIdx.x * 1024 + threadIdx.x;
    if (i < NN) {
        int r = excl[i] + bsum[blockIdx.x];
        excl[i] = r;
        cursor[i] = r;
    }
}
__global__ void fill_csr(const int* __restrict__ src, const int* __restrict__ dst,
                         int* __restrict__ cursor, int* __restrict__ col) {
    int e = blockIdx.x * blockDim.x + threadIdx.x;
    if (e < NE) {
        int p = atomicAdd(&cursor[dst[e]], 1);
        col[p] = src[e];
    }
}

// ---------------- CSR gather (fp16 rows, fp32 accumulate, 4x unrolled) -------
__global__ void gather_h(const __half* __restrict__ h, const int* __restrict__ rowptr,
                         const int* __restrict__ col, __half* __restrict__ agg) {
    int t = threadIdx.x;
    int node = blockIdx.x * 32 + (t >> 3);
    if (node >= NN) return;
    int c = t & 7;
    int beg = rowptr[node];
    int end = (node == NN - 1) ? NE : rowptr[node + 1];
    float acc[8] = {0.f, 0.f, 0.f, 0.f, 0.f, 0.f, 0.f, 0.f};
    int i = beg;
    for (; i + 3 < end; i += 4) {
        int s0 = __ldg(&col[i]);
        int s1 = __ldg(&col[i + 1]);
        int s2 = __ldg(&col[i + 2]);
        int s3 = __ldg(&col[i + 3]);
        uint4 v0 = ((const uint4*)(h + (size_t)s0 * 64))[c];
        uint4 v1 = ((const uint4*)(h + (size_t)s1 * 64))[c];
        uint4 v2 = ((const uint4*)(h + (size_t)s2 * 64))[c];
        uint4 v3 = ((const uint4*)(h + (size_t)s3 * 64))[c];
        const __half2* a0 = (const __half2*)&v0;
        const __half2* a1 = (const __half2*)&v1;
        const __half2* a2 = (const __half2*)&v2;
        const __half2* a3 = (const __half2*)&v3;
#pragma unroll
        for (int j = 0; j < 4; j++) {
            float2 f0 = __half22float2(a0[j]);
            float2 f1 = __half22float2(a1[j]);
            float2 f2 = __half22float2(a2[j]);
            float2 f3 = __half22float2(a3[j]);
            acc[2 * j]     += (f0.x + f1.x) + (f2.x + f3.x);
            acc[2 * j + 1] += (f0.y + f1.y) + (f2.y + f3.y);
        }
    }
    for (; i < end; i++) {
        int s = __ldg(&col[i]);
        uint4 v = ((const uint4*)(h + (size_t)s * 64))[c];
        const __half2* hv = (const __half2*)&v;
#pragma unroll
        for (int j = 0; j < 4; j++) {
            float2 f = __half22float2(hv[j]);
            acc[2 * j] += f.x;
            acc[2 * j + 1] += f.y;
        }
    }
    uint4 o;
    o.x = packh2(acc[0], acc[1]);
    o.y = packh2(acc[2], acc[3]);
    o.z = packh2(acc[4], acc[5]);
    o.w = packh2(acc[6], acc[7]);
    ((uint4*)(agg + (size_t)node * 64))[c] = o;
}

// ---------------- common async copy helper ----------------------------------
__device__ __forceinline__ void cp_async16(uint32_t saddr, const void* gaddr, int sz) {
    asm volatile("cp.async.cg.shared.global [%0], [%1], 16, %2;\n"
                 :: "r"(saddr), "l"(gaddr), "r"(sz));
}

// ============================================================================
// fp16 TC GEMM (wide): C = relu(A @ Wt^T + b), CTA tile 128x256x32,
// 8 warps (2x4), warp tile 64x64. N must be a multiple of 256.
// Halved smem-bytes/MAC vs 128x128 tiling (A-tile x4 + B-tile x2 per 2x MACs).
// ============================================================================
__global__ void __launch_bounds__(256, 1)
gemm_f16w(const __half* __restrict__ A, const __half* __restrict__ Wt,
          const float* __restrict__ bias, __half* __restrict__ Cout,
          int M, int N, int K) {
    constexpr int STRIDE_H = 40;
    constexpr int A_BYTES = 128 * STRIDE_H * 2;   // 10240
    constexpr int B_BYTES = 256 * STRIDE_H * 2;   // 20480
    constexpr int STAGE_BYTES = A_BYTES + B_BYTES;
    extern __shared__ char dsm[];
    uint32_t smem_u = (uint32_t)__cvta_generic_to_shared(dsm);

    const int tid = threadIdx.x;
    const int lane = tid & 31;
    const int warp = tid >> 5;
    const int wm = (warp >> 2) * 64;   // 2 row groups
    const int wn = (warp & 3) * 64;    // 4 col groups
    const int rowBase = blockIdx.y * 128;
    const int colBase = blockIdx.x * 256;
    const int KT = K / 32;

    const int lrow = lane & 7;
    const int sub = lane >> 3;
    const int subB = sub & 1;

    float acc[4][8][4];
#pragma unroll
    for (int i = 0; i < 4; i++)
#pragma unroll
        for (int j = 0; j < 8; j++)
#pragma unroll
            for (int q = 0; q < 4; q++) acc[i][j][q] = 0.0f;

    // loaders: A 512 chunks (2/thread), B 1024 chunks (4/thread)
    auto issue = [&](int stage, int kt) {
        const int k0 = kt * 32;
        uint32_t base = smem_u + stage * STAGE_BYTES;
#pragma unroll
        for (int i = 0; i < 2; i++) {
            int idx = tid + i * 256;
            int m = idx >> 2;
            int cq = idx & 3;
            const __half* gsrc = A + (size_t)(rowBase + m) * K + k0 + cq * 8;
            cp_async16(base + (m * STRIDE_H + cq * 8) * 2, gsrc,
                       (rowBase + m < M) ? 16 : 0);
        }
#pragma unroll
        for (int i = 0; i < 4; i++) {
            int idx = tid + i * 256;
            int n = idx >> 2;
            int cq = idx & 3;
            const __half* gsrc = Wt + (size_t)(colBase + n) * K + k0 + cq * 8;
            cp_async16(base + A_BYTES + (n * STRIDE_H + cq * 8) * 2, gsrc, 16);
        }
    };

#pragma unroll
    for (int p = 0; p < 2; p++) {
        issue(p, p);
        asm volatile("cp.async.commit_group;\n" ::: "memory");
    }

    for (int kt = 0; kt < KT; kt++) {
        asm volatile("cp.async.wait_group 1;\n" ::: "memory");
        __syncthreads();
        const int stage = kt % 3;
        uint32_t As_u = smem_u + stage * STAGE_BYTES;
        uint32_t Bs_u = As_u + A_BYTES;

#pragma unroll
        for (int ks = 0; ks < 2; ks++) {
            const int kb = ks * 16;
            uint32_t a[4][4], b[8][2];
#pragma unroll
            for (int mt = 0; mt < 4; mt++) {
                int r = wm + mt * 16 + (sub & 1) * 8 + lrow;
                uint32_t addr = As_u + (r * STRIDE_H + kb + (sub >> 1) * 8) * 2;
                asm volatile(
                    "ldmatrix.sync.aligned.m8n8.x4.shared.b16 {%0,%1,%2,%3}, [%4];"
                    : "=r"(a[mt][0]), "=r"(a[mt][1]), "=r"(a[mt][2]), "=r"(a[mt][3])
                    : "r"(addr));
            }
#pragma unroll
            for (int nt = 0; nt < 8; nt++) {
                int n = wn + nt * 8 + lrow;
                uint32_t addr = Bs_u + (n * STRIDE_H + kb + subB * 8) * 2;
                asm volatile(
                    "ldmatrix.sync.aligned.m8n8.x2.shared.b16 {%0,%1}, [%2];"
                    : "=r"(b[nt][0]), "=r"(b[nt][1]) : "r"(addr));
            }
#pragma unroll
            for (int mt = 0; mt < 4; mt++)
#pragma unroll
                for (int nt = 0; nt < 8; nt++) {
                    asm volatile(
                        "mma.sync.aligned.m16n8k16.row.col.f32.f16.f16.f32 "
                        "{%0,%1,%2,%3}, {%4,%5,%6,%7}, {%8,%9}, {%0,%1,%2,%3};"
                        : "+f"(acc[mt][nt][0]), "+f"(acc[mt][nt][1]),
                          "+f"(acc[mt][nt][2]), "+f"(acc[mt][nt][3])
                        : "r"(a[mt][0]), "r"(a[mt][1]), "r"(a[mt][2]), "r"(a[mt][3]),
                          "r"(b[nt][0]), "r"(b[nt][1]));
                }
        }
        if (kt + 2 < KT) issue((kt + 2) % 3, kt + 2);
        asm volatile("cp.async.commit_group;\n" ::: "memory");
    }

    const int g = lane >> 2;
    const int tq = lane & 3;
#pragma unroll
    for (int mt = 0; mt < 4; mt++) {
        int r0 = rowBase + wm + mt * 16 + g;
        int r1 = r0 + 8;
#pragma unroll
        for (int nt = 0; nt < 8; nt++) {
            int c = colBase + wn + nt * 8 + 2 * tq;
            float bx = __ldg(&bias[c]);
            float by = __ldg(&bias[c + 1]);
            if (r0 < M)
                *(uint32_t*)(Cout + (size_t)r0 * N + c) =
                    packh2(fmaxf(acc[mt][nt][0] + bx, 0.f), fmaxf(acc[mt][nt][1] + by, 0.f));
            if (r1 < M)
                *(uint32_t*)(Cout + (size_t)r1 * N + c) =
                    packh2(fmaxf(acc[mt][nt][2] + bx, 0.f), fmaxf(acc[mt][nt][3] + by, 0.f));
        }
    }
}

// ============================================================================
// fp16 tensor-core GEMM (narrow): tile 128x64, BK=64, row scales rs/ws.
// ============================================================================
template <bool OUT_HALF>
__global__ void __launch_bounds__(256, 2)
gemm_f16_s(const __half* __restrict__ A, const __half* __restrict__ Wt,
           const float* __restrict__ bias, const float* __restrict__ rs,
           const float* __restrict__ ws, void* __restrict__ Cout,
           int M, int N, int K) {
    constexpr int STRIDE_H = 72;
    constexpr int A_BYTES = 128 * STRIDE_H * 2;
    constexpr int B_BYTES = 64 * STRIDE_H * 2;
    constexpr int STAGE_BYTES = A_BYTES + B_BYTES;
    extern __shared__ char dsm[];
    uint32_t smem_u = (uint32_t)__cvta_generic_to_shared(dsm);

    const int tid = threadIdx.x;
    const int lane = tid & 31;
    const int warp = tid >> 5;
    const int wm = (warp >> 1) * 32;
    const int wn = (warp & 1) * 32;
    const int rowBase = blockIdx.y * 128;
    const int KT = K / 64;

    const int lrow = lane & 7;
    const int sub = lane >> 3;
    const int subB = sub & 1;

    float acc[2][4][4];
#pragma unroll
    for (int i = 0; i < 2; i++)
#pragma unroll
        for (int j = 0; j < 4; j++)
#pragma unroll
            for (int q = 0; q < 4; q++) acc[i][j][q] = 0.0f;

    auto issue = [&](int stage, int kt) {
        const int k0 = kt * 64;
        uint32_t base = smem_u + stage * STAGE_BYTES;
#pragma unroll
        for (int i = 0; i < 4; i++) {
            int idx = tid + i * 256;
            int m = idx >> 3;
            int cq = idx & 7;
            const __half* gsrc = A + (size_t)(rowBase + m) * K + k0 + cq * 8;
            cp_async16(base + m * 144 + cq * 16, gsrc, (rowBase + m < M) ? 16 : 0);
        }
#pragma unroll
        for (int i = 0; i < 2; i++) {
            int idx = tid + i * 256;
            int n = idx >> 3;
            int cq = idx & 7;
            const __half* gsrc = Wt + (size_t)n * K + k0 + cq * 8;
            cp_async16(base + A_BYTES + n * 144 + cq * 16, gsrc, 16);
        }
    };

#pragma unroll
    for (int p = 0; p < 2; p++) {
        if (p < KT) issue(p, p);
        asm volatile("cp.async.commit_group;\n" ::: "memory");
    }

    for (int kt = 0; kt < KT; kt++) {
        asm volatile("cp.async.wait_group 1;\n" ::: "memory");
        __syncthreads();
        const int stage = kt % 3;
        uint32_t As_u = smem_u + stage * STAGE_BYTES;
        uint32_t Bs_u = As_u + A_BYTES;

#pragma unroll
        for (int ks = 0; ks < 4; ks++) {
            const int kb = ks * 16;
            uint32_t a[2][4], b[4][2];
#pragma unroll
            for (int mt = 0; mt < 2; mt++) {
                int r = wm + mt * 16 + (sub & 1) * 8 + lrow;
                uint32_t addr = As_u + (r * STRIDE_H + kb + (sub >> 1) * 8) * 2;
                asm volatile(
                    "ldmatrix.sync.aligned.m8n8.x4.shared.b16 {%0,%1,%2,%3}, [%4];"
                    : "=r"(a[mt][0]), "=r"(a[mt][1]), "=r"(a[mt][2]), "=r"(a[mt][3])
                    : "r"(addr));
            }
#pragma unroll
            for (int nt = 0; nt < 4; nt++) {
                int n = wn + nt * 8 + lrow;
                uint32_t addr = Bs_u + (n * STRIDE_H + kb + subB * 8) * 2;
                asm volatile(
                    "ldmatrix.sync.aligned.m8n8.x2.shared.b16 {%0,%1}, [%2];"
                    : "=r"(b[nt][0]), "=r"(b[nt][1]) : "r"(addr));
            }
#pragma unroll
            for (int mt = 0; mt < 2; mt++)
#pragma unroll
                for (int nt = 0; nt < 4; nt++) {
                    asm volatile(
                        "mma.sync.aligned.m16n8k16.row.col.f32.f16.f16.f32 "
                        "{%0,%1,%2,%3}, {%4,%5,%6,%7}, {%8,%9}, {%0,%1,%2,%3};"
                        : "+f"(acc[mt][nt][0]), "+f"(acc[mt][nt][1]),
                          "+f"(acc[mt][nt][2]), "+f"(acc[mt][nt][3])
                        : "r"(a[mt][0]), "r"(a[mt][1]), "r"(a[mt][2]), "r"(a[mt][3]),
                          "r"(b[nt][0]), "r"(b[nt][1]));
                }
        }
        if (kt + 2 < KT) issue((kt + 2) % 3, kt + 2);
        asm volatile("cp.async.commit_group;\n" ::: "memory");
    }

    const int g = lane >> 2;
    const int tq = lane & 3;
#pragma unroll
    for (int mt = 0; mt < 2; mt++) {
        int r0 = rowBase + wm + mt * 16 + g;
        int r1 = r0 + 8;
        float rs0 = 1.f, rs1 = 1.f, ws0 = 1.f, ws1 = 1.f;
        if (rs) {
            if (r0 < M) rs0 = rs[r0];
            if (r1 < M) rs1 = rs[r1];
        }
        if (ws) {
            if (r0 < M) ws0 = ws[r0];
            if (r1 < M) ws1 = ws[r1];
        }
#pragma unroll
        for (int nt = 0; nt < 4; nt++) {
            int c = wn + nt * 8 + 2 * tq;
            float bx = (c < N) ? __ldg(&bias[c]) : 0.f;
            float by = (c + 1 < N) ? __ldg(&bias[c + 1]) : 0.f;
            if (r0 < M) {
                float vx = ws0 * fmaxf(acc[mt][nt][0] * rs0 + bx, 0.f);
                float vy = ws0 * fmaxf(acc[mt][nt][1] * rs0 + by, 0.f);
                if (OUT_HALF) {
                    if (c + 1 < N)
                        *(uint32_t*)((__half*)Cout + (size_t)r0 * N + c) = packh2(vx, vy);
                } else {
                    if (c + 1 < N)
                        *(float2*)((float*)Cout + (size_t)r0 * N + c) = make_float2(vx, vy);
                    else if (c < N)
                        ((float*)Cout)[(size_t)r0 * N + c] = vx;
                }
            }
            if (r1 < M) {
                float vx = ws1 * fmaxf(acc[mt][nt][2] * rs1 + bx, 0.f);
                float vy = ws1 * fmaxf(acc[mt][nt][3] * rs1 + by, 0.f);
                if (OUT_HALF) {
                    if (c + 1 < N)
                        *(uint32_t*)((__half*)Cout + (size_t)r1 * N + c) = packh2(vx, vy);
                } else {
                    if (c + 1 < N)
                        *(float2*)((float*)Cout + (size_t)r1 * N + c) = make_float2(vx, vy);
                    else if (c < N)
                        ((float*)Cout)[(size_t)r1 * N + c] = vx;
                }
            }
        }
    }
}

// ---------------- host orchestration ---------------------------------------
extern "C" void kernel_launch(void* const* d_in, const int* in_sizes, int n_in,
                              void* d_out, int out_size) {
    const float* x   = (const float*)d_in[0];
    const int* src   = (const int*)d_in[1];
    const int* dst   = (const int*)d_in[2];
    const float* W1  = (const float*)d_in[3];
    const float* b1  = (const float*)d_in[4];
    const float* W2  = (const float*)d_in[5];
    const float* b2  = (const float*)d_in[6];
    const float* W3  = (const float*)d_in[7];
    const float* b3  = (const float*)d_in[8];
    const float* Wg1 = (const float*)d_in[9];
    const float* bg1 = (const float*)d_in[10];
    const float* Wg2 = (const float*)d_in[11];
    const float* bg2 = (const float*)d_in[12];
    const float* Wg3 = (const float*)d_in[13];
    const float* bg3 = (const float*)d_in[14];
    const float* Wg4 = (const float*)d_in[15];
    const float* bg4 = (const float*)d_in[16];
    float* out = (float*)d_out;

    float *h1, *h2, *hA, *hB, *degf, *nrm;
    int *cnt, *rowptr, *cursor, *bsum, *col;
    __half *w1t, *w2t, *w3t, *wgt;
    cudaGetSymbolAddress((void**)&h1, g_h1);
    cudaGetSymbolAddress((void**)&h2, g_h2);
    cudaGetSymbolAddress((void**)&hA, g_hA);
    cudaGetSymbolAddress((void**)&hB, g_hB);
    cudaGetSymbolAddress((void**)&degf, g_degf);
    cudaGetSymbolAddress((void**)&nrm, g_nrm);
    cudaGetSymbolAddress((void**)&cnt, g_cnt);
    cudaGetSymbolAddress((void**)&rowptr, g_rowptr);
    cudaGetSymbolAddress((void**)&cursor, g_cursor);
    cudaGetSymbolAddress((void**)&bsum, g_bsum);
    cudaGetSymbolAddress((void**)&col, g_col);
    cudaGetSymbolAddress((void**)&w1t, g_w1t);
    cudaGetSymbolAddress((void**)&w2t, g_w2t);
    cudaGetSymbolAddress((void**)&w3t, g_w3t);
    cudaGetSymbolAddress((void**)&wgt, g_wgt);

    __half* xh  = (__half*)h2;   // x fp16 staged in g_h2 (dead after GEMM1)
    __half* h1h = (__half*)h1;
    __half* h2h = (__half*)h2;   // reuses g_h2 after GEMM1 consumed xh
    __half* hAh = (__half*)hA;
    __half* hBh = (__half*)hB;

    const float* nsrc = nrm;
    const float* ndst = nrm + NN;

    constexpr int SMEMW = 3 * ((128 + 256) * 40 * 2);   // 92160
    constexpr int SMEMS = 3 * ((128 + 64) * 72 * 2);
    cudaFuncSetAttribute(gemm_f16w, cudaFuncAttributeMaxDynamicSharedMemorySize, SMEMW);
    cudaFuncSetAttribute(gemm_f16_s<true>,  cudaFuncAttributeMaxDynamicSharedMemorySize, SMEMS);
    cudaFuncSetAttribute(gemm_f16_s<false>, cudaFuncAttributeMaxDynamicSharedMemorySize, SMEMS);

    const int M = NN;
    const int NYT = (M + 127) / 128;   // 782
    dim3 gS(1, NYT);

    // Launch order: GEMM1 at my index 3 (profiler capture slot).
    zero_fi<<<(NN + 255) / 256, 256>>>(degf, cnt, NN);                          // 0
    cvt_f2h<<<(NN * 512 / 4 + 255) / 256, 256>>>(x, xh, NN * 512 / 4);          // 1
    wcvt_kernel<<<(512 * 512 + 255) / 256, 256>>>(W1, w1t, 512, 512, 512);      // 2
    gemm_f16w<<<dim3(2, NYT), 256, SMEMW>>>(xh, w1t, b1, h1h, M, 512, 512);     // 3 (captured)
    deg_hist_kernel<<<(NE + 255) / 256, 256>>>(src, dst, degf, cnt);            // 4
    wcvt_kernel<<<(512 * 256 + 255) / 256, 256>>>(W2, w2t, 512, 256, 256);      // 5
    gemm_f16w<<<dim3(1, NYT), 256, SMEMW>>>(h1h, w2t, b2, h2h, M, 256, 512);    // 6
    scan1<<<NB_SCAN, 1024>>>(cnt, rowptr, bsum, degf, nrm);                     // 7
    scan2<<<1, 128>>>(bsum);                                                    // 8
    scan3<<<NB_SCAN, 1024>>>(rowptr, bsum, cursor);                             // 9
    fill_csr<<<(NE + 255) / 256, 256>>>(src, dst, cursor, col);                 // 10
    wcvt3g_kernel<<<(64 * 256 + 4 * 64 * 64 + 255) / 256, 256>>>(
        W3, w3t, Wg1, Wg2, Wg3, Wg4, wgt);                                      // 11
    gemm_f16_s<true><<<gS, 256, SMEMS>>>(h2h, w3t, b3, nullptr, nsrc, hAh, M, 64, 256); // 12

    const int gatherBlocks = (NN + 31) / 32;

    gather_h<<<gatherBlocks, 256>>>(hAh, rowptr, col, hBh);
    gemm_f16_s<true><<<gS, 256, SMEMS>>>(hBh, wgt + 0 * 4096, bg1, ndst, nsrc, hAh, M, 64, 64);

    gather_h<<<gatherBlocks, 256>>>(hAh, rowptr, col, hBh);
    gemm_f16_s<true><<<gS, 256, SMEMS>>>(hBh, wgt + 1 * 4096, bg2, ndst, nsrc, hAh, M, 64, 64);

    gather_h<<<gatherBlocks, 256>>>(hAh, rowptr, col, hBh);
    gemm_f16_s<true><<<gS, 256, SMEMS>>>(hBh, wgt + 2 * 4096, bg3, ndst, nsrc, hAh, M, 64, 64);

    gather_h<<<gatherBlocks, 256>>>(hAh, rowptr, col, hBh);
    gemm_f16_s<false><<<gS, 256, SMEMS>>>(hBh, wgt + 3 * 4096, bg4, ndst, nullptr, out, M, 40, 64);
}

// round 11
// speedup vs baseline: 1.0577x; 1.0577x over previous
#include <cuda_runtime.h>
#include <cuda_fp16.h>
#include <cstdint>

#define NN 100000
#define NE 1600000
#define NB_SCAN 98   // ceil(NN/1024)

// ---------------- scratch (device globals; no allocation allowed) ----------
__device__ float g_h1[(size_t)NN * 512];   // h1 as fp16 (aliased)
__device__ float g_h2[(size_t)NN * 256];   // xh (fp16) first, then h2 fp16
__device__ float g_hA[(size_t)NN * 64];    // fp16 node features (aliased)
__device__ float g_hB[(size_t)NN * 64];    // fp16 agg (aliased)
__device__ float g_degf[NN];
__device__ float g_nrm[2 * NN];      // [0..NN)=norm_src, [NN..2NN)=norm_dst
__device__ int   g_cnt[NN];
__device__ int   g_rowptr[NN];
__device__ int   g_cursor[NN];
__device__ int   g_bsum[128];
__device__ int   g_col[NE];
__device__ __half g_w1t[512 * 512];
__device__ __half g_w2t[256 * 512];
__device__ __half g_w3t[64 * 256];
__device__ __half g_wgt[4][64 * 64];

// ---------------- utility kernels -------------------------------------------
__global__ void zero_fi(float* __restrict__ pf, int* __restrict__ pi, int n) {
    int i = blockIdx.x * blockDim.x + threadIdx.x;
    if (i < n) { pf[i] = 0.0f; pi[i] = 0; }
}
__global__ void deg_hist_kernel(const int* __restrict__ src, const int* __restrict__ dst,
                                float* __restrict__ degf, int* __restrict__ cnt) {
    int e = blockIdx.x * blockDim.x + threadIdx.x;
    if (e < NE) {
        atomicAdd(&degf[src[e]], 1.0f);
        atomicAdd(&cnt[dst[e]], 1);
    }
}

__device__ __forceinline__ uint32_t packh2(float lo, float hi) {
    uint32_t r;
    asm("cvt.rn.f16x2.f32 %0, %1, %2;" : "=r"(r) : "f"(hi), "f"(lo));
    return r;
}

__global__ void cvt_f2h(const float* __restrict__ in, __half* __restrict__ out, int n4) {
    int i = blockIdx.x * blockDim.x + threadIdx.x;
    if (i < n4) {
        float4 v = ((const float4*)in)[i];
        uint2 o;
        o.x = packh2(v.x, v.y);
        o.y = packh2(v.z, v.w);
        ((uint2*)out)[i] = o;
    }
}

__global__ void wcvt_kernel(const float* __restrict__ W, __half* __restrict__ Wt,
                            int K, int N, int Npad) {
    int i = blockIdx.x * blockDim.x + threadIdx.x;
    if (i < Npad * K) {
        int n = i / K, k = i % K;
        Wt[i] = (n < N) ? __float2half(W[(size_t)k * N + n]) : __half(0.f);
    }
}
__global__ void wcvt3g_kernel(const float* __restrict__ W3, __half* __restrict__ w3t,
                              const float* __restrict__ Wg1, const float* __restrict__ Wg2,
                              const float* __restrict__ Wg3, const float* __restrict__ Wg4,
                              __half* __restrict__ Wt) {
    int i = blockIdx.x * blockDim.x + threadIdx.x;
    if (i < 64 * 256) {
        int n = i / 256, k = i % 256;
        w3t[i] = __float2half(W3[(size_t)k * 64 + n]);
    } else if (i < 64 * 256 + 4 * 64 * 64) {
        int j = i - 64 * 256;
        int which = j >> 12;
        int r = j & 4095;
        int n = r >> 6, k = r & 63;
        const float* W = (which == 0) ? Wg1 : (which == 1) ? Wg2 : (which == 2) ? Wg3 : Wg4;
        int N = (which == 3) ? 40 : 64;
        Wt[j] = (n < N) ? __float2half(W[(size_t)k * N + n]) : __half(0.f);
    }
}

// ---------------- CSR build (scan1 also computes norms) ----------------------
__global__ void scan1(const int* __restrict__ cnt, int* __restrict__ excl,
                      int* __restrict__ bsum, const float* __restrict__ degf,
                      float* __restrict__ nrm) {
    __shared__ int sh[1024];
    int tid = threadIdx.x;
    int i = blockIdx.x * 1024 + tid;
    int v = (i < NN) ? cnt[i] : 0;
    if (i < NN) {
        nrm[i] = rsqrtf(fmaxf(degf[i], 1.0f));
        nrm[NN + i] = rsqrtf(fmaxf((float)v, 1.0f));
    }
    sh[tid] = v;
    __syncthreads();
    for (int off = 1; off < 1024; off <<= 1) {
        int t = (tid >= off) ? sh[tid - off] : 0;
        __syncthreads();
        sh[tid] += t;
        __syncthreads();
    }
    if (i < NN) excl[i] = sh[tid] - v;
    if (tid == 1023) bsum[blockIdx.x] = sh[1023];
}
__global__ void scan2(int* __restrict__ bsum) {
    __shared__ int sh[128];
    int tid = threadIdx.x;
    int v = (tid < NB_SCAN) ? bsum[tid] : 0;
    sh[tid] = v;
    __syncthreads();
    for (int off = 1; off < 128; off <<= 1) {
        int t = (tid >= off) ? sh[tid - off] : 0;
        __syncthreads();
        sh[tid] += t;
        __syncthreads();
    }
    if (tid < NB_SCAN) bsum[tid] = sh[tid] - v;
}
__global__ void scan3(int* __restrict__ excl, const int* __restrict__ bsum,
                      int* __restrict__ cursor) {
    int i = blockIdx.x * 1024 + threadIdx.x;
    if (i < NN) {
        int r = excl[i] + bsum[blockIdx.x];
        excl[i] = r;
        cursor[i] = r;
    }
}
__global__ void fill_csr(const int* __restrict__ src, const int* __restrict__ dst,
                         int* __restrict__ cursor, int* __restrict__ col) {
    int e = blockIdx.x * blockDim.x + threadIdx.x;
    if (e < NE) {
        int p = atomicAdd(&cursor[dst[e]], 1);
        col[p] = src[e];
    }
}

// ---------------- CSR gather (fp16 rows, fp32 accumulate, 4x unrolled) -------
__global__ void gather_h(const __half* __restrict__ h, const int* __restrict__ rowptr,
                         const int* __restrict__ col, __half* __restrict__ agg) {
    int t = threadIdx.x;
    int node = blockIdx.x * 32 + (t >> 3);
    if (node >= NN) return;
    int c = t & 7;
    int beg = rowptr[node];
    int end = (node == NN - 1) ? NE : rowptr[node + 1];
    float acc[8] = {0.f, 0.f, 0.f, 0.f, 0.f, 0.f, 0.f, 0.f};
    int i = beg;
    for (; i + 3 < end; i += 4) {
        int s0 = __ldg(&col[i]);
        int s1 = __ldg(&col[i + 1]);
        int s2 = __ldg(&col[i + 2]);
        int s3 = __ldg(&col[i + 3]);
        uint4 v0 = ((const uint4*)(h + (size_t)s0 * 64))[c];
        uint4 v1 = ((const uint4*)(h + (size_t)s1 * 64))[c];
        uint4 v2 = ((const uint4*)(h + (size_t)s2 * 64))[c];
        uint4 v3 = ((const uint4*)(h + (size_t)s3 * 64))[c];
        const __half2* a0 = (const __half2*)&v0;
        const __half2* a1 = (const __half2*)&v1;
        const __half2* a2 = (const __half2*)&v2;
        const __half2* a3 = (const __half2*)&v3;
#pragma unroll
        for (int j = 0; j < 4; j++) {
            float2 f0 = __half22float2(a0[j]);
            float2 f1 = __half22float2(a1[j]);
            float2 f2 = __half22float2(a2[j]);
            float2 f3 = __half22float2(a3[j]);
            acc[2 * j]     += (f0.x + f1.x) + (f2.x + f3.x);
            acc[2 * j + 1] += (f0.y + f1.y) + (f2.y + f3.y);
        }
    }
    for (; i < end; i++) {
        int s = __ldg(&col[i]);
        uint4 v = ((const uint4*)(h + (size_t)s * 64))[c];
        const __half2* hv = (const __half2*)&v;
#pragma unroll
        for (int j = 0; j < 4; j++) {
            float2 f = __half22float2(hv[j]);
            acc[2 * j] += f.x;
            acc[2 * j + 1] += f.y;
        }
    }
    uint4 o;
    o.x = packh2(acc[0], acc[1]);
    o.y = packh2(acc[2], acc[3]);
    o.z = packh2(acc[4], acc[5]);
    o.w = packh2(acc[6], acc[7]);
    ((uint4*)(agg + (size_t)node * 64))[c] = o;
}

// ---------------- common async copy helper ----------------------------------
__device__ __forceinline__ void cp_async16(uint32_t saddr, const void* gaddr, int sz) {
    asm volatile("cp.async.cg.shared.global [%0], [%1], 16, %2;\n"
                 :: "r"(saddr), "l"(gaddr), "r"(sz));
}

// ============================================================================
// fp16 TC GEMM (extra-wide): CTA tile 128x256x32, 8 warps 2x4, warp 64x64.
// N multiple of 256. Used for GEMM1 only (N=512).
// ============================================================================
__global__ void __launch_bounds__(256, 1)
gemm_f16w(const __half* __restrict__ A, const __half* __restrict__ Wt,
          const float* __restrict__ bias, __half* __restrict__ Cout,
          int M, int N, int K) {
    constexpr int STRIDE_H = 40;
    constexpr int A_BYTES = 128 * STRIDE_H * 2;
    constexpr int B_BYTES = 256 * STRIDE_H * 2;
    constexpr int STAGE_BYTES = A_BYTES + B_BYTES;
    extern __shared__ char dsm[];
    uint32_t smem_u = (uint32_t)__cvta_generic_to_shared(dsm);

    const int tid = threadIdx.x;
    const int lane = tid & 31;
    const int warp = tid >> 5;
    const int wm = (warp >> 2) * 64;
    const int wn = (warp & 3) * 64;
    const int rowBase = blockIdx.y * 128;
    const int colBase = blockIdx.x * 256;
    const int KT = K / 32;

    const int lrow = lane & 7;
    const int sub = lane >> 3;
    const int subB = sub & 1;

    float acc[4][8][4];
#pragma unroll
    for (int i = 0; i < 4; i++)
#pragma unroll
        for (int j = 0; j < 8; j++)
#pragma unroll
            for (int q = 0; q < 4; q++) acc[i][j][q] = 0.0f;

    auto issue = [&](int stage, int kt) {
        const int k0 = kt * 32;
        uint32_t base = smem_u + stage * STAGE_BYTES;
#pragma unroll
        for (int i = 0; i < 2; i++) {
            int idx = tid + i * 256;
            int m = idx >> 2;
            int cq = idx & 3;
            const __half* gsrc = A + (size_t)(rowBase + m) * K + k0 + cq * 8;
            cp_async16(base + (m * STRIDE_H + cq * 8) * 2, gsrc,
                       (rowBase + m < M) ? 16 : 0);
        }
#pragma unroll
        for (int i = 0; i < 4; i++) {
            int idx = tid + i * 256;
            int n = idx >> 2;
            int cq = idx & 3;
            const __half* gsrc = Wt + (size_t)(colBase + n) * K + k0 + cq * 8;
            cp_async16(base + A_BYTES + (n * STRIDE_H + cq * 8) * 2, gsrc, 16);
        }
    };

#pragma unroll
    for (int p = 0; p < 2; p++) {
        issue(p, p);
        asm volatile("cp.async.commit_group;\n" ::: "memory");
    }

    for (int kt = 0; kt < KT; kt++) {
        asm volatile("cp.async.wait_group 1;\n" ::: "memory");
        __syncthreads();
        const int stage = kt % 3;
        uint32_t As_u = smem_u + stage * STAGE_BYTES;
        uint32_t Bs_u = As_u + A_BYTES;

#pragma unroll
        for (int ks = 0; ks < 2; ks++) {
            const int kb = ks * 16;
            uint32_t a[4][4], b[8][2];
#pragma unroll
            for (int mt = 0; mt < 4; mt++) {
                int r = wm + mt * 16 + (sub & 1) * 8 + lrow;
                uint32_t addr = As_u + (r * STRIDE_H + kb + (sub >> 1) * 8) * 2;
                asm volatile(
                    "ldmatrix.sync.aligned.m8n8.x4.shared.b16 {%0,%1,%2,%3}, [%4];"
                    : "=r"(a[mt][0]), "=r"(a[mt][1]), "=r"(a[mt][2]), "=r"(a[mt][3])
                    : "r"(addr));
            }
#pragma unroll
            for (int nt = 0; nt < 8; nt++) {
                int n = wn + nt * 8 + lrow;
                uint32_t addr = Bs_u + (n * STRIDE_H + kb + subB * 8) * 2;
                asm volatile(
                    "ldmatrix.sync.aligned.m8n8.x2.shared.b16 {%0,%1}, [%2];"
                    : "=r"(b[nt][0]), "=r"(b[nt][1]) : "r"(addr));
            }
#pragma unroll
            for (int mt = 0; mt < 4; mt++)
#pragma unroll
                for (int nt = 0; nt < 8; nt++) {
                    asm volatile(
                        "mma.sync.aligned.m16n8k16.row.col.f32.f16.f16.f32 "
                        "{%0,%1,%2,%3}, {%4,%5,%6,%7}, {%8,%9}, {%0,%1,%2,%3};"
                        : "+f"(acc[mt][nt][0]), "+f"(acc[mt][nt][1]),
                          "+f"(acc[mt][nt][2]), "+f"(acc[mt][nt][3])
                        : "r"(a[mt][0]), "r"(a[mt][1]), "r"(a[mt][2]), "r"(a[mt][3]),
                          "r"(b[nt][0]), "r"(b[nt][1]));
                }
        }
        if (kt + 2 < KT) issue((kt + 2) % 3, kt + 2);
        asm volatile("cp.async.commit_group;\n" ::: "memory");
    }

    const int g = lane >> 2;
    const int tq = lane & 3;
#pragma unroll
    for (int mt = 0; mt < 4; mt++) {
        int r0 = rowBase + wm + mt * 16 + g;
        int r1 = r0 + 8;
#pragma unroll
        for (int nt = 0; nt < 8; nt++) {
            int c = colBase + wn + nt * 8 + 2 * tq;
            float bx = __ldg(&bias[c]);
            float by = __ldg(&bias[c + 1]);
            if (r0 < M)
                *(uint32_t*)(Cout + (size_t)r0 * N + c) =
                    packh2(fmaxf(acc[mt][nt][0] + bx, 0.f), fmaxf(acc[mt][nt][1] + by, 0.f));
            if (r1 < M)
                *(uint32_t*)(Cout + (size_t)r1 * N + c) =
                    packh2(fmaxf(acc[mt][nt][2] + bx, 0.f), fmaxf(acc[mt][nt][3] + by, 0.f));
        }
    }
}

// ============================================================================
// fp16 TC GEMM (wide): CTA tile 128x128x32, occ 2. Used for GEMM2.
// ============================================================================
template <bool OUT_HALF>
__global__ void __launch_bounds__(256, 2)
gemm_f16(const __half* __restrict__ A, const __half* __restrict__ Wt,
         const float* __restrict__ bias, void* __restrict__ Cout,
         int M, int N, int K) {
    constexpr int STRIDE_H = 40;
    constexpr int A_BYTES = 128 * STRIDE_H * 2;
    constexpr int STAGE_BYTES = 2 * A_BYTES;
    extern __shared__ char dsm[];
    uint32_t smem_u = (uint32_t)__cvta_generic_to_shared(dsm);

    const int tid = threadIdx.x;
    const int lane = tid & 31;
    const int warp = tid >> 5;
    const int wm = (warp >> 2) * 64;
    const int wn = (warp & 3) * 32;
    const int rowBase = blockIdx.y * 128;
    const int colBase = blockIdx.x * 128;
    const int KT = K / 32;

    const int lrow = lane & 7;
    const int sub = lane >> 3;
    const int subB = sub & 1;

    float acc[4][4][4];
#pragma unroll
    for (int i = 0; i < 4; i++)
#pragma unroll
        for (int j = 0; j < 4; j++)
#pragma unroll
            for (int q = 0; q < 4; q++) acc[i][j][q] = 0.0f;

    const int l_m = tid >> 2;
    const int l_c = tid & 3;
    auto issue = [&](int stage, int kt) {
        const int k0 = kt * 32;
        uint32_t base = smem_u + stage * STAGE_BYTES;
#pragma unroll
        for (int i = 0; i < 2; i++) {
            int m = l_m + i * 64;
            const __half* gsrc = A + (size_t)(rowBase + m) * K + k0 + l_c * 8;
            cp_async16(base + m * 80 + l_c * 16, gsrc, (rowBase + m < M) ? 16 : 0);
        }
#pragma unroll
        for (int i = 0; i < 2; i++) {
            int n = l_m + i * 64;
            const __half* gsrc = Wt + (size_t)(colBase + n) * K + k0 + l_c * 8;
            cp_async16(base + A_BYTES + n * 80 + l_c * 16, gsrc, 16);
        }
    };

#pragma unroll
    for (int p = 0; p < 2; p++) {
        issue(p, p);
        asm volatile("cp.async.commit_group;\n" ::: "memory");
    }

    for (int kt = 0; kt < KT; kt++) {
        asm volatile("cp.async.wait_group 1;\n" ::: "memory");
        __syncthreads();
        const int stage = kt % 3;
        uint32_t As_u = smem_u + stage * STAGE_BYTES;
        uint32_t Bs_u = As_u + A_BYTES;

#pragma unroll
        for (int ks = 0; ks < 2; ks++) {
            const int kb = ks * 16;
            uint32_t a[4][4], b[4][2];
#pragma unroll
            for (int mt = 0; mt < 4; mt++) {
                int r = wm + mt * 16 + (sub & 1) * 8 + lrow;
                uint32_t addr = As_u + (r * STRIDE_H + kb + (sub >> 1) * 8) * 2;
                asm volatile(
                    "ldmatrix.sync.aligned.m8n8.x4.shared.b16 {%0,%1,%2,%3}, [%4];"
                    : "=r"(a[mt][0]), "=r"(a[mt][1]), "=r"(a[mt][2]), "=r"(a[mt][3])
                    : "r"(addr));
            }
#pragma unroll
            for (int nt = 0; nt < 4; nt++) {
                int n = wn + nt * 8 + lrow;
                uint32_t addr = Bs_u + (n * STRIDE_H + kb + subB * 8) * 2;
                asm volatile(
                    "ldmatrix.sync.aligned.m8n8.x2.shared.b16 {%0,%1}, [%2];"
                    : "=r"(b[nt][0]), "=r"(b[nt][1]) : "r"(addr));
            }
#pragma unroll
            for (int mt = 0; mt < 4; mt++)
#pragma unroll
                for (int nt = 0; nt < 4; nt++) {
                    asm volatile(
                        "mma.sync.aligned.m16n8k16.row.col.f32.f16.f16.f32 "
                        "{%0,%1,%2,%3}, {%4,%5,%6,%7}, {%8,%9}, {%0,%1,%2,%3};"
                        : "+f"(acc[mt][nt][0]), "+f"(acc[mt][nt][1]),
                          "+f"(acc[mt][nt][2]), "+f"(acc[mt][nt][3])
                        : "r"(a[mt][0]), "r"(a[mt][1]), "r"(a[mt][2]), "r"(a[mt][3]),
                          "r"(b[nt][0]), "r"(b[nt][1]));
                }
        }
        if (kt + 2 < KT) issue((kt + 2) % 3, kt + 2);
        asm volatile("cp.async.commit_group;\n" ::: "memory");
    }

    const int g = lane >> 2;
    const int tq = lane & 3;
#pragma unroll
    for (int mt = 0; mt < 4; mt++) {
        int r0 = rowBase + wm + mt * 16 + g;
        int r1 = r0 + 8;
#pragma unroll
        for (int nt = 0; nt < 4; nt++) {
            int c = colBase + wn + nt * 8 + 2 * tq;
            float bx = __ldg(&bias[c]);
            float by = __ldg(&bias[c + 1]);
            if (r0 < M) {
                float vx = fmaxf(acc[mt][nt][0] + bx, 0.f);
                float vy = fmaxf(acc[mt][nt][1] + by, 0.f);
                if (OUT_HALF)
                    *(uint32_t*)((__half*)Cout + (size_t)r0 * N + c) = packh2(vx, vy);
                else
                    *(float2*)((float*)Cout + (size_t)r0 * N + c) = make_float2(vx, vy);
            }
            if (r1 < M) {
                float vx = fmaxf(acc[mt][nt][2] + bx, 0.f);
                float vy = fmaxf(acc[mt][nt][3] + by, 0.f);
                if (OUT_HALF)
                    *(uint32_t*)((__half*)Cout + (size_t)r1 * N + c) = packh2(vx, vy);
                else
                    *(float2*)((float*)Cout + (size_t)r1 * N + c) = make_float2(vx, vy);
            }
        }
    }
}

// ============================================================================
// fp16 tensor-core GEMM (narrow): tile 128x64, BK=64, row scales rs/ws.
// ============================================================================
template <bool OUT_HALF>
__global__ void __launch_bounds__(256, 2)
gemm_f16_s(const __half* __restrict__ A, const __half* __restrict__ Wt,
           const float* __restrict__ bias, const float* __restrict__ rs,
           const float* __restrict__ ws, void* __restrict__ Cout,
           int M, int N, int K) {
    constexpr int STRIDE_H = 72;
    constexpr int A_BYTES = 128 * STRIDE_H * 2;
    constexpr int B_BYTES = 64 * STRIDE_H * 2;
    constexpr int STAGE_BYTES = A_BYTES + B_BYTES;
    extern __shared__ char dsm[];
    uint32_t smem_u = (uint32_t)__cvta_generic_to_shared(dsm);

    const int tid = threadIdx.x;
    const int lane = tid & 31;
    const int warp = tid >> 5;
    const int wm = (warp >> 1) * 32;
    const int wn = (warp & 1) * 32;
    const int rowBase = blockIdx.y * 128;
    const int KT = K / 64;

    const int lrow = lane & 7;
    const int sub = lane >> 3;
    const int subB = sub & 1;

    float acc[2][4][4];
#pragma unroll
    for (int i = 0; i < 2; i++)
#pragma unroll
        for (int j = 0; j < 4; j++)
#pragma unroll
            for (int q = 0; q < 4; q++) acc[i][j][q] = 0.0f;

    auto issue = [&](int stage, int kt) {
        const int k0 = kt * 64;
        uint32_t base = smem_u + stage * STAGE_BYTES;
#pragma unroll
        for (int i = 0; i < 4; i++) {
            int idx = tid + i * 256;
            int m = idx >> 3;
            int cq = idx & 7;
            const __half* gsrc = A + (size_t)(rowBase + m) * K + k0 + cq * 8;
            cp_async16(base + m * 144 + cq * 16, gsrc, (rowBase + m < M) ? 16 : 0);
        }
#pragma unroll
        for (int i = 0; i < 2; i++) {
            int idx = tid + i * 256;
            int n = idx >> 3;
            int cq = idx & 7;
            const __half* gsrc = Wt + (size_t)n * K + k0 + cq * 8;
            cp_async16(base + A_BYTES + n * 144 + cq * 16, gsrc, 16);
        }
    };

#pragma unroll
    for (int p = 0; p < 2; p++) {
        if (p < KT) issue(p, p);
        asm volatile("cp.async.commit_group;\n" ::: "memory");
    }

    for (int kt = 0; kt < KT; kt++) {
        asm volatile("cp.async.wait_group 1;\n" ::: "memory");
        __syncthreads();
        const int stage = kt % 3;
        uint32_t As_u = smem_u + stage * STAGE_BYTES;
        uint32_t Bs_u = As_u + A_BYTES;

#pragma unroll
        for (int ks = 0; ks < 4; ks++) {
            const int kb = ks * 16;
            uint32_t a[2][4], b[4][2];
#pragma unroll
            for (int mt = 0; mt < 2; mt++) {
                int r = wm + mt * 16 + (sub & 1) * 8 + lrow;
                uint32_t addr = As_u + (r * STRIDE_H + kb + (sub >> 1) * 8) * 2;
                asm volatile(
                    "ldmatrix.sync.aligned.m8n8.x4.shared.b16 {%0,%1,%2,%3}, [%4];"
                    : "=r"(a[mt][0]), "=r"(a[mt][1]), "=r"(a[mt][2]), "=r"(a[mt][3])
                    : "r"(addr));
            }
#pragma unroll
            for (int nt = 0; nt < 4; nt++) {
                int n = wn + nt * 8 + lrow;
                uint32_t addr = Bs_u + (n * STRIDE_H + kb + subB * 8) * 2;
                asm volatile(
                    "ldmatrix.sync.aligned.m8n8.x2.shared.b16 {%0,%1}, [%2];"
                    : "=r"(b[nt][0]), "=r"(b[nt][1]) : "r"(addr));
            }
#pragma unroll
            for (int mt = 0; mt < 2; mt++)
#pragma unroll
                for (int nt = 0; nt < 4; nt++) {
                    asm volatile(
                        "mma.sync.aligned.m16n8k16.row.col.f32.f16.f16.f32 "
                        "{%0,%1,%2,%3}, {%4,%5,%6,%7}, {%8,%9}, {%0,%1,%2,%3};"
                        : "+f"(acc[mt][nt][0]), "+f"(acc[mt][nt][1]),
                          "+f"(acc[mt][nt][2]), "+f"(acc[mt][nt][3])
                        : "r"(a[mt][0]), "r"(a[mt][1]), "r"(a[mt][2]), "r"(a[mt][3]),
                          "r"(b[nt][0]), "r"(b[nt][1]));
                }
        }
        if (kt + 2 < KT) issue((kt + 2) % 3, kt + 2);
        asm volatile("cp.async.commit_group;\n" ::: "memory");
    }

    const int g = lane >> 2;
    const int tq = lane & 3;
#pragma unroll
    for (int mt = 0; mt < 2; mt++) {
        int r0 = rowBase + wm + mt * 16 + g;
        int r1 = r0 + 8;
        float rs0 = 1.f, rs1 = 1.f, ws0 = 1.f, ws1 = 1.f;
        if (rs) {
            if (r0 < M) rs0 = rs[r0];
            if (r1 < M) rs1 = rs[r1];
        }
        if (ws) {
            if (r0 < M) ws0 = ws[r0];
            if (r1 < M) ws1 = ws[r1];
        }
#pragma unroll
        for (int nt = 0; nt < 4; nt++) {
            int c = wn + nt * 8 + 2 * tq;
            float bx = (c < N) ? __ldg(&bias[c]) : 0.f;
            float by = (c + 1 < N) ? __ldg(&bias[c + 1]) : 0.f;
            if (r0 < M) {
                float vx = ws0 * fmaxf(acc[mt][nt][0] * rs0 + bx, 0.f);
                float vy = ws0 * fmaxf(acc[mt][nt][1] * rs0 + by, 0.f);
                if (OUT_HALF) {
                    if (c + 1 < N)
                        *(uint32_t*)((__half*)Cout + (size_t)r0 * N + c) = packh2(vx, vy);
                } else {
                    if (c + 1 < N)
                        *(float2*)((float*)Cout + (size_t)r0 * N + c) = make_float2(vx, vy);
                    else if (c < N)
                        ((float*)Cout)[(size_t)r0 * N + c] = vx;
                }
            }
            if (r1 < M) {
                float vx = ws1 * fmaxf(acc[mt][nt][2] * rs1 + bx, 0.f);
                float vy = ws1 * fmaxf(acc[mt][nt][3] * rs1 + by, 0.f);
                if (OUT_HALF) {
                    if (c + 1 < N)
                        *(uint32_t*)((__half*)Cout + (size_t)r1 * N + c) = packh2(vx, vy);
                } else {
                    if (c + 1 < N)
                        *(float2*)((float*)Cout + (size_t)r1 * N + c) = make_float2(vx, vy);
                    else if (c < N)
                        ((float*)Cout)[(size_t)r1 * N + c] = vx;
                }
            }
        }
    }
}

// ---------------- host orchestration ---------------------------------------
extern "C" void kernel_launch(void* const* d_in, const int* in_sizes, int n_in,
                              void* d_out, int out_size) {
    const float* x   = (const float*)d_in[0];
    const int* src   = (const int*)d_in[1];
    const int* dst   = (const int*)d_in[2];
    const float* W1  = (const float*)d_in[3];
    const float* b1  = (const float*)d_in[4];
    const float* W2  = (const float*)d_in[5];
    const float* b2  = (const float*)d_in[6];
    const float* W3  = (const float*)d_in[7];
    const float* b3  = (const float*)d_in[8];
    const float* Wg1 = (const float*)d_in[9];
    const float* bg1 = (const float*)d_in[10];
    const float* Wg2 = (const float*)d_in[11];
    const float* bg2 = (const float*)d_in[12];
    const float* Wg3 = (const float*)d_in[13];
    const float* bg3 = (const float*)d_in[14];
    const float* Wg4 = (const float*)d_in[15];
    const float* bg4 = (const float*)d_in[16];
    float* out = (float*)d_out;

    float *h1, *h2, *hA, *hB, *degf, *nrm;
    int *cnt, *rowptr, *cursor, *bsum, *col;
    __half *w1t, *w2t, *w3t, *wgt;
    cudaGetSymbolAddress((void**)&h1, g_h1);
    cudaGetSymbolAddress((void**)&h2, g_h2);
    cudaGetSymbolAddress((void**)&hA, g_hA);
    cudaGetSymbolAddress((void**)&hB, g_hB);
    cudaGetSymbolAddress((void**)&degf, g_degf);
    cudaGetSymbolAddress((void**)&nrm, g_nrm);
    cudaGetSymbolAddress((void**)&cnt, g_cnt);
    cudaGetSymbolAddress((void**)&rowptr, g_rowptr);
    cudaGetSymbolAddress((void**)&cursor, g_cursor);
    cudaGetSymbolAddress((void**)&bsum, g_bsum);
    cudaGetSymbolAddress((void**)&col, g_col);
    cudaGetSymbolAddress((void**)&w1t, g_w1t);
    cudaGetSymbolAddress((void**)&w2t, g_w2t);
    cudaGetSymbolAddress((void**)&w3t, g_w3t);
    cudaGetSymbolAddress((void**)&wgt, g_wgt);

    __half* xh  = (__half*)h2;
    __half* h1h = (__half*)h1;
    __half* h2h = (__half*)h2;
    __half* hAh = (__half*)hA;
    __half* hBh = (__half*)hB;

    const float* nsrc = nrm;
    const float* ndst = nrm + NN;

    constexpr int SMEMW  = 3 * ((128 + 256) * 40 * 2);
    constexpr int SMEMF16 = 3 * (2 * 128 * 40 * 2);
    constexpr int SMEMS  = 3 * ((128 + 64) * 72 * 2);
    cudaFuncSetAttribute(gemm_f16w, cudaFuncAttributeMaxDynamicSharedMemorySize, SMEMW);
    cudaFuncSetAttribute(gemm_f16<true>, cudaFuncAttributeMaxDynamicSharedMemorySize, SMEMF16);
    cudaFuncSetAttribute(gemm_f16_s<true>,  cudaFuncAttributeMaxDynamicSharedMemorySize, SMEMS);
    cudaFuncSetAttribute(gemm_f16_s<false>, cudaFuncAttributeMaxDynamicSharedMemorySize, SMEMS);

    // side stream + events, created once (host objects; no device allocation)
    static cudaStream_t s2 = nullptr;
    static cudaEvent_t evFork = nullptr, evW1 = nullptr, evB = nullptr;
    if (!s2) {
        cudaStreamCreateWithFlags(&s2, cudaStreamNonBlocking);
        cudaEventCreateWithFlags(&evFork, cudaEventDisableTiming);
        cudaEventCreateWithFlags(&evW1, cudaEventDisableTiming);
        cudaEventCreateWithFlags(&evB, cudaEventDisableTiming);
    }

    const int M = NN;
    const int NYT = (M + 127) / 128;
    dim3 gS(1, NYT);

    // ---- fork side chain (independent of MLP until GEMM3) ----
    cudaEventRecord(evFork, 0);
    cudaStreamWaitEvent(s2, evFork, 0);
    wcvt_kernel<<<(512 * 512 + 255) / 256, 256, 0, s2>>>(W1, w1t, 512, 512, 512);
    cudaEventRecord(evW1, s2);
    wcvt_kernel<<<(512 * 256 + 255) / 256, 256, 0, s2>>>(W2, w2t, 512, 256, 256);
    zero_fi<<<(NN + 255) / 256, 256, 0, s2>>>(degf, cnt, NN);
    deg_hist_kernel<<<(NE + 255) / 256, 256, 0, s2>>>(src, dst, degf, cnt);
    scan1<<<NB_SCAN, 1024, 0, s2>>>(cnt, rowptr, bsum, degf, nrm);
    scan2<<<1, 128, 0, s2>>>(bsum);
    scan3<<<NB_SCAN, 1024, 0, s2>>>(rowptr, bsum, cursor);
    fill_csr<<<(NE + 255) / 256, 256, 0, s2>>>(src, dst, cursor, col);
    wcvt3g_kernel<<<(64 * 256 + 4 * 64 * 64 + 255) / 256, 256, 0, s2>>>(
        W3, w3t, Wg1, Wg2, Wg3, Wg4, wgt);
    cudaEventRecord(evB, s2);

    // ---- main chain ----
    cvt_f2h<<<(NN * 512 / 4 + 255) / 256, 256>>>(x, xh, NN * 512 / 4);
    cudaStreamWaitEvent(0, evW1, 0);
    gemm_f16w<<<dim3(2, NYT), 256, SMEMW>>>(xh, w1t, b1, h1h, M, 512, 512);
    cudaStreamWaitEvent(0, evB, 0);   // joins full side chain (done under GEMM1)
    gemm_f16<true><<<dim3(2, NYT), 256, SMEMF16>>>(h1h, w2t, b2, h2h, M, 256, 512);
    gemm_f16_s<true><<<gS, 256, SMEMS>>>(h2h, w3t, b3, nullptr, nsrc, hAh, M, 64, 256);

    const int gatherBlocks = (NN + 31) / 32;

    gather_h<<<gatherBlocks, 256>>>(hAh, rowptr, col, hBh);
    gemm_f16_s<true><<<gS, 256, SMEMS>>>(hBh, wgt + 0 * 4096, bg1, ndst, nsrc, hAh, M, 64, 64);

    gather_h<<<gatherBlocks, 256>>>(hAh, rowptr, col, hBh);
    gemm_f16_s<true><<<gS, 256, SMEMS>>>(hBh, wgt + 1 * 4096, bg2, ndst, nsrc, hAh, M, 64, 64);

    gather_h<<<gatherBlocks, 256>>>(hAh, rowptr, col, hBh);
    gemm_f16_s<true><<<gS, 256, SMEMS>>>(hBh, wgt + 2 * 4096, bg3, ndst, nsrc, hAh, M, 64, 64);

    gather_h<<<gatherBlocks, 256>>>(hAh, rowptr, col, hBh);
    gemm_f16_s<false><<<gS, 256, SMEMS>>>(hBh, wgt + 3 * 4096, bg4, ndst, nullptr, out, M, 40, 64);
}

// round 12
// speedup vs baseline: 1.0656x; 1.0075x over previous
#include <cuda_runtime.h>
#include <cuda_fp16.h>
#include <cstdint>

#define NN 100000
#define NE 1600000
#define NB_SCAN 98   // ceil(NN/1024)

// ---------------- scratch (device globals; no allocation allowed) ----------
__device__ float g_h1[(size_t)NN * 512];   // h1 as fp16 (aliased)
__device__ float g_h2[(size_t)NN * 256];   // xh (fp16) staged here (dead after GEMM1)
__device__ float g_hA[(size_t)NN * 64];    // fp16 node features (aliased)
__device__ float g_hB[(size_t)NN * 64];    // fp16 agg (aliased)
__device__ float g_degf[NN];
__device__ float g_nrm[2 * NN];      // [0..NN)=norm_src, [NN..2NN)=norm_dst
__device__ int   g_cnt[NN];
__device__ int   g_rowptr[NN];
__device__ int   g_cursor[NN];
__device__ int   g_bsum[128];
__device__ int   g_col[NE];
__device__ __half g_w1t[512 * 512];
__device__ __half g_w2t[256 * 512];
__device__ __half g_w3t[64 * 256];
__device__ __half g_wgt[4][64 * 64];

// ---------------- utility kernels -------------------------------------------
__global__ void zero_fi(float* __restrict__ pf, int* __restrict__ pi, int n) {
    int i = blockIdx.x * blockDim.x + threadIdx.x;
    if (i < n) { pf[i] = 0.0f; pi[i] = 0; }
}
__global__ void deg_hist_kernel(const int* __restrict__ src, const int* __restrict__ dst,
                                float* __restrict__ degf, int* __restrict__ cnt) {
    int e = blockIdx.x * blockDim.x + threadIdx.x;
    if (e < NE) {
        atomicAdd(&degf[src[e]], 1.0f);
        atomicAdd(&cnt[dst[e]], 1);
    }
}

__device__ __forceinline__ uint32_t packh2(float lo, float hi) {
    uint32_t r;
    asm("cvt.rn.f16x2.f32 %0, %1, %2;" : "=r"(r) : "f"(hi), "f"(lo));
    return r;
}

__global__ void cvt_f2h(const float* __restrict__ in, __half* __restrict__ out, int n4) {
    int i = blockIdx.x * blockDim.x + threadIdx.x;
    if (i < n4) {
        float4 v = ((const float4*)in)[i];
        uint2 o;
        o.x = packh2(v.x, v.y);
        o.y = packh2(v.z, v.w);
        ((uint2*)out)[i] = o;
    }
}

__global__ void wcvt_kernel(const float* __restrict__ W, __half* __restrict__ Wt,
                            int K, int N, int Npad) {
    int i = blockIdx.x * blockDim.x + threadIdx.x;
    if (i < Npad * K) {
        int n = i / K, k = i % K;
        Wt[i] = (n < N) ? __float2half(W[(size_t)k * N + n]) : __half(0.f);
    }
}
__global__ void wcvt3g_kernel(const float* __restrict__ W3, __half* __restrict__ w3t,
                              const float* __restrict__ Wg1, const float* __restrict__ Wg2,
                              const float* __restrict__ Wg3, const float* __restrict__ Wg4,
                              __half* __restrict__ Wt) {
    int i = blockIdx.x * blockDim.x + threadIdx.x;
    if (i < 64 * 256) {
        int n = i / 256, k = i % 256;
        w3t[i] = __float2half(W3[(size_t)k * 64 + n]);
    } else if (i < 64 * 256 + 4 * 64 * 64) {
        int j = i - 64 * 256;
        int which = j >> 12;
        int r = j & 4095;
        int n = r >> 6, k = r & 63;
        const float* W = (which == 0) ? Wg1 : (which == 1) ? Wg2 : (which == 2) ? Wg3 : Wg4;
        int N = (which == 3) ? 40 : 64;
        Wt[j] = (n < N) ? __float2half(W[(size_t)k * N + n]) : __half(0.f);
    }
}

// ---------------- CSR build (scan1 also computes norms) ----------------------
__global__ void scan1(const int* __restrict__ cnt, int* __restrict__ excl,
                      int* __restrict__ bsum, const float* __restrict__ degf,
                      float* __restrict__ nrm) {
    __shared__ int sh[1024];
    int tid = threadIdx.x;
    int i = blockIdx.x * 1024 + tid;
    int v = (i < NN) ? cnt[i] : 0;
    if (i < NN) {
        nrm[i] = rsqrtf(fmaxf(degf[i], 1.0f));
        nrm[NN + i] = rsqrtf(fmaxf((float)v, 1.0f));
    }
    sh[tid] = v;
    __syncthreads();
    for (int off = 1; off < 1024; off <<= 1) {
        int t = (tid >= off) ? sh[tid - off] : 0;
        __syncthreads();
        sh[tid] += t;
        __syncthreads();
    }
    if (i < NN) excl[i] = sh[tid] - v;
    if (tid == 1023) bsum[blockIdx.x] = sh[1023];
}
__global__ void scan2(int* __restrict__ bsum) {
    __shared__ int sh[128];
    int tid = threadIdx.x;
    int v = (tid < NB_SCAN) ? bsum[tid] : 0;
    sh[tid] = v;
    __syncthreads();
    for (int off = 1; off < 128; off <<= 1) {
        int t = (tid >= off) ? sh[tid - off] : 0;
        __syncthreads();
        sh[tid] += t;
        __syncthreads();
    }
    if (tid < NB_SCAN) bsum[tid] = sh[tid] - v;
}
__global__ void scan3(int* __restrict__ excl, const int* __restrict__ bsum,
                      int* __restrict__ cursor) {
    int i = blockIdx.x * 1024 + threadIdx.x;
    if (i < NN) {
        int r = excl[i] + bsum[blockIdx.x];
        excl[i] = r;
        cursor[i] = r;
    }
}
__global__ void fill_csr(const int* __restrict__ src, const int* __restrict__ dst,
                         int* __restrict__ cursor, int* __restrict__ col) {
    int e = blockIdx.x * blockDim.x + threadIdx.x;
    if (e < NE) {
        int p = atomicAdd(&cursor[dst[e]], 1);
        col[p] = src[e];
    }
}

// ---------------- CSR gather (fp16 rows, fp32 accumulate, 4x unrolled) -------
__global__ void gather_h(const __half* __restrict__ h, const int* __restrict__ rowptr,
                         const int* __restrict__ col, __half* __restrict__ agg) {
    int t = threadIdx.x;
    int node = blockIdx.x * 32 + (t >> 3);
    if (node >= NN) return;
    int c = t & 7;
    int beg = rowptr[node];
    int end = (node == NN - 1) ? NE : rowptr[node + 1];
    float acc[8] = {0.f, 0.f, 0.f, 0.f, 0.f, 0.f, 0.f, 0.f};
    int i = beg;
    for (; i + 3 < end; i += 4) {
        int s0 = __ldg(&col[i]);
        int s1 = __ldg(&col[i + 1]);
        int s2 = __ldg(&col[i + 2]);
        int s3 = __ldg(&col[i + 3]);
        uint4 v0 = ((const uint4*)(h + (size_t)s0 * 64))[c];
        uint4 v1 = ((const uint4*)(h + (size_t)s1 * 64))[c];
        uint4 v2 = ((const uint4*)(h + (size_t)s2 * 64))[c];
        uint4 v3 = ((const uint4*)(h + (size_t)s3 * 64))[c];
        const __half2* a0 = (const __half2*)&v0;
        const __half2* a1 = (const __half2*)&v1;
        const __half2* a2 = (const __half2*)&v2;
        const __half2* a3 = (const __half2*)&v3;
#pragma unroll
        for (int j = 0; j < 4; j++) {
            float2 f0 = __half22float2(a0[j]);
            float2 f1 = __half22float2(a1[j]);
            float2 f2 = __half22float2(a2[j]);
            float2 f3 = __half22float2(a3[j]);
            acc[2 * j]     += (f0.x + f1.x) + (f2.x + f3.x);
            acc[2 * j + 1] += (f0.y + f1.y) + (f2.y + f3.y);
        }
    }
    for (; i < end; i++) {
        int s = __ldg(&col[i]);
        uint4 v = ((const uint4*)(h + (size_t)s * 64))[c];
        const __half2* hv = (const __half2*)&v;
#pragma unroll
        for (int j = 0; j < 4; j++) {
            float2 f = __half22float2(hv[j]);
            acc[2 * j] += f.x;
            acc[2 * j + 1] += f.y;
        }
    }
    uint4 o;
    o.x = packh2(acc[0], acc[1]);
    o.y = packh2(acc[2], acc[3]);
    o.z = packh2(acc[4], acc[5]);
    o.w = packh2(acc[6], acc[7]);
    ((uint4*)(agg + (size_t)node * 64))[c] = o;
}

// ---------------- common async copy helper ----------------------------------
__device__ __forceinline__ void cp_async16(uint32_t saddr, const void* gaddr, int sz) {
    asm volatile("cp.async.cg.shared.global [%0], [%1], 16, %2;\n"
                 :: "r"(saddr), "l"(gaddr), "r"(sz));
}

// ============================================================================
// fp16 TC GEMM (extra-wide): CTA tile 128x256x32. Used for GEMM1 (N=512).
// ============================================================================
__global__ void __launch_bounds__(256, 1)
gemm_f16w(const __half* __restrict__ A, const __half* __restrict__ Wt,
          const float* __restrict__ bias, __half* __restrict__ Cout,
          int M, int N, int K) {
    constexpr int STRIDE_H = 40;
    constexpr int A_BYTES = 128 * STRIDE_H * 2;
    constexpr int B_BYTES = 256 * STRIDE_H * 2;
    constexpr int STAGE_BYTES = A_BYTES + B_BYTES;
    extern __shared__ char dsm[];
    uint32_t smem_u = (uint32_t)__cvta_generic_to_shared(dsm);

    const int tid = threadIdx.x;
    const int lane = tid & 31;
    const int warp = tid >> 5;
    const int wm = (warp >> 2) * 64;
    const int wn = (warp & 3) * 64;
    const int rowBase = blockIdx.y * 128;
    const int colBase = blockIdx.x * 256;
    const int KT = K / 32;

    const int lrow = lane & 7;
    const int sub = lane >> 3;
    const int subB = sub & 1;

    float acc[4][8][4];
#pragma unroll
    for (int i = 0; i < 4; i++)
#pragma unroll
        for (int j = 0; j < 8; j++)
#pragma unroll
            for (int q = 0; q < 4; q++) acc[i][j][q] = 0.0f;

    auto issue = [&](int stage, int kt) {
        const int k0 = kt * 32;
        uint32_t base = smem_u + stage * STAGE_BYTES;
#pragma unroll
        for (int i = 0; i < 2; i++) {
            int idx = tid + i * 256;
            int m = idx >> 2;
            int cq = idx & 3;
            const __half* gsrc = A + (size_t)(rowBase + m) * K + k0 + cq * 8;
            cp_async16(base + (m * STRIDE_H + cq * 8) * 2, gsrc,
                       (rowBase + m < M) ? 16 : 0);
        }
#pragma unroll
        for (int i = 0; i < 4; i++) {
            int idx = tid + i * 256;
            int n = idx >> 2;
            int cq = idx & 3;
            const __half* gsrc = Wt + (size_t)(colBase + n) * K + k0 + cq * 8;
            cp_async16(base + A_BYTES + (n * STRIDE_H + cq * 8) * 2, gsrc, 16);
        }
    };

#pragma unroll
    for (int p = 0; p < 2; p++) {
        issue(p, p);
        asm volatile("cp.async.commit_group;\n" ::: "memory");
    }

    for (int kt = 0; kt < KT; kt++) {
        asm volatile("cp.async.wait_group 1;\n" ::: "memory");
        __syncthreads();
        const int stage = kt % 3;
        uint32_t As_u = smem_u + stage * STAGE_BYTES;
        uint32_t Bs_u = As_u + A_BYTES;

#pragma unroll
        for (int ks = 0; ks < 2; ks++) {
            const int kb = ks * 16;
            uint32_t a[4][4], b[8][2];
#pragma unroll
            for (int mt = 0; mt < 4; mt++) {
                int r = wm + mt * 16 + (sub & 1) * 8 + lrow;
                uint32_t addr = As_u + (r * STRIDE_H + kb + (sub >> 1) * 8) * 2;
                asm volatile(
                    "ldmatrix.sync.aligned.m8n8.x4.shared.b16 {%0,%1,%2,%3}, [%4];"
                    : "=r"(a[mt][0]), "=r"(a[mt][1]), "=r"(a[mt][2]), "=r"(a[mt][3])
                    : "r"(addr));
            }
#pragma unroll
            for (int nt = 0; nt < 8; nt++) {
                int n = wn + nt * 8 + lrow;
                uint32_t addr = Bs_u + (n * STRIDE_H + kb + subB * 8) * 2;
                asm volatile(
                    "ldmatrix.sync.aligned.m8n8.x2.shared.b16 {%0,%1}, [%2];"
                    : "=r"(b[nt][0]), "=r"(b[nt][1]) : "r"(addr));
            }
#pragma unroll
            for (int mt = 0; mt < 4; mt++)
#pragma unroll
                for (int nt = 0; nt < 8; nt++) {
                    asm volatile(
                        "mma.sync.aligned.m16n8k16.row.col.f32.f16.f16.f32 "
                        "{%0,%1,%2,%3}, {%4,%5,%6,%7}, {%8,%9}, {%0,%1,%2,%3};"
                        : "+f"(acc[mt][nt][0]), "+f"(acc[mt][nt][1]),
                          "+f"(acc[mt][nt][2]), "+f"(acc[mt][nt][3])
                        : "r"(a[mt][0]), "r"(a[mt][1]), "r"(a[mt][2]), "r"(a[mt][3]),
                          "r"(b[nt][0]), "r"(b[nt][1]));
                }
        }
        if (kt + 2 < KT) issue((kt + 2) % 3, kt + 2);
        asm volatile("cp.async.commit_group;\n" ::: "memory");
    }

    const int g = lane >> 2;
    const int tq = lane & 3;
#pragma unroll
    for (int mt = 0; mt < 4; mt++) {
        int r0 = rowBase + wm + mt * 16 + g;
        int r1 = r0 + 8;
#pragma unroll
        for (int nt = 0; nt < 8; nt++) {
            int c = colBase + wn + nt * 8 + 2 * tq;
            float bx = __ldg(&bias[c]);
            float by = __ldg(&bias[c + 1]);
            if (r0 < M)
                *(uint32_t*)(Cout + (size_t)r0 * N + c) =
                    packh2(fmaxf(acc[mt][nt][0] + bx, 0.f), fmaxf(acc[mt][nt][1] + by, 0.f));
            if (r1 < M)
                *(uint32_t*)(Cout + (size_t)r1 * N + c) =
                    packh2(fmaxf(acc[mt][nt][2] + bx, 0.f), fmaxf(acc[mt][nt][3] + by, 0.f));
        }
    }
}

// ============================================================================
// Fused GEMM2+GEMM3: per 128-row slab,
//   h2 = relu(h1 @ W2t^T + b2)  [128 x 256]  (kept in SMEM)
//   hA = nsrc .* relu(h2 @ W3t^T + b3)  [128 x 64]  -> gmem fp16
// W2t: [256,512], W3t: [64,256]. One CTA per slab (grid.y = ceil(M/128)).
// ============================================================================
__global__ void __launch_bounds__(256, 1)
gemm_f16_23(const __half* __restrict__ A, const __half* __restrict__ W2t,
            const float* __restrict__ b2, const __half* __restrict__ W3t,
            const float* __restrict__ b3, const float* __restrict__ nsrc,
            __half* __restrict__ Cout, int M) {
    constexpr int K = 512;
    constexpr int N2 = 256;
    constexpr int STRIDE_H = 40;
    constexpr int A_BYTES = 128 * STRIDE_H * 2;   // 10240
    constexpr int B_BYTES = 256 * STRIDE_H * 2;   // 20480
    constexpr int STAGE_BYTES = A_BYTES + B_BYTES;
    constexpr int W3_OFF = 3 * STAGE_BYTES;        // 92160 (own region)
    constexpr int S2 = 264;                        // h2/W3 smem stride (halves)
    extern __shared__ char dsm[];
    uint32_t smem_u = (uint32_t)__cvta_generic_to_shared(dsm);
    uint32_t w3_u = smem_u + W3_OFF;
    uint32_t h2_u = smem_u;                        // reuses stage area post-drain

    const int tid = threadIdx.x;
    const int lane = tid & 31;
    const int warp = tid >> 5;
    const int rowBase = blockIdx.y * 128;
    const int KT = K / 32;                         // 16

    const int lrow = lane & 7;
    const int sub = lane >> 3;
    const int subB = sub & 1;
    const int g = lane >> 2;
    const int tq = lane & 3;

    // ---- prefetch W3 (64x256 halves = 2048 x 16B, 8/thread), own group ----
#pragma unroll
    for (int i = 0; i < 8; i++) {
        int idx = tid + i * 256;
        int n = idx >> 5;          // 32 chunks per 256-half row
        int cq = idx & 31;
        cp_async16(w3_u + (n * S2 + cq * 8) * 2, W3t + (size_t)n * 256 + cq * 8, 16);
    }
    asm volatile("cp.async.commit_group;\n" ::: "memory");

    // ---- main GEMM2 loop: warp grid 2x4, warp tile 64x64, colBase=0 ----
    const int wm = (warp >> 2) * 64;
    const int wn = (warp & 3) * 64;

    float acc[4][8][4];
#pragma unroll
    for (int i = 0; i < 4; i++)
#pragma unroll
        for (int j = 0; j < 8; j++)
#pragma unroll
            for (int q = 0; q < 4; q++) acc[i][j][q] = 0.0f;

    auto issue = [&](int stage, int kt) {
        const int k0 = kt * 32;
        uint32_t base = smem_u + stage * STAGE_BYTES;
#pragma unroll
        for (int i = 0; i < 2; i++) {
            int idx = tid + i * 256;
            int m = idx >> 2;
            int cq = idx & 3;
            const __half* gsrc = A + (size_t)(rowBase + m) * K + k0 + cq * 8;
            cp_async16(base + (m * STRIDE_H + cq * 8) * 2, gsrc,
                       (rowBase + m < M) ? 16 : 0);
        }
#pragma unroll
        for (int i = 0; i < 4; i++) {
            int idx = tid + i * 256;
            int n = idx >> 2;
            int cq = idx & 3;
            const __half* gsrc = W2t + (size_t)n * K + k0 + cq * 8;
            cp_async16(base + A_BYTES + (n * STRIDE_H + cq * 8) * 2, gsrc, 16);
        }
    };

#pragma unroll
    for (int p = 0; p < 2; p++) {
        issue(p, p);
        asm volatile("cp.async.commit_group;\n" ::: "memory");
    }

    for (int kt = 0; kt < KT; kt++) {
        asm volatile("cp.async.wait_group 1;\n" ::: "memory");
        __syncthreads();
        const int stage = kt % 3;
        uint32_t As_u = smem_u + stage * STAGE_BYTES;
        uint32_t Bs_u = As_u + A_BYTES;

#pragma unroll
        for (int ks = 0; ks < 2; ks++) {
            const int kb = ks * 16;
            uint32_t a[4][4], b[8][2];
#pragma unroll
            for (int mt = 0; mt < 4; mt++) {
                int r = wm + mt * 16 + (sub & 1) * 8 + lrow;
                uint32_t addr = As_u + (r * STRIDE_H + kb + (sub >> 1) * 8) * 2;
                asm volatile(
                    "ldmatrix.sync.aligned.m8n8.x4.shared.b16 {%0,%1,%2,%3}, [%4];"
                    : "=r"(a[mt][0]), "=r"(a[mt][1]), "=r"(a[mt][2]), "=r"(a[mt][3])
                    : "r"(addr));
            }
#pragma unroll
            for (int nt = 0; nt < 8; nt++) {
                int n = wn + nt * 8 + lrow;
                uint32_t addr = Bs_u + (n * STRIDE_H + kb + subB * 8) * 2;
                asm volatile(
                    "ldmatrix.sync.aligned.m8n8.x2.shared.b16 {%0,%1}, [%2];"
                    : "=r"(b[nt][0]), "=r"(b[nt][1]) : "r"(addr));
            }
#pragma unroll
            for (int mt = 0; mt < 4; mt++)
#pragma unroll
                for (int nt = 0; nt < 8; nt++) {
                    asm volatile(
                        "mma.sync.aligned.m16n8k16.row.col.f32.f16.f16.f32 "
                        "{%0,%1,%2,%3}, {%4,%5,%6,%7}, {%8,%9}, {%0,%1,%2,%3};"
                        : "+f"(acc[mt][nt][0]), "+f"(acc[mt][nt][1]),
                          "+f"(acc[mt][nt][2]), "+f"(acc[mt][nt][3])
                        : "r"(a[mt][0]), "r"(a[mt][1]), "r"(a[mt][2]), "r"(a[mt][3]),
                          "r"(b[nt][0]), "r"(b[nt][1]));
                }
        }
        if (kt + 2 < KT) issue((kt + 2) % 3, kt + 2);
        asm volatile("cp.async.commit_group;\n" ::: "memory");
    }

    // ---- drain pipeline, then write h2 tile (relu+bias, fp16) into smem ----
    asm volatile("cp.async.wait_group 0;\n" ::: "memory");
    __syncthreads();
    __half* h2s = (__half*)dsm;
#pragma unroll
    for (int mt = 0; mt < 4; mt++) {
        int lr0 = wm + mt * 16 + g;
        int lr1 = lr0 + 8;
#pragma unroll
        for (int nt = 0; nt < 8; nt++) {
            int c = wn + nt * 8 + 2 * tq;
            float bx = __ldg(&b2[c]);
            float by = __ldg(&b2[c + 1]);
            *(uint32_t*)(h2s + lr0 * S2 + c) =
                packh2(fmaxf(acc[mt][nt][0] + bx, 0.f), fmaxf(acc[mt][nt][1] + by, 0.f));
            *(uint32_t*)(h2s + lr1 * S2 + c) =
                packh2(fmaxf(acc[mt][nt][2] + bx, 0.f), fmaxf(acc[mt][nt][3] + by, 0.f));
        }
    }
    __syncthreads();

    // ---- GEMM3: h2s[128x256] @ W3^T -> 128x64; warp grid 4x2, tile 32x32 ----
    const int wm2 = (warp >> 1) * 32;
    const int wn2 = (warp & 1) * 32;

    float acc2[2][4][4];
#pragma unroll
    for (int i = 0; i < 2; i++)
#pragma unroll
        for (int j = 0; j < 4; j++)
#pragma unroll
            for (int q = 0; q < 4; q++) acc2[i][j][q] = 0.0f;

#pragma unroll
    for (int ks = 0; ks < 16; ks++) {
        const int kb = ks * 16;
        uint32_t a[2][4], b[4][2];
#pragma unroll
        for (int mt = 0; mt < 2; mt++) {
            int r = wm2 + mt * 16 + (sub & 1) * 8 + lrow;
            uint32_t addr = h2_u + (r * S2 + kb + (sub >> 1) * 8) * 2;
            asm volatile(
                "ldmatrix.sync.aligned.m8n8.x4.shared.b16 {%0,%1,%2,%3}, [%4];"
                : "=r"(a[mt][0]), "=r"(a[mt][1]), "=r"(a[mt][2]), "=r"(a[mt][3])
                : "r"(addr));
        }
#pragma unroll
        for (int nt = 0; nt < 4; nt++) {
            int n = wn2 + nt * 8 + lrow;
            uint32_t addr = w3_u + (n * S2 + kb + subB * 8) * 2;
            asm volatile(
                "ldmatrix.sync.aligned.m8n8.x2.shared.b16 {%0,%1}, [%2];"
                : "=r"(b[nt][0]), "=r"(b[nt][1]) : "r"(addr));
        }
#pragma unroll
        for (int mt = 0; mt < 2; mt++)
#pragma unroll
            for (int nt = 0; nt < 4; nt++) {
                asm volatile(
                    "mma.sync.aligned.m16n8k16.row.col.f32.f16.f16.f32 "
                    "{%0,%1,%2,%3}, {%4,%5,%6,%7}, {%8,%9}, {%0,%1,%2,%3};"
                    : "+f"(acc2[mt][nt][0]), "+f"(acc2[mt][nt][1]),
                      "+f"(acc2[mt][nt][2]), "+f"(acc2[mt][nt][3])
                    : "r"(a[mt][0]), "r"(a[mt][1]), "r"(a[mt][2]), "r"(a[mt][3]),
                      "r"(b[nt][0]), "r"(b[nt][1]));
            }
    }

    // ---- epilogue: hA = nsrc * relu(. + b3), fp16 [M,64] ----
#pragma unroll
    for (int mt = 0; mt < 2; mt++) {
        int r0 = rowBase + wm2 + mt * 16 + g;
        int r1 = r0 + 8;
        float w0 = (r0 < M) ? nsrc[r0] : 0.f;
        float w1 = (r1 < M) ? nsrc[r1] : 0.f;
#pragma unroll
        for (int nt = 0; nt < 4; nt++) {
            int c = wn2 + nt * 8 + 2 * tq;
            float bx = __ldg(&b3[c]);
            float by = __ldg(&b3[c + 1]);
            if (r0 < M)
                *(uint32_t*)(Cout + (size_t)r0 * 64 + c) =
                    packh2(w0 * fmaxf(acc2[mt][nt][0] + bx, 0.f),
                           w0 * fmaxf(acc2[mt][nt][1] + by, 0.f));
            if (r1 < M)
                *(uint32_t*)(Cout + (size_t)r1 * 64 + c) =
                    packh2(w1 * fmaxf(acc2[mt][nt][2] + bx, 0.f),
                           w1 * fmaxf(acc2[mt][nt][3] + by, 0.f));
        }
    }
}

// ============================================================================
// fp16 tensor-core GEMM (narrow): tile 128x64, BK=64, row scales rs/ws.
// ============================================================================
template <bool OUT_HALF>
__global__ void __launch_bounds__(256, 2)
gemm_f16_s(const __half* __restrict__ A, const __half* __restrict__ Wt,
           const float* __restrict__ bias, const float* __restrict__ rs,
           const float* __restrict__ ws, void* __restrict__ Cout,
           int M, int N, int K) {
    constexpr int STRIDE_H = 72;
    constexpr int A_BYTES = 128 * STRIDE_H * 2;
    constexpr int B_BYTES = 64 * STRIDE_H * 2;
    constexpr int STAGE_BYTES = A_BYTES + B_BYTES;
    extern __shared__ char dsm[];
    uint32_t smem_u = (uint32_t)__cvta_generic_to_shared(dsm);

    const int tid = threadIdx.x;
    const int lane = tid & 31;
    const int warp = tid >> 5;
    const int wm = (warp >> 1) * 32;
    const int wn = (warp & 1) * 32;
    const int rowBase = blockIdx.y * 128;
    const int KT = K / 64;

    const int lrow = lane & 7;
    const int sub = lane >> 3;
    const int subB = sub & 1;

    float acc[2][4][4];
#pragma unroll
    for (int i = 0; i < 2; i++)
#pragma unroll
        for (int j = 0; j < 4; j++)
#pragma unroll
            for (int q = 0; q < 4; q++) acc[i][j][q] = 0.0f;

    auto issue = [&](int stage, int kt) {
        const int k0 = kt * 64;
        uint32_t base = smem_u + stage * STAGE_BYTES;
#pragma unroll
        for (int i = 0; i < 4; i++) {
            int idx = tid + i * 256;
            int m = idx >> 3;
            int cq = idx & 7;
            const __half* gsrc = A + (size_t)(rowBase + m) * K + k0 + cq * 8;
            cp_async16(base + m * 144 + cq * 16, gsrc, (rowBase + m < M) ? 16 : 0);
        }
#pragma unroll
        for (int i = 0; i < 2; i++) {
            int idx = tid + i * 256;
            int n = idx >> 3;
            int cq = idx & 7;
            const __half* gsrc = Wt + (size_t)n * K + k0 + cq * 8;
            cp_async16(base + A_BYTES + n * 144 + cq * 16, gsrc, 16);
        }
    };

#pragma unroll
    for (int p = 0; p < 2; p++) {
        if (p < KT) issue(p, p);
        asm volatile("cp.async.commit_group;\n" ::: "memory");
    }

    for (int kt = 0; kt < KT; kt++) {
        asm volatile("cp.async.wait_group 1;\n" ::: "memory");
        __syncthreads();
        const int stage = kt % 3;
        uint32_t As_u = smem_u + stage * STAGE_BYTES;
        uint32_t Bs_u = As_u + A_BYTES;

#pragma unroll
        for (int ks = 0; ks < 4; ks++) {
            const int kb = ks * 16;
            uint32_t a[2][4], b[4][2];
#pragma unroll
            for (int mt = 0; mt < 2; mt++) {
                int r = wm + mt * 16 + (sub & 1) * 8 + lrow;
                uint32_t addr = As_u + (r * STRIDE_H + kb + (sub >> 1) * 8) * 2;
                asm volatile(
                    "ldmatrix.sync.aligned.m8n8.x4.shared.b16 {%0,%1,%2,%3}, [%4];"
                    : "=r"(a[mt][0]), "=r"(a[mt][1]), "=r"(a[mt][2]), "=r"(a[mt][3])
                    : "r"(addr));
            }
#pragma unroll
            for (int nt = 0; nt < 4; nt++) {
                int n = wn + nt * 8 + lrow;
                uint32_t addr = Bs_u + (n * STRIDE_H + kb + subB * 8) * 2;
                asm volatile(
                    "ldmatrix.sync.aligned.m8n8.x2.shared.b16 {%0,%1}, [%2];"
                    : "=r"(b[nt][0]), "=r"(b[nt][1]) : "r"(addr));
            }
#pragma unroll
            for (int mt = 0; mt < 2; mt++)
#pragma unroll
                for (int nt = 0; nt < 4; nt++) {
                    asm volatile(
                        "mma.sync.aligned.m16n8k16.row.col.f32.f16.f16.f32 "
                        "{%0,%1,%2,%3}, {%4,%5,%6,%7}, {%8,%9}, {%0,%1,%2,%3};"
                        : "+f"(acc[mt][nt][0]), "+f"(acc[mt][nt][1]),
                          "+f"(acc[mt][nt][2]), "+f"(acc[mt][nt][3])
                        : "r"(a[mt][0]), "r"(a[mt][1]), "r"(a[mt][2]), "r"(a[mt][3]),
                          "r"(b[nt][0]), "r"(b[nt][1]));
                }
        }
        if (kt + 2 < KT) issue((kt + 2) % 3, kt + 2);
        asm volatile("cp.async.commit_group;\n" ::: "memory");
    }

    const int g = lane >> 2;
    const int tq = lane & 3;
#pragma unroll
    for (int mt = 0; mt < 2; mt++) {
        int r0 = rowBase + wm + mt * 16 + g;
        int r1 = r0 + 8;
        float rs0 = 1.f, rs1 = 1.f, ws0 = 1.f, ws1 = 1.f;
        if (rs) {
            if (r0 < M) rs0 = rs[r0];
            if (r1 < M) rs1 = rs[r1];
        }
        if (ws) {
            if (r0 < M) ws0 = ws[r0];
            if (r1 < M) ws1 = ws[r1];
        }
#pragma unroll
        for (int nt = 0; nt < 4; nt++) {
            int c = wn + nt * 8 + 2 * tq;
            float bx = (c < N) ? __ldg(&bias[c]) : 0.f;
            float by = (c + 1 < N) ? __ldg(&bias[c + 1]) : 0.f;
            if (r0 < M) {
                float vx = ws0 * fmaxf(acc[mt][nt][0] * rs0 + bx, 0.f);
                float vy = ws0 * fmaxf(acc[mt][nt][1] * rs0 + by, 0.f);
                if (OUT_HALF) {
                    if (c + 1 < N)
                        *(uint32_t*)((__half*)Cout + (size_t)r0 * N + c) = packh2(vx, vy);
                } else {
                    if (c + 1 < N)
                        *(float2*)((float*)Cout + (size_t)r0 * N + c) = make_float2(vx, vy);
                    else if (c < N)
                        ((float*)Cout)[(size_t)r0 * N + c] = vx;
                }
            }
            if (r1 < M) {
                float vx = ws1 * fmaxf(acc[mt][nt][2] * rs1 + bx, 0.f);
                float vy = ws1 * fmaxf(acc[mt][nt][3] * rs1 + by, 0.f);
                if (OUT_HALF) {
                    if (c + 1 < N)
                        *(uint32_t*)((__half*)Cout + (size_t)r1 * N + c) = packh2(vx, vy);
                } else {
                    if (c + 1 < N)
                        *(float2*)((float*)Cout + (size_t)r1 * N + c) = make_float2(vx, vy);
                    else if (c < N)
                        ((float*)Cout)[(size_t)r1 * N + c] = vx;
                }
            }
        }
    }
}

// ---------------- host orchestration ---------------------------------------
extern "C" void kernel_launch(void* const* d_in, const int* in_sizes, int n_in,
                              void* d_out, int out_size) {
    const float* x   = (const float*)d_in[0];
    const int* src   = (const int*)d_in[1];
    const int* dst   = (const int*)d_in[2];
    const float* W1  = (const float*)d_in[3];
    const float* b1  = (const float*)d_in[4];
    const float* W2  = (const float*)d_in[5];
    const float* b2  = (const float*)d_in[6];
    const float* W3  = (const float*)d_in[7];
    const float* b3  = (const float*)d_in[8];
    const float* Wg1 = (const float*)d_in[9];
    const float* bg1 = (const float*)d_in[10];
    const float* Wg2 = (const float*)d_in[11];
    const float* bg2 = (const float*)d_in[12];
    const float* Wg3 = (const float*)d_in[13];
    const float* bg3 = (const float*)d_in[14];
    const float* Wg4 = (const float*)d_in[15];
    const float* bg4 = (const float*)d_in[16];
    float* out = (float*)d_out;

    float *h1, *h2, *hA, *hB, *degf, *nrm;
    int *cnt, *rowptr, *cursor, *bsum, *col;
    __half *w1t, *w2t, *w3t, *wgt;
    cudaGetSymbolAddress((void**)&h1, g_h1);
    cudaGetSymbolAddress((void**)&h2, g_h2);
    cudaGetSymbolAddress((void**)&hA, g_hA);
    cudaGetSymbolAddress((void**)&hB, g_hB);
    cudaGetSymbolAddress((void**)&degf, g_degf);
    cudaGetSymbolAddress((void**)&nrm, g_nrm);
    cudaGetSymbolAddress((void**)&cnt, g_cnt);
    cudaGetSymbolAddress((void**)&rowptr, g_rowptr);
    cudaGetSymbolAddress((void**)&cursor, g_cursor);
    cudaGetSymbolAddress((void**)&bsum, g_bsum);
    cudaGetSymbolAddress((void**)&col, g_col);
    cudaGetSymbolAddress((void**)&w1t, g_w1t);
    cudaGetSymbolAddress((void**)&w2t, g_w2t);
    cudaGetSymbolAddress((void**)&w3t, g_w3t);
    cudaGetSymbolAddress((void**)&wgt, g_wgt);

    __half* xh  = (__half*)h2;   // x fp16 staged in g_h2 (dead after GEMM1)
    __half* h1h = (__half*)h1;
    __half* hAh = (__half*)hA;
    __half* hBh = (__half*)hB;

    const float* nsrc = nrm;
    const float* ndst = nrm + NN;

    constexpr int SMEMW  = 3 * ((128 + 256) * 40 * 2);          // 92160
    constexpr int SMEM23 = 3 * ((128 + 256) * 40 * 2) + 64 * 264 * 2;  // 125952
    constexpr int SMEMS  = 3 * ((128 + 64) * 72 * 2);
    cudaFuncSetAttribute(gemm_f16w, cudaFuncAttributeMaxDynamicSharedMemorySize, SMEMW);
    cudaFuncSetAttribute(gemm_f16_23, cudaFuncAttributeMaxDynamicSharedMemorySize, SMEM23);
    cudaFuncSetAttribute(gemm_f16_s<true>,  cudaFuncAttributeMaxDynamicSharedMemorySize, SMEMS);
    cudaFuncSetAttribute(gemm_f16_s<false>, cudaFuncAttributeMaxDynamicSharedMemorySize, SMEMS);

    // side stream + events, created once (host objects; no device allocation)
    static cudaStream_t s2 = nullptr;
    static cudaEvent_t evFork = nullptr, evW1 = nullptr, evB = nullptr;
    if (!s2) {
        cudaStreamCreateWithFlags(&s2, cudaStreamNonBlocking);
        cudaEventCreateWithFlags(&evFork, cudaEventDisableTiming);
        cudaEventCreateWithFlags(&evW1, cudaEventDisableTiming);
        cudaEventCreateWithFlags(&evB, cudaEventDisableTiming);
    }

    const int M = NN;
    const int NYT = (M + 127) / 128;
    dim3 gS(1, NYT);

    // ---- fork side chain (weights + CSR; independent of MLP until GEMM2/3) ----
    cudaEventRecord(evFork, 0);
    cudaStreamWaitEvent(s2, evFork, 0);
    wcvt_kernel<<<(512 * 512 + 255) / 256, 256, 0, s2>>>(W1, w1t, 512, 512, 512);
    cudaEventRecord(evW1, s2);
    wcvt_kernel<<<(512 * 256 + 255) / 256, 256, 0, s2>>>(W2, w2t, 512, 256, 256);
    zero_fi<<<(NN + 255) / 256, 256, 0, s2>>>(degf, cnt, NN);
    deg_hist_kernel<<<(NE + 255) / 256, 256, 0, s2>>>(src, dst, degf, cnt);
    scan1<<<NB_SCAN, 1024, 0, s2>>>(cnt, rowptr, bsum, degf, nrm);
    scan2<<<1, 128, 0, s2>>>(bsum);
    scan3<<<NB_SCAN, 1024, 0, s2>>>(rowptr, bsum, cursor);
    fill_csr<<<(NE + 255) / 256, 256, 0, s2>>>(src, dst, cursor, col);
    wcvt3g_kernel<<<(64 * 256 + 4 * 64 * 64 + 255) / 256, 256, 0, s2>>>(
        W3, w3t, Wg1, Wg2, Wg3, Wg4, wgt);
    cudaEventRecord(evB, s2);

    // ---- main chain ----
    cvt_f2h<<<(NN * 512 / 4 + 255) / 256, 256>>>(x, xh, NN * 512 / 4);
    cudaStreamWaitEvent(0, evW1, 0);
    gemm_f16w<<<dim3(2, NYT), 256, SMEMW>>>(xh, w1t, b1, h1h, M, 512, 512);
    cudaStreamWaitEvent(0, evB, 0);   // join side chain (W2t/W3t/norms/CSR ready)
    // fused GEMM2+GEMM3: h1 -> (h2 in smem) -> hA (scaled by norm_src)
    gemm_f16_23<<<dim3(1, NYT), 256, SMEM23>>>(h1h, w2t, b2, w3t, b3, nsrc, hAh, M);

    const int gatherBlocks = (NN + 31) / 32;

    gather_h<<<gatherBlocks, 256>>>(hAh, rowptr, col, hBh);
    gemm_f16_s<true><<<gS, 256, SMEMS>>>(hBh, wgt + 0 * 4096, bg1, ndst, nsrc, hAh, M, 64, 64);

    gather_h<<<gatherBlocks, 256>>>(hAh, rowptr, col, hBh);
    gemm_f16_s<true><<<gS, 256, SMEMS>>>(hBh, wgt + 1 * 4096, bg2, ndst, nsrc, hAh, M, 64, 64);

    gather_h<<<gatherBlocks, 256>>>(hAh, rowptr, col, hBh);
    gemm_f16_s<true><<<gS, 256, SMEMS>>>(hBh, wgt + 2 * 4096, bg3, ndst, nsrc, hAh, M, 64, 64);

    gather_h<<<gatherBlocks, 256>>>(hAh, rowptr, col, hBh);
    gemm_f16_s<false><<<gS, 256, SMEMS>>>(hBh, wgt + 3 * 4096, bg4, ndst, nullptr, out, M, 40, 64);
}

// round 13
// speedup vs baseline: 1.0921x; 1.0248x over previous
#include <cuda_runtime.h>
#include <cuda_fp16.h>
#include <cstdint>

#define NN 100000
#define NE 1600000
#define NB_SCAN 98   // ceil(NN/1024)

// ---------------- scratch (device globals; no allocation allowed) ----------
__device__ float g_h1[(size_t)NN * 512];   // h1 as fp16 (aliased)
__device__ float g_h2[(size_t)NN * 256];   // xh (fp16) staged here (dead after GEMM1)
__device__ float g_hA[(size_t)NN * 64];    // fp16 node features (aliased)
__device__ float g_hB[(size_t)NN * 64];    // fp16 agg (aliased)
__device__ float g_degf[NN];
__device__ float g_nrm[2 * NN];      // [0..NN)=norm_src, [NN..2NN)=norm_dst
__device__ int   g_cnt[NN];
__device__ int   g_rowptr[NN];
__device__ int   g_cursor[NN];
__device__ int   g_bsum[128];
__device__ int   g_col[NE];
__device__ __half g_w1t[512 * 512];
__device__ __half g_w2t[256 * 512];
__device__ __half g_w3t[64 * 256];
__device__ __half g_wgt[4][64 * 64];

// ---------------- utility kernels -------------------------------------------
__global__ void zero_fi(float* __restrict__ pf, int* __restrict__ pi, int n) {
    int i = blockIdx.x * blockDim.x + threadIdx.x;
    if (i < n) { pf[i] = 0.0f; pi[i] = 0; }
}
__global__ void deg_hist_kernel(const int* __restrict__ src, const int* __restrict__ dst,
                                float* __restrict__ degf, int* __restrict__ cnt) {
    int e = blockIdx.x * blockDim.x + threadIdx.x;
    if (e < NE) {
        atomicAdd(&degf[src[e]], 1.0f);
        atomicAdd(&cnt[dst[e]], 1);
    }
}

__device__ __forceinline__ uint32_t packh2(float lo, float hi) {
    uint32_t r;
    asm("cvt.rn.f16x2.f32 %0, %1, %2;" : "=r"(r) : "f"(hi), "f"(lo));
    return r;
}

__global__ void cvt_f2h(const float* __restrict__ in, __half* __restrict__ out, int n4) {
    int i = blockIdx.x * blockDim.x + threadIdx.x;
    if (i < n4) {
        float4 v = ((const float4*)in)[i];
        uint2 o;
        o.x = packh2(v.x, v.y);
        o.y = packh2(v.z, v.w);
        ((uint2*)out)[i] = o;
    }
}

__global__ void wcvt_kernel(const float* __restrict__ W, __half* __restrict__ Wt,
                            int K, int N, int Npad) {
    int i = blockIdx.x * blockDim.x + threadIdx.x;
    if (i < Npad * K) {
        int n = i / K, k = i % K;
        Wt[i] = (n < N) ? __float2half(W[(size_t)k * N + n]) : __half(0.f);
    }
}
__global__ void wcvt3g_kernel(const float* __restrict__ W3, __half* __restrict__ w3t,
                              const float* __restrict__ Wg1, const float* __restrict__ Wg2,
                              const float* __restrict__ Wg3, const float* __restrict__ Wg4,
                              __half* __restrict__ Wt) {
    int i = blockIdx.x * blockDim.x + threadIdx.x;
    if (i < 64 * 256) {
        int n = i / 256, k = i % 256;
        w3t[i] = __float2half(W3[(size_t)k * 64 + n]);
    } else if (i < 64 * 256 + 4 * 64 * 64) {
        int j = i - 64 * 256;
        int which = j >> 12;
        int r = j & 4095;
        int n = r >> 6, k = r & 63;
        const float* W = (which == 0) ? Wg1 : (which == 1) ? Wg2 : (which == 2) ? Wg3 : Wg4;
        int N = (which == 3) ? 40 : 64;
        Wt[j] = (n < N) ? __float2half(W[(size_t)k * N + n]) : __half(0.f);
    }
}

// ---------------- CSR build (scan1 also computes norms) ----------------------
__global__ void scan1(const int* __restrict__ cnt, int* __restrict__ excl,
                      int* __restrict__ bsum, const float* __restrict__ degf,
                      float* __restrict__ nrm) {
    __shared__ int sh[1024];
    int tid = threadIdx.x;
    int i = blockIdx.x * 1024 + tid;
    int v = (i < NN) ? cnt[i] : 0;
    if (i < NN) {
        nrm[i] = rsqrtf(fmaxf(degf[i], 1.0f));
        nrm[NN + i] = rsqrtf(fmaxf((float)v, 1.0f));
    }
    sh[tid] = v;
    __syncthreads();
    for (int off = 1; off < 1024; off <<= 1) {
        int t = (tid >= off) ? sh[tid - off] : 0;
        __syncthreads();
        sh[tid] += t;
        __syncthreads();
    }
    if (i < NN) excl[i] = sh[tid] - v;
    if (tid == 1023) bsum[blockIdx.x] = sh[1023];
}
__global__ void scan2(int* __restrict__ bsum) {
    __shared__ int sh[128];
    int tid = threadIdx.x;
    int v = (tid < NB_SCAN) ? bsum[tid] : 0;
    sh[tid] = v;
    __syncthreads();
    for (int off = 1; off < 128; off <<= 1) {
        int t = (tid >= off) ? sh[tid - off] : 0;
        __syncthreads();
        sh[tid] += t;
        __syncthreads();
    }
    if (tid < NB_SCAN) bsum[tid] = sh[tid] - v;
}
__global__ void scan3(int* __restrict__ excl, const int* __restrict__ bsum,
                      int* __restrict__ cursor) {
    int i = blockIdx.x * 1024 + threadIdx.x;
    if (i < NN) {
        int r = excl[i] + bsum[blockIdx.x];
        excl[i] = r;
        cursor[i] = r;
    }
}
__global__ void fill_csr(const int* __restrict__ src, const int* __restrict__ dst,
                         int* __restrict__ cursor, int* __restrict__ col) {
    int e = blockIdx.x * blockDim.x + threadIdx.x;
    if (e < NE) {
        int p = atomicAdd(&cursor[dst[e]], 1);
        col[p] = src[e];
    }
}

// ---------------- CSR gather (fp16 rows, fp32 accumulate, 4x unrolled) -------
__global__ void gather_h(const __half* __restrict__ h, const int* __restrict__ rowptr,
                         const int* __restrict__ col, __half* __restrict__ agg) {
    int t = threadIdx.x;
    int node = blockIdx.x * 32 + (t >> 3);
    if (node >= NN) return;
    int c = t & 7;
    int beg = rowptr[node];
    int end = (node == NN - 1) ? NE : rowptr[node + 1];
    float acc[8] = {0.f, 0.f, 0.f, 0.f, 0.f, 0.f, 0.f, 0.f};
    int i = beg;
    for (; i + 3 < end; i += 4) {
        int s0 = __ldg(&col[i]);
        int s1 = __ldg(&col[i + 1]);
        int s2 = __ldg(&col[i + 2]);
        int s3 = __ldg(&col[i + 3]);
        uint4 v0 = ((const uint4*)(h + (size_t)s0 * 64))[c];
        uint4 v1 = ((const uint4*)(h + (size_t)s1 * 64))[c];
        uint4 v2 = ((const uint4*)(h + (size_t)s2 * 64))[c];
        uint4 v3 = ((const uint4*)(h + (size_t)s3 * 64))[c];
        const __half2* a0 = (const __half2*)&v0;
        const __half2* a1 = (const __half2*)&v1;
        const __half2* a2 = (const __half2*)&v2;
        const __half2* a3 = (const __half2*)&v3;
#pragma unroll
        for (int j = 0; j < 4; j++) {
            float2 f0 = __half22float2(a0[j]);
            float2 f1 = __half22float2(a1[j]);
            float2 f2 = __half22float2(a2[j]);
            float2 f3 = __half22float2(a3[j]);
            acc[2 * j]     += (f0.x + f1.x) + (f2.x + f3.x);
            acc[2 * j + 1] += (f0.y + f1.y) + (f2.y + f3.y);
        }
    }
    for (; i < end; i++) {
        int s = __ldg(&col[i]);
        uint4 v = ((const uint4*)(h + (size_t)s * 64))[c];
        const __half2* hv = (const __half2*)&v;
#pragma unroll
        for (int j = 0; j < 4; j++) {
            float2 f = __half22float2(hv[j]);
            acc[2 * j] += f.x;
            acc[2 * j + 1] += f.y;
        }
    }
    uint4 o;
    o.x = packh2(acc[0], acc[1]);
    o.y = packh2(acc[2], acc[3]);
    o.z = packh2(acc[4], acc[5]);
    o.w = packh2(acc[6], acc[7]);
    ((uint4*)(agg + (size_t)node * 64))[c] = o;
}

// ---------------- common async copy helper ----------------------------------
__device__ __forceinline__ void cp_async16(uint32_t saddr, const void* gaddr, int sz) {
    asm volatile("cp.async.cg.shared.global [%0], [%1], 16, %2;\n"
                 :: "r"(saddr), "l"(gaddr), "r"(sz));
}

// ============================================================================
// fp16 TC GEMM (extra-wide, BK=64): CTA tile 128x256x64, 3-stage, stride 72.
// Used for GEMM1 (N=512, K=512). 8 warps (2x4), warp tile 64x64.
// ============================================================================
__global__ void __launch_bounds__(256, 1)
gemm_f16w(const __half* __restrict__ A, const __half* __restrict__ Wt,
          const float* __restrict__ bias, __half* __restrict__ Cout,
          int M, int N, int K) {
    constexpr int SH = 72;                      // halves per smem row
    constexpr int A_BYTES = 128 * SH * 2;       // 18432
    constexpr int B_BYTES = 256 * SH * 2;       // 36864
    constexpr int STAGE_BYTES = A_BYTES + B_BYTES;   // 55296
    extern __shared__ char dsm[];
    uint32_t smem_u = (uint32_t)__cvta_generic_to_shared(dsm);

    const int tid = threadIdx.x;
    const int lane = tid & 31;
    const int warp = tid >> 5;
    const int wm = (warp >> 2) * 64;
    const int wn = (warp & 3) * 64;
    const int rowBase = blockIdx.y * 128;
    const int colBase = blockIdx.x * 256;
    const int KT = K / 64;                      // 8

    const int lrow = lane & 7;
    const int sub = lane >> 3;
    const int subB = sub & 1;

    float acc[4][8][4];
#pragma unroll
    for (int i = 0; i < 4; i++)
#pragma unroll
        for (int j = 0; j < 8; j++)
#pragma unroll
            for (int q = 0; q < 4; q++) acc[i][j][q] = 0.0f;

    // loaders per K64 tile: A = 128x8 chunks (4/thr), B = 256x8 chunks (8/thr)
    auto issue = [&](int stage, int kt) {
        const int k0 = kt * 64;
        uint32_t base = smem_u + stage * STAGE_BYTES;
#pragma unroll
        for (int i = 0; i < 4; i++) {
            int idx = tid + i * 256;
            int m = idx >> 3;
            int cq = idx & 7;
            const __half* gsrc = A + (size_t)(rowBase + m) * K + k0 + cq * 8;
            cp_async16(base + (m * SH + cq * 8) * 2, gsrc, (rowBase + m < M) ? 16 : 0);
        }
#pragma unroll
        for (int i = 0; i < 8; i++) {
            int idx = tid + i * 256;
            int n = idx >> 3;
            int cq = idx & 7;
            const __half* gsrc = Wt + (size_t)(colBase + n) * K + k0 + cq * 8;
            cp_async16(base + A_BYTES + (n * SH + cq * 8) * 2, gsrc, 16);
        }
    };

#pragma unroll
    for (int p = 0; p < 2; p++) {
        issue(p, p);
        asm volatile("cp.async.commit_group;\n" ::: "memory");
    }

    for (int kt = 0; kt < KT; kt++) {
        asm volatile("cp.async.wait_group 1;\n" ::: "memory");
        __syncthreads();
        const int stage = kt % 3;
        uint32_t As_u = smem_u + stage * STAGE_BYTES;
        uint32_t Bs_u = As_u + A_BYTES;

#pragma unroll
        for (int ks = 0; ks < 4; ks++) {
            const int kb = ks * 16;
            uint32_t a[4][4], b[8][2];
#pragma unroll
            for (int mt = 0; mt < 4; mt++) {
                int r = wm + mt * 16 + (sub & 1) * 8 + lrow;
                uint32_t addr = As_u + (r * SH + kb + (sub >> 1) * 8) * 2;
                asm volatile(
                    "ldmatrix.sync.aligned.m8n8.x4.shared.b16 {%0,%1,%2,%3}, [%4];"
                    : "=r"(a[mt][0]), "=r"(a[mt][1]), "=r"(a[mt][2]), "=r"(a[mt][3])
                    : "r"(addr));
            }
#pragma unroll
            for (int nt = 0; nt < 8; nt++) {
                int n = wn + nt * 8 + lrow;
                uint32_t addr = Bs_u + (n * SH + kb + subB * 8) * 2;
                asm volatile(
                    "ldmatrix.sync.aligned.m8n8.x2.shared.b16 {%0,%1}, [%2];"
                    : "=r"(b[nt][0]), "=r"(b[nt][1]) : "r"(addr));
            }
#pragma unroll
            for (int mt = 0; mt < 4; mt++)
#pragma unroll
                for (int nt = 0; nt < 8; nt++) {
                    asm volatile(
                        "mma.sync.aligned.m16n8k16.row.col.f32.f16.f16.f32 "
                        "{%0,%1,%2,%3}, {%4,%5,%6,%7}, {%8,%9}, {%0,%1,%2,%3};"
                        : "+f"(acc[mt][nt][0]), "+f"(acc[mt][nt][1]),
                          "+f"(acc[mt][nt][2]), "+f"(acc[mt][nt][3])
                        : "r"(a[mt][0]), "r"(a[mt][1]), "r"(a[mt][2]), "r"(a[mt][3]),
                          "r"(b[nt][0]), "r"(b[nt][1]));
                }
        }
        if (kt + 2 < KT) issue((kt + 2) % 3, kt + 2);
        asm volatile("cp.async.commit_group;\n" ::: "memory");
    }

    const int g = lane >> 2;
    const int tq = lane & 3;
#pragma unroll
    for (int mt = 0; mt < 4; mt++) {
        int r0 = rowBase + wm + mt * 16 + g;
        int r1 = r0 + 8;
#pragma unroll
        for (int nt = 0; nt < 8; nt++) {
            int c = colBase + wn + nt * 8 + 2 * tq;
            float bx = __ldg(&bias[c]);
            float by = __ldg(&bias[c + 1]);
            if (r0 < M)
                *(uint32_t*)(Cout + (size_t)r0 * N + c) =
                    packh2(fmaxf(acc[mt][nt][0] + bx, 0.f), fmaxf(acc[mt][nt][1] + by, 0.f));
            if (r1 < M)
                *(uint32_t*)(Cout + (size_t)r1 * N + c) =
                    packh2(fmaxf(acc[mt][nt][2] + bx, 0.f), fmaxf(acc[mt][nt][3] + by, 0.f));
        }
    }
}

// ============================================================================
// Fused GEMM2+GEMM3 (unchanged from R12): per 128-row slab,
//   h2 = relu(h1 @ W2t^T + b2)  kept in SMEM; hA = nsrc.*relu(h2@W3t^T+b3)
// ============================================================================
__global__ void __launch_bounds__(256, 1)
gemm_f16_23(const __half* __restrict__ A, const __half* __restrict__ W2t,
            const float* __restrict__ b2, const __half* __restrict__ W3t,
            const float* __restrict__ b3, const float* __restrict__ nsrc,
            __half* __restrict__ Cout, int M) {
    constexpr int K = 512;
    constexpr int STRIDE_H = 40;
    constexpr int A_BYTES = 128 * STRIDE_H * 2;
    constexpr int B_BYTES = 256 * STRIDE_H * 2;
    constexpr int STAGE_BYTES = A_BYTES + B_BYTES;
    constexpr int W3_OFF = 3 * STAGE_BYTES;
    constexpr int S2 = 264;
    extern __shared__ char dsm[];
    uint32_t smem_u = (uint32_t)__cvta_generic_to_shared(dsm);
    uint32_t w3_u = smem_u + W3_OFF;
    uint32_t h2_u = smem_u;

    const int tid = threadIdx.x;
    const int lane = tid & 31;
    const int warp = tid >> 5;
    const int rowBase = blockIdx.y * 128;
    const int KT = K / 32;

    const int lrow = lane & 7;
    const int sub = lane >> 3;
    const int subB = sub & 1;
    const int g = lane >> 2;
    const int tq = lane & 3;

#pragma unroll
    for (int i = 0; i < 8; i++) {
        int idx = tid + i * 256;
        int n = idx >> 5;
        int cq = idx & 31;
        cp_async16(w3_u + (n * S2 + cq * 8) * 2, W3t + (size_t)n * 256 + cq * 8, 16);
    }
    asm volatile("cp.async.commit_group;\n" ::: "memory");

    const int wm = (warp >> 2) * 64;
    const int wn = (warp & 3) * 64;

    float acc[4][8][4];
#pragma unroll
    for (int i = 0; i < 4; i++)
#pragma unroll
        for (int j = 0; j < 8; j++)
#pragma unroll
            for (int q = 0; q < 4; q++) acc[i][j][q] = 0.0f;

    auto issue = [&](int stage, int kt) {
        const int k0 = kt * 32;
        uint32_t base = smem_u + stage * STAGE_BYTES;
#pragma unroll
        for (int i = 0; i < 2; i++) {
            int idx = tid + i * 256;
            int m = idx >> 2;
            int cq = idx & 3;
            const __half* gsrc = A + (size_t)(rowBase + m) * K + k0 + cq * 8;
            cp_async16(base + (m * STRIDE_H + cq * 8) * 2, gsrc,
                       (rowBase + m < M) ? 16 : 0);
        }
#pragma unroll
        for (int i = 0; i < 4; i++) {
            int idx = tid + i * 256;
            int n = idx >> 2;
            int cq = idx & 3;
            const __half* gsrc = W2t + (size_t)n * K + k0 + cq * 8;
            cp_async16(base + A_BYTES + (n * STRIDE_H + cq * 8) * 2, gsrc, 16);
        }
    };

#pragma unroll
    for (int p = 0; p < 2; p++) {
        issue(p, p);
        asm volatile("cp.async.commit_group;\n" ::: "memory");
    }

    for (int kt = 0; kt < KT; kt++) {
        asm volatile("cp.async.wait_group 1;\n" ::: "memory");
        __syncthreads();
        const int stage = kt % 3;
        uint32_t As_u = smem_u + stage * STAGE_BYTES;
        uint32_t Bs_u = As_u + A_BYTES;

#pragma unroll
        for (int ks = 0; ks < 2; ks++) {
            const int kb = ks * 16;
            uint32_t a[4][4], b[8][2];
#pragma unroll
            for (int mt = 0; mt < 4; mt++) {
                int r = wm + mt * 16 + (sub & 1) * 8 + lrow;
                uint32_t addr = As_u + (r * STRIDE_H + kb + (sub >> 1) * 8) * 2;
                asm volatile(
                    "ldmatrix.sync.aligned.m8n8.x4.shared.b16 {%0,%1,%2,%3}, [%4];"
                    : "=r"(a[mt][0]), "=r"(a[mt][1]), "=r"(a[mt][2]), "=r"(a[mt][3])
                    : "r"(addr));
            }
#pragma unroll
            for (int nt = 0; nt < 8; nt++) {
                int n = wn + nt * 8 + lrow;
                uint32_t addr = Bs_u + (n * STRIDE_H + kb + subB * 8) * 2;
                asm volatile(
                    "ldmatrix.sync.aligned.m8n8.x2.shared.b16 {%0,%1}, [%2];"
                    : "=r"(b[nt][0]), "=r"(b[nt][1]) : "r"(addr));
            }
#pragma unroll
            for (int mt = 0; mt < 4; mt++)
#pragma unroll
                for (int nt = 0; nt < 8; nt++) {
                    asm volatile(
                        "mma.sync.aligned.m16n8k16.row.col.f32.f16.f16.f32 "
                        "{%0,%1,%2,%3}, {%4,%5,%6,%7}, {%8,%9}, {%0,%1,%2,%3};"
                        : "+f"(acc[mt][nt][0]), "+f"(acc[mt][nt][1]),
                          "+f"(acc[mt][nt][2]), "+f"(acc[mt][nt][3])
                        : "r"(a[mt][0]), "r"(a[mt][1]), "r"(a[mt][2]), "r"(a[mt][3]),
                          "r"(b[nt][0]), "r"(b[nt][1]));
                }
        }
        if (kt + 2 < KT) issue((kt + 2) % 3, kt + 2);
        asm volatile("cp.async.commit_group;\n" ::: "memory");
    }

    asm volatile("cp.async.wait_group 0;\n" ::: "memory");
    __syncthreads();
    __half* h2s = (__half*)dsm;
#pragma unroll
    for (int mt = 0; mt < 4; mt++) {
        int lr0 = wm + mt * 16 + g;
        int lr1 = lr0 + 8;
#pragma unroll
        for (int nt = 0; nt < 8; nt++) {
            int c = wn + nt * 8 + 2 * tq;
            float bx = __ldg(&b2[c]);
            float by = __ldg(&b2[c + 1]);
            *(uint32_t*)(h2s + lr0 * S2 + c) =
                packh2(fmaxf(acc[mt][nt][0] + bx, 0.f), fmaxf(acc[mt][nt][1] + by, 0.f));
            *(uint32_t*)(h2s + lr1 * S2 + c) =
                packh2(fmaxf(acc[mt][nt][2] + bx, 0.f), fmaxf(acc[mt][nt][3] + by, 0.f));
        }
    }
    __syncthreads();

    const int wm2 = (warp >> 1) * 32;
    const int wn2 = (warp & 1) * 32;

    float acc2[2][4][4];
#pragma unroll
    for (int i = 0; i < 2; i++)
#pragma unroll
        for (int j = 0; j < 4; j++)
#pragma unroll
            for (int q = 0; q < 4; q++) acc2[i][j][q] = 0.0f;

#pragma unroll
    for (int ks = 0; ks < 16; ks++) {
        const int kb = ks * 16;
        uint32_t a[2][4], b[4][2];
#pragma unroll
        for (int mt = 0; mt < 2; mt++) {
            int r = wm2 + mt * 16 + (sub & 1) * 8 + lrow;
            uint32_t addr = h2_u + (r * S2 + kb + (sub >> 1) * 8) * 2;
            asm volatile(
                "ldmatrix.sync.aligned.m8n8.x4.shared.b16 {%0,%1,%2,%3}, [%4];"
                : "=r"(a[mt][0]), "=r"(a[mt][1]), "=r"(a[mt][2]), "=r"(a[mt][3])
                : "r"(addr));
        }
#pragma unroll
        for (int nt = 0; nt < 4; nt++) {
            int n = wn2 + nt * 8 + lrow;
            uint32_t addr = w3_u + (n * S2 + kb + subB * 8) * 2;
            asm volatile(
                "ldmatrix.sync.aligned.m8n8.x2.shared.b16 {%0,%1}, [%2];"
                : "=r"(b[nt][0]), "=r"(b[nt][1]) : "r"(addr));
        }
#pragma unroll
        for (int mt = 0; mt < 2; mt++)
#pragma unroll
            for (int nt = 0; nt < 4; nt++) {
                asm volatile(
                    "mma.sync.aligned.m16n8k16.row.col.f32.f16.f16.f32 "
                    "{%0,%1,%2,%3}, {%4,%5,%6,%7}, {%8,%9}, {%0,%1,%2,%3};"
                    : "+f"(acc2[mt][nt][0]), "+f"(acc2[mt][nt][1]),
                      "+f"(acc2[mt][nt][2]), "+f"(acc2[mt][nt][3])
                    : "r"(a[mt][0]), "r"(a[mt][1]), "r"(a[mt][2]), "r"(a[mt][3]),
                      "r"(b[nt][0]), "r"(b[nt][1]));
            }
    }

#pragma unroll
    for (int mt = 0; mt < 2; mt++) {
        int r0 = rowBase + wm2 + mt * 16 + g;
        int r1 = r0 + 8;
        float w0 = (r0 < M) ? nsrc[r0] : 0.f;
        float w1 = (r1 < M) ? nsrc[r1] : 0.f;
#pragma unroll
        for (int nt = 0; nt < 4; nt++) {
            int c = wn2 + nt * 8 + 2 * tq;
            float bx = __ldg(&b3[c]);
            float by = __ldg(&b3[c + 1]);
            if (r0 < M)
                *(uint32_t*)(Cout + (size_t)r0 * 64 + c) =
                    packh2(w0 * fmaxf(acc2[mt][nt][0] + bx, 0.f),
                           w0 * fmaxf(acc2[mt][nt][1] + by, 0.f));
            if (r1 < M)
                *(uint32_t*)(Cout + (size_t)r1 * 64 + c) =
                    packh2(w1 * fmaxf(acc2[mt][nt][2] + bx, 0.f),
                           w1 * fmaxf(acc2[mt][nt][3] + by, 0.f));
        }
    }
}

// ============================================================================
// fp16 tensor-core GEMM (narrow): tile 128x64, BK=64, row scales rs/ws.
// ============================================================================
template <bool OUT_HALF>
__global__ void __launch_bounds__(256, 2)
gemm_f16_s(const __half* __restrict__ A, const __half* __restrict__ Wt,
           const float* __restrict__ bias, const float* __restrict__ rs,
           const float* __restrict__ ws, void* __restrict__ Cout,
           int M, int N, int K) {
    constexpr int STRIDE_H = 72;
    constexpr int A_BYTES = 128 * STRIDE_H * 2;
    constexpr int B_BYTES = 64 * STRIDE_H * 2;
    constexpr int STAGE_BYTES = A_BYTES + B_BYTES;
    extern __shared__ char dsm[];
    uint32_t smem_u = (uint32_t)__cvta_generic_to_shared(dsm);

    const int tid = threadIdx.x;
    const int lane = tid & 31;
    const int warp = tid >> 5;
    const int wm = (warp >> 1) * 32;
    const int wn = (warp & 1) * 32;
    const int rowBase = blockIdx.y * 128;
    const int KT = K / 64;

    const int lrow = lane & 7;
    const int sub = lane >> 3;
    const int subB = sub & 1;

    float acc[2][4][4];
#pragma unroll
    for (int i = 0; i < 2; i++)
#pragma unroll
        for (int j = 0; j < 4; j++)
#pragma unroll
            for (int q = 0; q < 4; q++) acc[i][j][q] = 0.0f;

    auto issue = [&](int stage, int kt) {
        const int k0 = kt * 64;
        uint32_t base = smem_u + stage * STAGE_BYTES;
#pragma unroll
        for (int i = 0; i < 4; i++) {
            int idx = tid + i * 256;
            int m = idx >> 3;
            int cq = idx & 7;
            const __half* gsrc = A + (size_t)(rowBase + m) * K + k0 + cq * 8;
            cp_async16(base + m * 144 + cq * 16, gsrc, (rowBase + m < M) ? 16 : 0);
        }
#pragma unroll
        for (int i = 0; i < 2; i++) {
            int idx = tid + i * 256;
            int n = idx >> 3;
            int cq = idx & 7;
            const __half* gsrc = Wt + (size_t)n * K + k0 + cq * 8;
            cp_async16(base + A_BYTES + n * 144 + cq * 16, gsrc, 16);
        }
    };

#pragma unroll
    for (int p = 0; p < 2; p++) {
        if (p < KT) issue(p, p);
        asm volatile("cp.async.commit_group;\n" ::: "memory");
    }

    for (int kt = 0; kt < KT; kt++) {
        asm volatile("cp.async.wait_group 1;\n" ::: "memory");
        __syncthreads();
        const int stage = kt % 3;
        uint32_t As_u = smem_u + stage * STAGE_BYTES;
        uint32_t Bs_u = As_u + A_BYTES;

#pragma unroll
        for (int ks = 0; ks < 4; ks++) {
            const int kb = ks * 16;
            uint32_t a[2][4], b[4][2];
#pragma unroll
            for (int mt = 0; mt < 2; mt++) {
                int r = wm + mt * 16 + (sub & 1) * 8 + lrow;
                uint32_t addr = As_u + (r * STRIDE_H + kb + (sub >> 1) * 8) * 2;
                asm volatile(
                    "ldmatrix.sync.aligned.m8n8.x4.shared.b16 {%0,%1,%2,%3}, [%4];"
                    : "=r"(a[mt][0]), "=r"(a[mt][1]), "=r"(a[mt][2]), "=r"(a[mt][3])
                    : "r"(addr));
            }
#pragma unroll
            for (int nt = 0; nt < 4; nt++) {
                int n = wn + nt * 8 + lrow;
                uint32_t addr = Bs_u + (n * STRIDE_H + kb + subB * 8) * 2;
                asm volatile(
                    "ldmatrix.sync.aligned.m8n8.x2.shared.b16 {%0,%1}, [%2];"
                    : "=r"(b[nt][0]), "=r"(b[nt][1]) : "r"(addr));
            }
#pragma unroll
            for (int mt = 0; mt < 2; mt++)
#pragma unroll
                for (int nt = 0; nt < 4; nt++) {
                    asm volatile(
                        "mma.sync.aligned.m16n8k16.row.col.f32.f16.f16.f32 "
                        "{%0,%1,%2,%3}, {%4,%5,%6,%7}, {%8,%9}, {%0,%1,%2,%3};"
                        : "+f"(acc[mt][nt][0]), "+f"(acc[mt][nt][1]),
                          "+f"(acc[mt][nt][2]), "+f"(acc[mt][nt][3])
                        : "r"(a[mt][0]), "r"(a[mt][1]), "r"(a[mt][2]), "r"(a[mt][3]),
                          "r"(b[nt][0]), "r"(b[nt][1]));
                }
        }
        if (kt + 2 < KT) issue((kt + 2) % 3, kt + 2);
        asm volatile("cp.async.commit_group;\n" ::: "memory");
    }

    const int g = lane >> 2;
    const int tq = lane & 3;
#pragma unroll
    for (int mt = 0; mt < 2; mt++) {
        int r0 = rowBase + wm + mt * 16 + g;
        int r1 = r0 + 8;
        float rs0 = 1.f, rs1 = 1.f, ws0 = 1.f, ws1 = 1.f;
        if (rs) {
            if (r0 < M) rs0 = rs[r0];
            if (r1 < M) rs1 = rs[r1];
        }
        if (ws) {
            if (r0 < M) ws0 = ws[r0];
            if (r1 < M) ws1 = ws[r1];
        }
#pragma unroll
        for (int nt = 0; nt < 4; nt++) {
            int c = wn + nt * 8 + 2 * tq;
            float bx = (c < N) ? __ldg(&bias[c]) : 0.f;
            float by = (c + 1 < N) ? __ldg(&bias[c + 1]) : 0.f;
            if (r0 < M) {
                float vx = ws0 * fmaxf(acc[mt][nt][0] * rs0 + bx, 0.f);
                float vy = ws0 * fmaxf(acc[mt][nt][1] * rs0 + by, 0.f);
                if (OUT_HALF) {
                    if (c + 1 < N)
                        *(uint32_t*)((__half*)Cout + (size_t)r0 * N + c) = packh2(vx, vy);
                } else {
                    if (c + 1 < N)
                        *(float2*)((float*)Cout + (size_t)r0 * N + c) = make_float2(vx, vy);
                    else if (c < N)
                        ((float*)Cout)[(size_t)r0 * N + c] = vx;
                }
            }
            if (r1 < M) {
                float vx = ws1 * fmaxf(acc[mt][nt][2] * rs1 + bx, 0.f);
                float vy = ws1 * fmaxf(acc[mt][nt][3] * rs1 + by, 0.f);
                if (OUT_HALF) {
                    if (c + 1 < N)
                        *(uint32_t*)((__half*)Cout + (size_t)r1 * N + c) = packh2(vx, vy);
                } else {
                    if (c + 1 < N)
                        *(float2*)((float*)Cout + (size_t)r1 * N + c) = make_float2(vx, vy);
                    else if (c < N)
                        ((float*)Cout)[(size_t)r1 * N + c] = vx;
                }
            }
        }
    }
}

// ---------------- host orchestration ---------------------------------------
extern "C" void kernel_launch(void* const* d_in, const int* in_sizes, int n_in,
                              void* d_out, int out_size) {
    const float* x   = (const float*)d_in[0];
    const int* src   = (const int*)d_in[1];
    const int* dst   = (const int*)d_in[2];
    const float* W1  = (const float*)d_in[3];
    const float* b1  = (const float*)d_in[4];
    const float* W2  = (const float*)d_in[5];
    const float* b2  = (const float*)d_in[6];
    const float* W3  = (const float*)d_in[7];
    const float* b3  = (const float*)d_in[8];
    const float* Wg1 = (const float*)d_in[9];
    const float* bg1 = (const float*)d_in[10];
    const float* Wg2 = (const float*)d_in[11];
    const float* bg2 = (const float*)d_in[12];
    const float* Wg3 = (const float*)d_in[13];
    const float* bg3 = (const float*)d_in[14];
    const float* Wg4 = (const float*)d_in[15];
    const float* bg4 = (const float*)d_in[16];
    float* out = (float*)d_out;

    float *h1, *h2, *hA, *hB, *degf, *nrm;
    int *cnt, *rowptr, *cursor, *bsum, *col;
    __half *w1t, *w2t, *w3t, *wgt;
    cudaGetSymbolAddress((void**)&h1, g_h1);
    cudaGetSymbolAddress((void**)&h2, g_h2);
    cudaGetSymbolAddress((void**)&hA, g_hA);
    cudaGetSymbolAddress((void**)&hB, g_hB);
    cudaGetSymbolAddress((void**)&degf, g_degf);
    cudaGetSymbolAddress((void**)&nrm, g_nrm);
    cudaGetSymbolAddress((void**)&cnt, g_cnt);
    cudaGetSymbolAddress((void**)&rowptr, g_rowptr);
    cudaGetSymbolAddress((void**)&cursor, g_cursor);
    cudaGetSymbolAddress((void**)&bsum, g_bsum);
    cudaGetSymbolAddress((void**)&col, g_col);
    cudaGetSymbolAddress((void**)&w1t, g_w1t);
    cudaGetSymbolAddress((void**)&w2t, g_w2t);
    cudaGetSymbolAddress((void**)&w3t, g_w3t);
    cudaGetSymbolAddress((void**)&wgt, g_wgt);

    __half* xh  = (__half*)h2;   // x fp16 staged in g_h2 (dead after GEMM1)
    __half* h1h = (__half*)h1;
    __half* hAh = (__half*)hA;
    __half* hBh = (__half*)hB;

    const float* nsrc = nrm;
    const float* ndst = nrm + NN;

    constexpr int SMEMW  = 3 * ((128 + 256) * 72 * 2);          // 165888
    constexpr int SMEM23 = 3 * ((128 + 256) * 40 * 2) + 64 * 264 * 2;  // 125952
    constexpr int SMEMS  = 3 * ((128 + 64) * 72 * 2);
    cudaFuncSetAttribute(gemm_f16w, cudaFuncAttributeMaxDynamicSharedMemorySize, SMEMW);
    cudaFuncSetAttribute(gemm_f16_23, cudaFuncAttributeMaxDynamicSharedMemorySize, SMEM23);
    cudaFuncSetAttribute(gemm_f16_s<true>,  cudaFuncAttributeMaxDynamicSharedMemorySize, SMEMS);
    cudaFuncSetAttribute(gemm_f16_s<false>, cudaFuncAttributeMaxDynamicSharedMemorySize, SMEMS);

    // side stream + events, created once (host objects; no device allocation)
    static cudaStream_t s2 = nullptr;
    static cudaEvent_t evFork = nullptr, evW1 = nullptr, evB = nullptr;
    if (!s2) {
        cudaStreamCreateWithFlags(&s2, cudaStreamNonBlocking);
        cudaEventCreateWithFlags(&evFork, cudaEventDisableTiming);
        cudaEventCreateWithFlags(&evW1, cudaEventDisableTiming);
        cudaEventCreateWithFlags(&evB, cudaEventDisableTiming);
    }

    const int M = NN;
    const int NYT = (M + 127) / 128;
    dim3 gS(1, NYT);

    // ---- fork side chain (weights + CSR) ----
    cudaEventRecord(evFork, 0);
    cudaStreamWaitEvent(s2, evFork, 0);
    wcvt_kernel<<<(512 * 512 + 255) / 256, 256, 0, s2>>>(W1, w1t, 512, 512, 512);
    cudaEventRecord(evW1, s2);
    wcvt_kernel<<<(512 * 256 + 255) / 256, 256, 0, s2>>>(W2, w2t, 512, 256, 256);
    zero_fi<<<(NN + 255) / 256, 256, 0, s2>>>(degf, cnt, NN);
    deg_hist_kernel<<<(NE + 255) / 256, 256, 0, s2>>>(src, dst, degf, cnt);
    scan1<<<NB_SCAN, 1024, 0, s2>>>(cnt, rowptr, bsum, degf, nrm);
    scan2<<<1, 128, 0, s2>>>(bsum);
    scan3<<<NB_SCAN, 1024, 0, s2>>>(rowptr, bsum, cursor);
    fill_csr<<<(NE + 255) / 256, 256, 0, s2>>>(src, dst, cursor, col);
    wcvt3g_kernel<<<(64 * 256 + 4 * 64 * 64 + 255) / 256, 256, 0, s2>>>(
        W3, w3t, Wg1, Wg2, Wg3, Wg4, wgt);
    cudaEventRecord(evB, s2);

    // ---- main chain ----
    cvt_f2h<<<(NN * 512 / 4 + 255) / 256, 256>>>(x, xh, NN * 512 / 4);
    cudaStreamWaitEvent(0, evW1, 0);
    gemm_f16w<<<dim3(2, NYT), 256, SMEMW>>>(xh, w1t, b1, h1h, M, 512, 512);
    cudaStreamWaitEvent(0, evB, 0);
    gemm_f16_23<<<dim3(1, NYT), 256, SMEM23>>>(h1h, w2t, b2, w3t, b3, nsrc, hAh, M);

    const int gatherBlocks = (NN + 31) / 32;

    gather_h<<<gatherBlocks, 256>>>(hAh, rowptr, col, hBh);
    gemm_f16_s<true><<<gS, 256, SMEMS>>>(hBh, wgt + 0 * 4096, bg1, ndst, nsrc, hAh, M, 64, 64);

    gather_h<<<gatherBlocks, 256>>>(hAh, rowptr, col, hBh);
    gemm_f16_s<true><<<gS, 256, SMEMS>>>(hBh, wgt + 1 * 4096, bg2, ndst, nsrc, hAh, M, 64, 64);

    gather_h<<<gatherBlocks, 256>>>(hAh, rowptr, col, hBh);
    gemm_f16_s<true><<<gS, 256, SMEMS>>>(hBh, wgt + 2 * 4096, bg3, ndst, nsrc, hAh, M, 64, 64);

    gather_h<<<gatherBlocks, 256>>>(hAh, rowptr, col, hBh);
    gemm_f16_s<false><<<gS, 256, SMEMS>>>(hBh, wgt + 3 * 4096, bg4, ndst, nullptr, out, M, 40, 64);
}

// round 14
// speedup vs baseline: 1.1238x; 1.0290x over previous
#include <cuda_runtime.h>
#include <cuda_fp16.h>
#include <cstdint>

#define NN 100000
#define NE 1600000
#define NB_SCAN 98   // ceil(NN/1024)

// ---------------- scratch (device globals; no allocation allowed) ----------
__device__ float g_h1[(size_t)NN * 512];   // h1 as fp16 (aliased)
__device__ float g_h2[(size_t)NN * 256];   // xh (fp16) staged here (dead after GEMM1)
__device__ float g_hA[(size_t)NN * 64];    // fp16 node features (aliased)
__device__ float g_hB[(size_t)NN * 64];    // fp16 agg (aliased)
__device__ float g_degf[NN];
__device__ float g_nrm[2 * NN];      // [0..NN)=norm_src, [NN..2NN)=norm_dst
__device__ int   g_cnt[NN];
__device__ int   g_rowptr[NN];
__device__ int   g_cursor[NN];
__device__ int   g_bsum[128];
__device__ int   g_col[NE];
__device__ __half g_w1t[512 * 512];
__device__ __half g_w2t[256 * 512];
__device__ __half g_w3t[64 * 256];
__device__ __half g_wgt[4][64 * 64];

// ---------------- utility kernels -------------------------------------------
__global__ void zero_fi(float* __restrict__ pf, int* __restrict__ pi, int n) {
    int i = blockIdx.x * blockDim.x + threadIdx.x;
    if (i < n) { pf[i] = 0.0f; pi[i] = 0; }
}
__global__ void deg_hist_kernel(const int* __restrict__ src, const int* __restrict__ dst,
                                float* __restrict__ degf, int* __restrict__ cnt) {
    int e = blockIdx.x * blockDim.x + threadIdx.x;
    if (e < NE) {
        atomicAdd(&degf[src[e]], 1.0f);
        atomicAdd(&cnt[dst[e]], 1);
    }
}

__device__ __forceinline__ uint32_t packh2(float lo, float hi) {
    uint32_t r;
    asm("cvt.rn.f16x2.f32 %0, %1, %2;" : "=r"(r) : "f"(hi), "f"(lo));
    return r;
}

__global__ void cvt_f2h(const float* __restrict__ in, __half* __restrict__ out, int n4) {
    int i = blockIdx.x * blockDim.x + threadIdx.x;
    if (i < n4) {
        float4 v = ((const float4*)in)[i];
        uint2 o;
        o.x = packh2(v.x, v.y);
        o.y = packh2(v.z, v.w);
        ((uint2*)out)[i] = o;
    }
}

__global__ void wcvt_kernel(const float* __restrict__ W, __half* __restrict__ Wt,
                            int K, int N, int Npad) {
    int i = blockIdx.x * blockDim.x + threadIdx.x;
    if (i < Npad * K) {
        int n = i / K, k = i % K;
        Wt[i] = (n < N) ? __float2half(W[(size_t)k * N + n]) : __half(0.f);
    }
}
__global__ void wcvt3g_kernel(const float* __restrict__ W3, __half* __restrict__ w3t,
                              const float* __restrict__ Wg1, const float* __restrict__ Wg2,
                              const float* __restrict__ Wg3, const float* __restrict__ Wg4,
                              __half* __restrict__ Wt) {
    int i = blockIdx.x * blockDim.x + threadIdx.x;
    if (i < 64 * 256) {
        int n = i / 256, k = i % 256;
        w3t[i] = __float2half(W3[(size_t)k * 64 + n]);
    } else if (i < 64 * 256 + 4 * 64 * 64) {
        int j = i - 64 * 256;
        int which = j >> 12;
        int r = j & 4095;
        int n = r >> 6, k = r & 63;
        const float* W = (which == 0) ? Wg1 : (which == 1) ? Wg2 : (which == 2) ? Wg3 : Wg4;
        int N = (which == 3) ? 40 : 64;
        Wt[j] = (n < N) ? __float2half(W[(size_t)k * N + n]) : __half(0.f);
    }
}

// ---------------- CSR build (scan1 also computes norms) ----------------------
__global__ void scan1(const int* __restrict__ cnt, int* __restrict__ excl,
                      int* __restrict__ bsum, const float* __restrict__ degf,
                      float* __restrict__ nrm) {
    __shared__ int sh[1024];
    int tid = threadIdx.x;
    int i = blockIdx.x * 1024 + tid;
    int v = (i < NN) ? cnt[i] : 0;
    if (i < NN) {
        nrm[i] = rsqrtf(fmaxf(degf[i], 1.0f));
        nrm[NN + i] = rsqrtf(fmaxf((float)v, 1.0f));
    }
    sh[tid] = v;
    __syncthreads();
    for (int off = 1; off < 1024; off <<= 1) {
        int t = (tid >= off) ? sh[tid - off] : 0;
        __syncthreads();
        sh[tid] += t;
        __syncthreads();
    }
    if (i < NN) excl[i] = sh[tid] - v;
    if (tid == 1023) bsum[blockIdx.x] = sh[1023];
}
__global__ void scan2(int* __restrict__ bsum) {
    __shared__ int sh[128];
    int tid = threadIdx.x;
    int v = (tid < NB_SCAN) ? bsum[tid] : 0;
    sh[tid] = v;
    __syncthreads();
    for (int off = 1; off < 128; off <<= 1) {
        int t = (tid >= off) ? sh[tid - off] : 0;
        __syncthreads();
        sh[tid] += t;
        __syncthreads();
    }
    if (tid < NB_SCAN) bsum[tid] = sh[tid] - v;
}
__global__ void scan3(int* __restrict__ excl, const int* __restrict__ bsum,
                      int* __restrict__ cursor) {
    int i = blockIdx.x * 1024 + threadIdx.x;
    if (i < NN) {
        int r = excl[i] + bsum[blockIdx.x];
        excl[i] = r;
        cursor[i] = r;
    }
}
__global__ void fill_csr(const int* __restrict__ src, const int* __restrict__ dst,
                         int* __restrict__ cursor, int* __restrict__ col) {
    int e = blockIdx.x * blockDim.x + threadIdx.x;
    if (e < NE) {
        int p = atomicAdd(&cursor[dst[e]], 1);
        col[p] = src[e];
    }
}

// ---------------- CSR gather (fp16 rows, fp32 accumulate, 4x unrolled) -------
__global__ void gather_h(const __half* __restrict__ h, const int* __restrict__ rowptr,
                         const int* __restrict__ col, __half* __restrict__ agg) {
    int t = threadIdx.x;
    int node = blockIdx.x * 32 + (t >> 3);
    if (node >= NN) return;
    int c = t & 7;
    int beg = rowptr[node];
    int end = (node == NN - 1) ? NE : rowptr[node + 1];
    float acc[8] = {0.f, 0.f, 0.f, 0.f, 0.f, 0.f, 0.f, 0.f};
    int i = beg;
    for (; i + 3 < end; i += 4) {
        int s0 = __ldg(&col[i]);
        int s1 = __ldg(&col[i + 1]);
        int s2 = __ldg(&col[i + 2]);
        int s3 = __ldg(&col[i + 3]);
        uint4 v0 = ((const uint4*)(h + (size_t)s0 * 64))[c];
        uint4 v1 = ((const uint4*)(h + (size_t)s1 * 64))[c];
        uint4 v2 = ((const uint4*)(h + (size_t)s2 * 64))[c];
        uint4 v3 = ((const uint4*)(h + (size_t)s3 * 64))[c];
        const __half2* a0 = (const __half2*)&v0;
        const __half2* a1 = (const __half2*)&v1;
        const __half2* a2 = (const __half2*)&v2;
        const __half2* a3 = (const __half2*)&v3;
#pragma unroll
        for (int j = 0; j < 4; j++) {
            float2 f0 = __half22float2(a0[j]);
            float2 f1 = __half22float2(a1[j]);
            float2 f2 = __half22float2(a2[j]);
            float2 f3 = __half22float2(a3[j]);
            acc[2 * j]     += (f0.x + f1.x) + (f2.x + f3.x);
            acc[2 * j + 1] += (f0.y + f1.y) + (f2.y + f3.y);
        }
    }
    for (; i < end; i++) {
        int s = __ldg(&col[i]);
        uint4 v = ((const uint4*)(h + (size_t)s * 64))[c];
        const __half2* hv = (const __half2*)&v;
#pragma unroll
        for (int j = 0; j < 4; j++) {
            float2 f = __half22float2(hv[j]);
            acc[2 * j] += f.x;
            acc[2 * j + 1] += f.y;
        }
    }
    uint4 o;
    o.x = packh2(acc[0], acc[1]);
    o.y = packh2(acc[2], acc[3]);
    o.z = packh2(acc[4], acc[5]);
    o.w = packh2(acc[6], acc[7]);
    ((uint4*)(agg + (size_t)node * 64))[c] = o;
}

// ---------------- common async copy helper ----------------------------------
__device__ __forceinline__ void cp_async16(uint32_t saddr, const void* gaddr, int sz) {
    asm volatile("cp.async.cg.shared.global [%0], [%1], 16, %2;\n"
                 :: "r"(saddr), "l"(gaddr), "r"(sz));
}

// ============================================================================
// fp16 TC GEMM (extra-wide, BK=64): CTA tile 128x256x64, 3-stage, stride 72.
// Used for GEMM1 (N=512, K=512). 8 warps (2x4), warp tile 64x64.
// ============================================================================
__global__ void __launch_bounds__(256, 1)
gemm_f16w(const __half* __restrict__ A, const __half* __restrict__ Wt,
          const float* __restrict__ bias, __half* __restrict__ Cout,
          int M, int N, int K) {
    constexpr int SH = 72;
    constexpr int A_BYTES = 128 * SH * 2;
    constexpr int B_BYTES = 256 * SH * 2;
    constexpr int STAGE_BYTES = A_BYTES + B_BYTES;
    extern __shared__ char dsm[];
    uint32_t smem_u = (uint32_t)__cvta_generic_to_shared(dsm);

    const int tid = threadIdx.x;
    const int lane = tid & 31;
    const int warp = tid >> 5;
    const int wm = (warp >> 2) * 64;
    const int wn = (warp & 3) * 64;
    const int rowBase = blockIdx.y * 128;
    const int colBase = blockIdx.x * 256;
    const int KT = K / 64;

    const int lrow = lane & 7;
    const int sub = lane >> 3;
    const int subB = sub & 1;

    float acc[4][8][4];
#pragma unroll
    for (int i = 0; i < 4; i++)
#pragma unroll
        for (int j = 0; j < 8; j++)
#pragma unroll
            for (int q = 0; q < 4; q++) acc[i][j][q] = 0.0f;

    auto issue = [&](int stage, int kt) {
        const int k0 = kt * 64;
        uint32_t base = smem_u + stage * STAGE_BYTES;
#pragma unroll
        for (int i = 0; i < 4; i++) {
            int idx = tid + i * 256;
            int m = idx >> 3;
            int cq = idx & 7;
            const __half* gsrc = A + (size_t)(rowBase + m) * K + k0 + cq * 8;
            cp_async16(base + (m * SH + cq * 8) * 2, gsrc, (rowBase + m < M) ? 16 : 0);
        }
#pragma unroll
        for (int i = 0; i < 8; i++) {
            int idx = tid + i * 256;
            int n = idx >> 3;
            int cq = idx & 7;
            const __half* gsrc = Wt + (size_t)(colBase + n) * K + k0 + cq * 8;
            cp_async16(base + A_BYTES + (n * SH + cq * 8) * 2, gsrc, 16);
        }
    };

#pragma unroll
    for (int p = 0; p < 2; p++) {
        issue(p, p);
        asm volatile("cp.async.commit_group;\n" ::: "memory");
    }

    for (int kt = 0; kt < KT; kt++) {
        asm volatile("cp.async.wait_group 1;\n" ::: "memory");
        __syncthreads();
        const int stage = kt % 3;
        uint32_t As_u = smem_u + stage * STAGE_BYTES;
        uint32_t Bs_u = As_u + A_BYTES;

#pragma unroll
        for (int ks = 0; ks < 4; ks++) {
            const int kb = ks * 16;
            uint32_t a[4][4], b[8][2];
#pragma unroll
            for (int mt = 0; mt < 4; mt++) {
                int r = wm + mt * 16 + (sub & 1) * 8 + lrow;
                uint32_t addr = As_u + (r * SH + kb + (sub >> 1) * 8) * 2;
                asm volatile(
                    "ldmatrix.sync.aligned.m8n8.x4.shared.b16 {%0,%1,%2,%3}, [%4];"
                    : "=r"(a[mt][0]), "=r"(a[mt][1]), "=r"(a[mt][2]), "=r"(a[mt][3])
                    : "r"(addr));
            }
#pragma unroll
            for (int nt = 0; nt < 8; nt++) {
                int n = wn + nt * 8 + lrow;
                uint32_t addr = Bs_u + (n * SH + kb + subB * 8) * 2;
                asm volatile(
                    "ldmatrix.sync.aligned.m8n8.x2.shared.b16 {%0,%1}, [%2];"
                    : "=r"(b[nt][0]), "=r"(b[nt][1]) : "r"(addr));
            }
#pragma unroll
            for (int mt = 0; mt < 4; mt++)
#pragma unroll
                for (int nt = 0; nt < 8; nt++) {
                    asm volatile(
                        "mma.sync.aligned.m16n8k16.row.col.f32.f16.f16.f32 "
                        "{%0,%1,%2,%3}, {%4,%5,%6,%7}, {%8,%9}, {%0,%1,%2,%3};"
                        : "+f"(acc[mt][nt][0]), "+f"(acc[mt][nt][1]),
                          "+f"(acc[mt][nt][2]), "+f"(acc[mt][nt][3])
                        : "r"(a[mt][0]), "r"(a[mt][1]), "r"(a[mt][2]), "r"(a[mt][3]),
                          "r"(b[nt][0]), "r"(b[nt][1]));
                }
        }
        if (kt + 2 < KT) issue((kt + 2) % 3, kt + 2);
        asm volatile("cp.async.commit_group;\n" ::: "memory");
    }

    const int g = lane >> 2;
    const int tq = lane & 3;
#pragma unroll
    for (int mt = 0; mt < 4; mt++) {
        int r0 = rowBase + wm + mt * 16 + g;
        int r1 = r0 + 8;
#pragma unroll
        for (int nt = 0; nt < 8; nt++) {
            int c = colBase + wn + nt * 8 + 2 * tq;
            float bx = __ldg(&bias[c]);
            float by = __ldg(&bias[c + 1]);
            if (r0 < M)
                *(uint32_t*)(Cout + (size_t)r0 * N + c) =
                    packh2(fmaxf(acc[mt][nt][0] + bx, 0.f), fmaxf(acc[mt][nt][1] + by, 0.f));
            if (r1 < M)
                *(uint32_t*)(Cout + (size_t)r1 * N + c) =
                    packh2(fmaxf(acc[mt][nt][2] + bx, 0.f), fmaxf(acc[mt][nt][3] + by, 0.f));
        }
    }
}

// ============================================================================
// Fused GEMM2+GEMM3 (BK=64 mainloop): per 128-row slab,
//   h2 = relu(h1 @ W2t^T + b2)  kept in SMEM; hA = nsrc.*relu(h2@W3t^T+b3)
// ============================================================================
__global__ void __launch_bounds__(256, 1)
gemm_f16_23(const __half* __restrict__ A, const __half* __restrict__ W2t,
            const float* __restrict__ b2, const __half* __restrict__ W3t,
            const float* __restrict__ b3, const float* __restrict__ nsrc,
            __half* __restrict__ Cout, int M) {
    constexpr int K = 512;
    constexpr int SH = 72;
    constexpr int A_BYTES = 128 * SH * 2;       // 18432
    constexpr int B_BYTES = 256 * SH * 2;       // 36864
    constexpr int STAGE_BYTES = A_BYTES + B_BYTES;   // 55296
    constexpr int W3_OFF = 3 * STAGE_BYTES;     // 165888
    constexpr int S2 = 264;                     // h2/W3 smem stride (halves)
    extern __shared__ char dsm[];
    uint32_t smem_u = (uint32_t)__cvta_generic_to_shared(dsm);
    uint32_t w3_u = smem_u + W3_OFF;
    uint32_t h2_u = smem_u;                     // reuses stage area post-drain

    const int tid = threadIdx.x;
    const int lane = tid & 31;
    const int warp = tid >> 5;
    const int rowBase = blockIdx.y * 128;
    const int KT = K / 64;                      // 8

    const int lrow = lane & 7;
    const int sub = lane >> 3;
    const int subB = sub & 1;
    const int g = lane >> 2;
    const int tq = lane & 3;

    // ---- prefetch W3 (64x256 halves = 2048 x 16B, 8/thread), own group ----
#pragma unroll
    for (int i = 0; i < 8; i++) {
        int idx = tid + i * 256;
        int n = idx >> 5;
        int cq = idx & 31;
        cp_async16(w3_u + (n * S2 + cq * 8) * 2, W3t + (size_t)n * 256 + cq * 8, 16);
    }
    asm volatile("cp.async.commit_group;\n" ::: "memory");

    const int wm = (warp >> 2) * 64;
    const int wn = (warp & 3) * 64;

    float acc[4][8][4];
#pragma unroll
    for (int i = 0; i < 4; i++)
#pragma unroll
        for (int j = 0; j < 8; j++)
#pragma unroll
            for (int q = 0; q < 4; q++) acc[i][j][q] = 0.0f;

    auto issue = [&](int stage, int kt) {
        const int k0 = kt * 64;
        uint32_t base = smem_u + stage * STAGE_BYTES;
#pragma unroll
        for (int i = 0; i < 4; i++) {
            int idx = tid + i * 256;
            int m = idx >> 3;
            int cq = idx & 7;
            const __half* gsrc = A + (size_t)(rowBase + m) * K + k0 + cq * 8;
            cp_async16(base + (m * SH + cq * 8) * 2, gsrc, (rowBase + m < M) ? 16 : 0);
        }
#pragma unroll
        for (int i = 0; i < 8; i++) {
            int idx = tid + i * 256;
            int n = idx >> 3;
            int cq = idx & 7;
            const __half* gsrc = W2t + (size_t)n * K + k0 + cq * 8;
            cp_async16(base + A_BYTES + (n * SH + cq * 8) * 2, gsrc, 16);
        }
    };

#pragma unroll
    for (int p = 0; p < 2; p++) {
        issue(p, p);
        asm volatile("cp.async.commit_group;\n" ::: "memory");
    }

    for (int kt = 0; kt < KT; kt++) {
        asm volatile("cp.async.wait_group 1;\n" ::: "memory");
        __syncthreads();
        const int stage = kt % 3;
        uint32_t As_u = smem_u + stage * STAGE_BYTES;
        uint32_t Bs_u = As_u + A_BYTES;

#pragma unroll
        for (int ks = 0; ks < 4; ks++) {
            const int kb = ks * 16;
            uint32_t a[4][4], b[8][2];
#pragma unroll
            for (int mt = 0; mt < 4; mt++) {
                int r = wm + mt * 16 + (sub & 1) * 8 + lrow;
                uint32_t addr = As_u + (r * SH + kb + (sub >> 1) * 8) * 2;
                asm volatile(
                    "ldmatrix.sync.aligned.m8n8.x4.shared.b16 {%0,%1,%2,%3}, [%4];"
                    : "=r"(a[mt][0]), "=r"(a[mt][1]), "=r"(a[mt][2]), "=r"(a[mt][3])
                    : "r"(addr));
            }
#pragma unroll
            for (int nt = 0; nt < 8; nt++) {
                int n = wn + nt * 8 + lrow;
                uint32_t addr = Bs_u + (n * SH + kb + subB * 8) * 2;
                asm volatile(
                    "ldmatrix.sync.aligned.m8n8.x2.shared.b16 {%0,%1}, [%2];"
                    : "=r"(b[nt][0]), "=r"(b[nt][1]) : "r"(addr));
            }
#pragma unroll
            for (int mt = 0; mt < 4; mt++)
#pragma unroll
                for (int nt = 0; nt < 8; nt++) {
                    asm volatile(
                        "mma.sync.aligned.m16n8k16.row.col.f32.f16.f16.f32 "
                        "{%0,%1,%2,%3}, {%4,%5,%6,%7}, {%8,%9}, {%0,%1,%2,%3};"
                        : "+f"(acc[mt][nt][0]), "+f"(acc[mt][nt][1]),
                          "+f"(acc[mt][nt][2]), "+f"(acc[mt][nt][3])
                        : "r"(a[mt][0]), "r"(a[mt][1]), "r"(a[mt][2]), "r"(a[mt][3]),
                          "r"(b[nt][0]), "r"(b[nt][1]));
                }
        }
        if (kt + 2 < KT) issue((kt + 2) % 3, kt + 2);
        asm volatile("cp.async.commit_group;\n" ::: "memory");
    }

    // ---- drain, write h2 tile into smem (stride S2) ----
    asm volatile("cp.async.wait_group 0;\n" ::: "memory");
    __syncthreads();
    __half* h2s = (__half*)dsm;
#pragma unroll
    for (int mt = 0; mt < 4; mt++) {
        int lr0 = wm + mt * 16 + g;
        int lr1 = lr0 + 8;
#pragma unroll
        for (int nt = 0; nt < 8; nt++) {
            int c = wn + nt * 8 + 2 * tq;
            float bx = __ldg(&b2[c]);
            float by = __ldg(&b2[c + 1]);
            *(uint32_t*)(h2s + lr0 * S2 + c) =
                packh2(fmaxf(acc[mt][nt][0] + bx, 0.f), fmaxf(acc[mt][nt][1] + by, 0.f));
            *(uint32_t*)(h2s + lr1 * S2 + c) =
                packh2(fmaxf(acc[mt][nt][2] + bx, 0.f), fmaxf(acc[mt][nt][3] + by, 0.f));
        }
    }
    __syncthreads();

    // ---- GEMM3: h2s[128x256] @ W3^T -> 128x64 ----
    const int wm2 = (warp >> 1) * 32;
    const int wn2 = (warp & 1) * 32;

    float acc2[2][4][4];
#pragma unroll
    for (int i = 0; i < 2; i++)
#pragma unroll
        for (int j = 0; j < 4; j++)
#pragma unroll
            for (int q = 0; q < 4; q++) acc2[i][j][q] = 0.0f;

#pragma unroll
    for (int ks = 0; ks < 16; ks++) {
        const int kb = ks * 16;
        uint32_t a[2][4], b[4][2];
#pragma unroll
        for (int mt = 0; mt < 2; mt++) {
            int r = wm2 + mt * 16 + (sub & 1) * 8 + lrow;
            uint32_t addr = h2_u + (r * S2 + kb + (sub >> 1) * 8) * 2;
            asm volatile(
                "ldmatrix.sync.aligned.m8n8.x4.shared.b16 {%0,%1,%2,%3}, [%4];"
                : "=r"(a[mt][0]), "=r"(a[mt][1]), "=r"(a[mt][2]), "=r"(a[mt][3])
                : "r"(addr));
        }
#pragma unroll
        for (int nt = 0; nt < 4; nt++) {
            int n = wn2 + nt * 8 + lrow;
            uint32_t addr = w3_u + (n * S2 + kb + subB * 8) * 2;
            asm volatile(
                "ldmatrix.sync.aligned.m8n8.x2.shared.b16 {%0,%1}, [%2];"
                : "=r"(b[nt][0]), "=r"(b[nt][1]) : "r"(addr));
        }
#pragma unroll
        for (int mt = 0; mt < 2; mt++)
#pragma unroll
            for (int nt = 0; nt < 4; nt++) {
                asm volatile(
                    "mma.sync.aligned.m16n8k16.row.col.f32.f16.f16.f32 "
                    "{%0,%1,%2,%3}, {%4,%5,%6,%7}, {%8,%9}, {%0,%1,%2,%3};"
                    : "+f"(acc2[mt][nt][0]), "+f"(acc2[mt][nt][1]),
                      "+f"(acc2[mt][nt][2]), "+f"(acc2[mt][nt][3])
                    : "r"(a[mt][0]), "r"(a[mt][1]), "r"(a[mt][2]), "r"(a[mt][3]),
                      "r"(b[nt][0]), "r"(b[nt][1]));
            }
    }

#pragma unroll
    for (int mt = 0; mt < 2; mt++) {
        int r0 = rowBase + wm2 + mt * 16 + g;
        int r1 = r0 + 8;
        float w0 = (r0 < M) ? nsrc[r0] : 0.f;
        float w1 = (r1 < M) ? nsrc[r1] : 0.f;
#pragma unroll
        for (int nt = 0; nt < 4; nt++) {
            int c = wn2 + nt * 8 + 2 * tq;
            float bx = __ldg(&b3[c]);
            float by = __ldg(&b3[c + 1]);
            if (r0 < M)
                *(uint32_t*)(Cout + (size_t)r0 * 64 + c) =
                    packh2(w0 * fmaxf(acc2[mt][nt][0] + bx, 0.f),
                           w0 * fmaxf(acc2[mt][nt][1] + by, 0.f));
            if (r1 < M)
                *(uint32_t*)(Cout + (size_t)r1 * 64 + c) =
                    packh2(w1 * fmaxf(acc2[mt][nt][2] + bx, 0.f),
                           w1 * fmaxf(acc2[mt][nt][3] + by, 0.f));
        }
    }
}

// ============================================================================
// fp16 tensor-core GEMM (narrow): tile 128x64, BK=64, row scales rs/ws.
// ============================================================================
template <bool OUT_HALF>
__global__ void __launch_bounds__(256, 2)
gemm_f16_s(const __half* __restrict__ A, const __half* __restrict__ Wt,
           const float* __restrict__ bias, const float* __restrict__ rs,
           const float* __restrict__ ws, void* __restrict__ Cout,
           int M, int N, int K) {
    constexpr int STRIDE_H = 72;
    constexpr int A_BYTES = 128 * STRIDE_H * 2;
    constexpr int B_BYTES = 64 * STRIDE_H * 2;
    constexpr int STAGE_BYTES = A_BYTES + B_BYTES;
    extern __shared__ char dsm[];
    uint32_t smem_u = (uint32_t)__cvta_generic_to_shared(dsm);

    const int tid = threadIdx.x;
    const int lane = tid & 31;
    const int warp = tid >> 5;
    const int wm = (warp >> 1) * 32;
    const int wn = (warp & 1) * 32;
    const int rowBase = blockIdx.y * 128;
    const int KT = K / 64;

    const int lrow = lane & 7;
    const int sub = lane >> 3;
    const int subB = sub & 1;

    float acc[2][4][4];
#pragma unroll
    for (int i = 0; i < 2; i++)
#pragma unroll
        for (int j = 0; j < 4; j++)
#pragma unroll
            for (int q = 0; q < 4; q++) acc[i][j][q] = 0.0f;

    auto issue = [&](int stage, int kt) {
        const int k0 = kt * 64;
        uint32_t base = smem_u + stage * STAGE_BYTES;
#pragma unroll
        for (int i = 0; i < 4; i++) {
            int idx = tid + i * 256;
            int m = idx >> 3;
            int cq = idx & 7;
            const __half* gsrc = A + (size_t)(rowBase + m) * K + k0 + cq * 8;
            cp_async16(base + m * 144 + cq * 16, gsrc, (rowBase + m < M) ? 16 : 0);
        }
#pragma unroll
        for (int i = 0; i < 2; i++) {
            int idx = tid + i * 256;
            int n = idx >> 3;
            int cq = idx & 7;
            const __half* gsrc = Wt + (size_t)n * K + k0 + cq * 8;
            cp_async16(base + A_BYTES + n * 144 + cq * 16, gsrc, 16);
        }
    };

#pragma unroll
    for (int p = 0; p < 2; p++) {
        if (p < KT) issue(p, p);
        asm volatile("cp.async.commit_group;\n" ::: "memory");
    }

    for (int kt = 0; kt < KT; kt++) {
        asm volatile("cp.async.wait_group 1;\n" ::: "memory");
        __syncthreads();
        const int stage = kt % 3;
        uint32_t As_u = smem_u + stage * STAGE_BYTES;
        uint32_t Bs_u = As_u + A_BYTES;

#pragma unroll
        for (int ks = 0; ks < 4; ks++) {
            const int kb = ks * 16;
            uint32_t a[2][4], b[4][2];
#pragma unroll
            for (int mt = 0; mt < 2; mt++) {
                int r = wm + mt * 16 + (sub & 1) * 8 + lrow;
                uint32_t addr = As_u + (r * STRIDE_H + kb + (sub >> 1) * 8) * 2;
                asm volatile(
                    "ldmatrix.sync.aligned.m8n8.x4.shared.b16 {%0,%1,%2,%3}, [%4];"
                    : "=r"(a[mt][0]), "=r"(a[mt][1]), "=r"(a[mt][2]), "=r"(a[mt][3])
                    : "r"(addr));
            }
#pragma unroll
            for (int nt = 0; nt < 4; nt++) {
                int n = wn + nt * 8 + lrow;
                uint32_t addr = Bs_u + (n * STRIDE_H + kb + subB * 8) * 2;
                asm volatile(
                    "ldmatrix.sync.aligned.m8n8.x2.shared.b16 {%0,%1}, [%2];"
                    : "=r"(b[nt][0]), "=r"(b[nt][1]) : "r"(addr));
            }
#pragma unroll
            for (int mt = 0; mt < 2; mt++)
#pragma unroll
                for (int nt = 0; nt < 4; nt++) {
                    asm volatile(
                        "mma.sync.aligned.m16n8k16.row.col.f32.f16.f16.f32 "
                        "{%0,%1,%2,%3}, {%4,%5,%6,%7}, {%8,%9}, {%0,%1,%2,%3};"
                        : "+f"(acc[mt][nt][0]), "+f"(acc[mt][nt][1]),
                          "+f"(acc[mt][nt][2]), "+f"(acc[mt][nt][3])
                        : "r"(a[mt][0]), "r"(a[mt][1]), "r"(a[mt][2]), "r"(a[mt][3]),
                          "r"(b[nt][0]), "r"(b[nt][1]));
                }
        }
        if (kt + 2 < KT) issue((kt + 2) % 3, kt + 2);
        asm volatile("cp.async.commit_group;\n" ::: "memory");
    }

    const int g = lane >> 2;
    const int tq = lane & 3;
#pragma unroll
    for (int mt = 0; mt < 2; mt++) {
        int r0 = rowBase + wm + mt * 16 + g;
        int r1 = r0 + 8;
        float rs0 = 1.f, rs1 = 1.f, ws0 = 1.f, ws1 = 1.f;
        if (rs) {
            if (r0 < M) rs0 = rs[r0];
            if (r1 < M) rs1 = rs[r1];
        }
        if (ws) {
            if (r0 < M) ws0 = ws[r0];
            if (r1 < M) ws1 = ws[r1];
        }
#pragma unroll
        for (int nt = 0; nt < 4; nt++) {
            int c = wn + nt * 8 + 2 * tq;
            float bx = (c < N) ? __ldg(&bias[c]) : 0.f;
            float by = (c + 1 < N) ? __ldg(&bias[c + 1]) : 0.f;
            if (r0 < M) {
                float vx = ws0 * fmaxf(acc[mt][nt][0] * rs0 + bx, 0.f);
                float vy = ws0 * fmaxf(acc[mt][nt][1] * rs0 + by, 0.f);
                if (OUT_HALF) {
                    if (c + 1 < N)
                        *(uint32_t*)((__half*)Cout + (size_t)r0 * N + c) = packh2(vx, vy);
                } else {
                    if (c + 1 < N)
                        *(float2*)((float*)Cout + (size_t)r0 * N + c) = make_float2(vx, vy);
                    else if (c < N)
                        ((float*)Cout)[(size_t)r0 * N + c] = vx;
                }
            }
            if (r1 < M) {
                float vx = ws1 * fmaxf(acc[mt][nt][2] * rs1 + bx, 0.f);
                float vy = ws1 * fmaxf(acc[mt][nt][3] * rs1 + by, 0.f);
                if (OUT_HALF) {
                    if (c + 1 < N)
                        *(uint32_t*)((__half*)Cout + (size_t)r1 * N + c) = packh2(vx, vy);
                } else {
                    if (c + 1 < N)
                        *(float2*)((float*)Cout + (size_t)r1 * N + c) = make_float2(vx, vy);
                    else if (c < N)
                        ((float*)Cout)[(size_t)r1 * N + c] = vx;
                }
            }
        }
    }
}

// ---------------- host orchestration ---------------------------------------
extern "C" void kernel_launch(void* const* d_in, const int* in_sizes, int n_in,
                              void* d_out, int out_size) {
    const float* x   = (const float*)d_in[0];
    const int* src   = (const int*)d_in[1];
    const int* dst   = (const int*)d_in[2];
    const float* W1  = (const float*)d_in[3];
    const float* b1  = (const float*)d_in[4];
    const float* W2  = (const float*)d_in[5];
    const float* b2  = (const float*)d_in[6];
    const float* W3  = (const float*)d_in[7];
    const float* b3  = (const float*)d_in[8];
    const float* Wg1 = (const float*)d_in[9];
    const float* bg1 = (const float*)d_in[10];
    const float* Wg2 = (const float*)d_in[11];
    const float* bg2 = (const float*)d_in[12];
    const float* Wg3 = (const float*)d_in[13];
    const float* bg3 = (const float*)d_in[14];
    const float* Wg4 = (const float*)d_in[15];
    const float* bg4 = (const float*)d_in[16];
    float* out = (float*)d_out;

    float *h1, *h2, *hA, *hB, *degf, *nrm;
    int *cnt, *rowptr, *cursor, *bsum, *col;
    __half *w1t, *w2t, *w3t, *wgt;
    cudaGetSymbolAddress((void**)&h1, g_h1);
    cudaGetSymbolAddress((void**)&h2, g_h2);
    cudaGetSymbolAddress((void**)&hA, g_hA);
    cudaGetSymbolAddress((void**)&hB, g_hB);
    cudaGetSymbolAddress((void**)&degf, g_degf);
    cudaGetSymbolAddress((void**)&nrm, g_nrm);
    cudaGetSymbolAddress((void**)&cnt, g_cnt);
    cudaGetSymbolAddress((void**)&rowptr, g_rowptr);
    cudaGetSymbolAddress((void**)&cursor, g_cursor);
    cudaGetSymbolAddress((void**)&bsum, g_bsum);
    cudaGetSymbolAddress((void**)&col, g_col);
    cudaGetSymbolAddress((void**)&w1t, g_w1t);
    cudaGetSymbolAddress((void**)&w2t, g_w2t);
    cudaGetSymbolAddress((void**)&w3t, g_w3t);
    cudaGetSymbolAddress((void**)&wgt, g_wgt);

    __half* xh  = (__half*)h2;   // x fp16 staged in g_h2 (dead after GEMM1)
    __half* h1h = (__half*)h1;
    __half* hAh = (__half*)hA;
    __half* hBh = (__half*)hB;

    const float* nsrc = nrm;
    const float* ndst = nrm + NN;

    constexpr int SMEMW  = 3 * ((128 + 256) * 72 * 2);          // 165888
    constexpr int SMEM23 = 3 * ((128 + 256) * 72 * 2) + 64 * 264 * 2;  // 199680
    constexpr int SMEMS  = 3 * ((128 + 64) * 72 * 2);
    cudaFuncSetAttribute(gemm_f16w, cudaFuncAttributeMaxDynamicSharedMemorySize, SMEMW);
    cudaFuncSetAttribute(gemm_f16_23, cudaFuncAttributeMaxDynamicSharedMemorySize, SMEM23);
    cudaFuncSetAttribute(gemm_f16_s<true>,  cudaFuncAttributeMaxDynamicSharedMemorySize, SMEMS);
    cudaFuncSetAttribute(gemm_f16_s<false>, cudaFuncAttributeMaxDynamicSharedMemorySize, SMEMS);

    // side stream + events, created once (host objects; no device allocation)
    static cudaStream_t s2 = nullptr;
    static cudaEvent_t evFork = nullptr, evW1 = nullptr, evB = nullptr;
    if (!s2) {
        cudaStreamCreateWithFlags(&s2, cudaStreamNonBlocking);
        cudaEventCreateWithFlags(&evFork, cudaEventDisableTiming);
        cudaEventCreateWithFlags(&evW1, cudaEventDisableTiming);
        cudaEventCreateWithFlags(&evB, cudaEventDisableTiming);
    }

    const int M = NN;
    const int NYT = (M + 127) / 128;
    dim3 gS(1, NYT);

    // ---- fork side chain (weights + CSR) ----
    cudaEventRecord(evFork, 0);
    cudaStreamWaitEvent(s2, evFork, 0);
    wcvt_kernel<<<(512 * 512 + 255) / 256, 256, 0, s2>>>(W1, w1t, 512, 512, 512);
    cudaEventRecord(evW1, s2);
    wcvt_kernel<<<(512 * 256 + 255) / 256, 256, 0, s2>>>(W2, w2t, 512, 256, 256);
    zero_fi<<<(NN + 255) / 256, 256, 0, s2>>>(degf, cnt, NN);
    deg_hist_kernel<<<(NE + 255) / 256, 256, 0, s2>>>(src, dst, degf, cnt);
    scan1<<<NB_SCAN, 1024, 0, s2>>>(cnt, rowptr, bsum, degf, nrm);
    scan2<<<1, 128, 0, s2>>>(bsum);
    scan3<<<NB_SCAN, 1024, 0, s2>>>(rowptr, bsum, cursor);
    fill_csr<<<(NE + 255) / 256, 256, 0, s2>>>(src, dst, cursor, col);
    wcvt3g_kernel<<<(64 * 256 + 4 * 64 * 64 + 255) / 256, 256, 0, s2>>>(
        W3, w3t, Wg1, Wg2, Wg3, Wg4, wgt);
    cudaEventRecord(evB, s2);

    // ---- main chain ----
    cvt_f2h<<<(NN * 512 / 4 + 255) / 256, 256>>>(x, xh, NN * 512 / 4);
    cudaStreamWaitEvent(0, evW1, 0);
    gemm_f16w<<<dim3(2, NYT), 256, SMEMW>>>(xh, w1t, b1, h1h, M, 512, 512);
    cudaStreamWaitEvent(0, evB, 0);
    gemm_f16_23<<<dim3(1, NYT), 256, SMEM23>>>(h1h, w2t, b2, w3t, b3, nsrc, hAh, M);

    const int gatherBlocks = (NN + 31) / 32;

    gather_h<<<gatherBlocks, 256>>>(hAh, rowptr, col, hBh);
    gemm_f16_s<true><<<gS, 256, SMEMS>>>(hBh, wgt + 0 * 4096, bg1, ndst, nsrc, hAh, M, 64, 64);

    gather_h<<<gatherBlocks, 256>>>(hAh, rowptr, col, hBh);
    gemm_f16_s<true><<<gS, 256, SMEMS>>>(hBh, wgt + 1 * 4096, bg2, ndst, nsrc, hAh, M, 64, 64);

    gather_h<<<gatherBlocks, 256>>>(hAh, rowptr, col, hBh);
    gemm_f16_s<true><<<gS, 256, SMEMS>>>(hBh, wgt + 2 * 4096, bg3, ndst, nsrc, hAh, M, 64, 64);

    gather_h<<<gatherBlocks, 256>>>(hAh, rowptr, col, hBh);
    gemm_f16_s<false><<<gS, 256, SMEMS>>>(hBh, wgt + 3 * 4096, bg4, ndst, nullptr, out, M, 40, 64);
}

// round 15
// speedup vs baseline: 1.1332x; 1.0084x over previous
#include <cuda_runtime.h>
#include <cuda_fp16.h>
#include <cstdint>

#define NN 100000
#define NE 1600000
#define NB_SCAN 98   // ceil(NN/1024)

// ---------------- scratch (device globals; no allocation allowed) ----------
__device__ float g_h1[(size_t)NN * 512];   // h1 as fp16 (aliased)
__device__ float g_h2[(size_t)NN * 256];   // xh (fp16) staged here (dead after GEMM1)
__device__ float g_hA[(size_t)NN * 64];    // fp16 node features (aliased)
__device__ float g_hB[(size_t)NN * 64];    // fp16 ping-pong (aliased)
__device__ float g_degf[NN];
__device__ float g_nrm[2 * NN];      // [0..NN)=norm_src, [NN..2NN)=norm_dst
__device__ int   g_cnt[NN];
__device__ int   g_rowptr[NN];
__device__ int   g_cursor[NN];
__device__ int   g_bsum[128];
__device__ int   g_col[NE];
__device__ __half g_w1t[512 * 512];
__device__ __half g_w2t[256 * 512];
__device__ __half g_w3t[64 * 256];
__device__ __half g_wgt[4][64 * 64];

// ---------------- utility kernels -------------------------------------------
__global__ void zero_fi(float* __restrict__ pf, int* __restrict__ pi, int n) {
    int i = blockIdx.x * blockDim.x + threadIdx.x;
    if (i < n) { pf[i] = 0.0f; pi[i] = 0; }
}
__global__ void deg_hist_kernel(const int* __restrict__ src, const int* __restrict__ dst,
                                float* __restrict__ degf, int* __restrict__ cnt) {
    int e = blockIdx.x * blockDim.x + threadIdx.x;
    if (e < NE) {
        atomicAdd(&degf[src[e]], 1.0f);
        atomicAdd(&cnt[dst[e]], 1);
    }
}

__device__ __forceinline__ uint32_t packh2(float lo, float hi) {
    uint32_t r;
    asm("cvt.rn.f16x2.f32 %0, %1, %2;" : "=r"(r) : "f"(hi), "f"(lo));
    return r;
}

__global__ void cvt_f2h(const float* __restrict__ in, __half* __restrict__ out, int n4) {
    int i = blockIdx.x * blockDim.x + threadIdx.x;
    if (i < n4) {
        float4 v = ((const float4*)in)[i];
        uint2 o;
        o.x = packh2(v.x, v.y);
        o.y = packh2(v.z, v.w);
        ((uint2*)out)[i] = o;
    }
}

__global__ void wcvt_kernel(const float* __restrict__ W, __half* __restrict__ Wt,
                            int K, int N, int Npad) {
    int i = blockIdx.x * blockDim.x + threadIdx.x;
    if (i < Npad * K) {
        int n = i / K, k = i % K;
        Wt[i] = (n < N) ? __float2half(W[(size_t)k * N + n]) : __half(0.f);
    }
}
__global__ void wcvt3g_kernel(const float* __restrict__ W3, __half* __restrict__ w3t,
                              const float* __restrict__ Wg1, const float* __restrict__ Wg2,
                              const float* __restrict__ Wg3, const float* __restrict__ Wg4,
                              __half* __restrict__ Wt) {
    int i = blockIdx.x * blockDim.x + threadIdx.x;
    if (i < 64 * 256) {
        int n = i / 256, k = i % 256;
        w3t[i] = __float2half(W3[(size_t)k * 64 + n]);
    } else if (i < 64 * 256 + 4 * 64 * 64) {
        int j = i - 64 * 256;
        int which = j >> 12;
        int r = j & 4095;
        int n = r >> 6, k = r & 63;
        const float* W = (which == 0) ? Wg1 : (which == 1) ? Wg2 : (which == 2) ? Wg3 : Wg4;
        int N = (which == 3) ? 40 : 64;
        Wt[j] = (n < N) ? __float2half(W[(size_t)k * N + n]) : __half(0.f);
    }
}

// ---------------- CSR build (scan1 also computes norms) ----------------------
__global__ void scan1(const int* __restrict__ cnt, int* __restrict__ excl,
                      int* __restrict__ bsum, const float* __restrict__ degf,
                      float* __restrict__ nrm) {
    __shared__ int sh[1024];
    int tid = threadIdx.x;
    int i = blockIdx.x * 1024 + tid;
    int v = (i < NN) ? cnt[i] : 0;
    if (i < NN) {
        nrm[i] = rsqrtf(fmaxf(degf[i], 1.0f));
        nrm[NN + i] = rsqrtf(fmaxf((float)v, 1.0f));
    }
    sh[tid] = v;
    __syncthreads();
    for (int off = 1; off < 1024; off <<= 1) {
        int t = (tid >= off) ? sh[tid - off] : 0;
        __syncthreads();
        sh[tid] += t;
        __syncthreads();
    }
    if (i < NN) excl[i] = sh[tid] - v;
    if (tid == 1023) bsum[blockIdx.x] = sh[1023];
}
__global__ void scan2(int* __restrict__ bsum) {
    __shared__ int sh[128];
    int tid = threadIdx.x;
    int v = (tid < NB_SCAN) ? bsum[tid] : 0;
    sh[tid] = v;
    __syncthreads();
    for (int off = 1; off < 128; off <<= 1) {
        int t = (tid >= off) ? sh[tid - off] : 0;
        __syncthreads();
        sh[tid] += t;
        __syncthreads();
    }
    if (tid < NB_SCAN) bsum[tid] = sh[tid] - v;
}
__global__ void scan3(int* __restrict__ excl, const int* __restrict__ bsum,
                      int* __restrict__ cursor) {
    int i = blockIdx.x * 1024 + threadIdx.x;
    if (i < NN) {
        int r = excl[i] + bsum[blockIdx.x];
        excl[i] = r;
        cursor[i] = r;
    }
}
__global__ void fill_csr(const int* __restrict__ src, const int* __restrict__ dst,
                         int* __restrict__ cursor, int* __restrict__ col) {
    int e = blockIdx.x * blockDim.x + threadIdx.x;
    if (e < NE) {
        int p = atomicAdd(&cursor[dst[e]], 1);
        col[p] = src[e];
    }
}

// ---------------- common async copy helper ----------------------------------
__device__ __forceinline__ void cp_async16(uint32_t saddr, const void* gaddr, int sz) {
    asm volatile("cp.async.cg.shared.global [%0], [%1], 16, %2;\n"
                 :: "r"(saddr), "l"(gaddr), "r"(sz));
}

// ============================================================================
// Fused GCN layer v2: 32 nodes/block, 3125 blocks (same gather parallelism as
// the standalone gather). agg tile kept in SMEM; in-block 32x64 @ 64x64 mma.
//   C[r,:] = ws[r] * relu( rs[r] * (agg @ Wt^T)[r,:] + b ),  N <= 64.
// ============================================================================
template <bool OUT_HALF>
__global__ void __launch_bounds__(256, 4)
gcn_fused2(const __half* __restrict__ h, const int* __restrict__ rowptr,
           const int* __restrict__ col, const __half* __restrict__ Wt,
           const float* __restrict__ bias, const float* __restrict__ rs,
           const float* __restrict__ ws, void* __restrict__ Cout,
           int M, int N) {
    constexpr int SH = 72;
    __shared__ __align__(16) __half As[32 * SH];
    __shared__ __align__(16) __half Bs[64 * SH];
    uint32_t As_u = (uint32_t)__cvta_generic_to_shared(As);
    uint32_t Bs_u = (uint32_t)__cvta_generic_to_shared(Bs);

    const int tid = threadIdx.x;
    const int lane = tid & 31;
    const int warp = tid >> 5;
    const int nodeBase = blockIdx.x * 32;

    // ---- prefetch weights: 64 rows x 64 halves = 512 x 16B, 2/thread ----
#pragma unroll
    for (int i = 0; i < 2; i++) {
        int idx = tid + i * 256;
        int n = idx >> 3;
        int cq = idx & 7;
        cp_async16(Bs_u + (n * SH + cq * 8) * 2, Wt + (size_t)n * 64 + cq * 8, 16);
    }
    asm volatile("cp.async.commit_group;\n" ::: "memory");

    // ---- gather: 8 lanes/node, 1 node per lane-group (same as gather_h) ----
    {
        int localRow = tid >> 3;            // 0..31
        int node = nodeBase + localRow;
        int c = tid & 7;
        float acc[8] = {0.f, 0.f, 0.f, 0.f, 0.f, 0.f, 0.f, 0.f};
        if (node < M) {
            int beg = __ldg(&rowptr[node]);
            int end = (node == NN - 1) ? NE : __ldg(&rowptr[node + 1]);
            int i = beg;
            for (; i + 3 < end; i += 4) {
                int s0 = __ldg(&col[i]);
                int s1 = __ldg(&col[i + 1]);
                int s2 = __ldg(&col[i + 2]);
                int s3 = __ldg(&col[i + 3]);
                uint4 v0 = ((const uint4*)(h + (size_t)s0 * 64))[c];
                uint4 v1 = ((const uint4*)(h + (size_t)s1 * 64))[c];
                uint4 v2 = ((const uint4*)(h + (size_t)s2 * 64))[c];
                uint4 v3 = ((const uint4*)(h + (size_t)s3 * 64))[c];
                const __half2* a0 = (const __half2*)&v0;
                const __half2* a1 = (const __half2*)&v1;
                const __half2* a2 = (const __half2*)&v2;
                const __half2* a3 = (const __half2*)&v3;
#pragma unroll
                for (int j = 0; j < 4; j++) {
                    float2 f0 = __half22float2(a0[j]);
                    float2 f1 = __half22float2(a1[j]);
                    float2 f2 = __half22float2(a2[j]);
                    float2 f3 = __half22float2(a3[j]);
                    acc[2 * j]     += (f0.x + f1.x) + (f2.x + f3.x);
                    acc[2 * j + 1] += (f0.y + f1.y) + (f2.y + f3.y);
                }
            }
            for (; i < end; i++) {
                int s = __ldg(&col[i]);
                uint4 v = ((const uint4*)(h + (size_t)s * 64))[c];
                const __half2* hv = (const __half2*)&v;
#pragma unroll
                for (int j = 0; j < 4; j++) {
                    float2 f = __half22float2(hv[j]);
                    acc[2 * j] += f.x;
                    acc[2 * j + 1] += f.y;
                }
            }
        }
        uint4 o;
        o.x = packh2(acc[0], acc[1]);
        o.y = packh2(acc[2], acc[3]);
        o.z = packh2(acc[4], acc[5]);
        o.w = packh2(acc[6], acc[7]);
        *(uint4*)(As + localRow * SH + c * 8) = o;
    }
    asm volatile("cp.async.wait_group 0;\n" ::: "memory");
    __syncthreads();

    // ---- mma: 32x64 output; warp m = warp>>2 (16 rows), n = warp&3 (16 cols)
    const int wm = (warp >> 2) * 16;
    const int wn = (warp & 3) * 16;
    const int lrow = lane & 7;
    const int sub = lane >> 3;
    const int subB = sub & 1;

    float acc2[2][4];
#pragma unroll
    for (int j = 0; j < 2; j++)
#pragma unroll
        for (int q = 0; q < 4; q++) acc2[j][q] = 0.0f;

#pragma unroll
    for (int ks = 0; ks < 4; ks++) {
        const int kb = ks * 16;
        uint32_t a[4], b[2][2];
        {
            int r = wm + (sub & 1) * 8 + lrow;
            uint32_t addr = As_u + (r * SH + kb + (sub >> 1) * 8) * 2;
            asm volatile(
                "ldmatrix.sync.aligned.m8n8.x4.shared.b16 {%0,%1,%2,%3}, [%4];"
                : "=r"(a[0]), "=r"(a[1]), "=r"(a[2]), "=r"(a[3]) : "r"(addr));
        }
#pragma unroll
        for (int nt = 0; nt < 2; nt++) {
            int n = wn + nt * 8 + lrow;
            uint32_t addr = Bs_u + (n * SH + kb + subB * 8) * 2;
            asm volatile(
                "ldmatrix.sync.aligned.m8n8.x2.shared.b16 {%0,%1}, [%2];"
                : "=r"(b[nt][0]), "=r"(b[nt][1]) : "r"(addr));
        }
#pragma unroll
        for (int nt = 0; nt < 2; nt++) {
            asm volatile(
                "mma.sync.aligned.m16n8k16.row.col.f32.f16.f16.f32 "
                "{%0,%1,%2,%3}, {%4,%5,%6,%7}, {%8,%9}, {%0,%1,%2,%3};"
                : "+f"(acc2[nt][0]), "+f"(acc2[nt][1]),
                  "+f"(acc2[nt][2]), "+f"(acc2[nt][3])
                : "r"(a[0]), "r"(a[1]), "r"(a[2]), "r"(a[3]),
                  "r"(b[nt][0]), "r"(b[nt][1]));
        }
    }

    // ---- epilogue ----
    const int g = lane >> 2;
    const int tq = lane & 3;
    int r0 = nodeBase + wm + g;
    int r1 = r0 + 8;
    float rs0 = 1.f, rs1 = 1.f, ws0 = 1.f, ws1 = 1.f;
    if (r0 < M) { rs0 = rs[r0]; if (ws) ws0 = ws[r0]; }
    if (r1 < M) { rs1 = rs[r1]; if (ws) ws1 = ws[r1]; }
#pragma unroll
    for (int nt = 0; nt < 2; nt++) {
        int c = wn + nt * 8 + 2 * tq;
        float bx = (c < N) ? __ldg(&bias[c]) : 0.f;
        float by = (c + 1 < N) ? __ldg(&bias[c + 1]) : 0.f;
        if (r0 < M) {
            float vx = ws0 * fmaxf(acc2[nt][0] * rs0 + bx, 0.f);
            float vy = ws0 * fmaxf(acc2[nt][1] * rs0 + by, 0.f);
            if (OUT_HALF) {
                if (c + 1 < N)
                    *(uint32_t*)((__half*)Cout + (size_t)r0 * N + c) = packh2(vx, vy);
            } else {
                if (c + 1 < N)
                    *(float2*)((float*)Cout + (size_t)r0 * N + c) = make_float2(vx, vy);
                else if (c < N)
                    ((float*)Cout)[(size_t)r0 * N + c] = vx;
            }
        }
        if (r1 < M) {
            float vx = ws1 * fmaxf(acc2[nt][2] * rs1 + bx, 0.f);
            float vy = ws1 * fmaxf(acc2[nt][3] * rs1 + by, 0.f);
            if (OUT_HALF) {
                if (c + 1 < N)
                    *(uint32_t*)((__half*)Cout + (size_t)r1 * N + c) = packh2(vx, vy);
            } else {
                if (c + 1 < N)
                    *(float2*)((float*)Cout + (size_t)r1 * N + c) = make_float2(vx, vy);
                else if (c < N)
                    ((float*)Cout)[(size_t)r1 * N + c] = vx;
            }
        }
    }
}

// ============================================================================
// fp16 TC GEMM (extra-wide, BK=64): CTA tile 128x256x64, 3-stage, stride 72.
// Used for GEMM1 (N=512, K=512).
// ============================================================================
__global__ void __launch_bounds__(256, 1)
gemm_f16w(const __half* __restrict__ A, const __half* __restrict__ Wt,
          const float* __restrict__ bias, __half* __restrict__ Cout,
          int M, int N, int K) {
    constexpr int SH = 72;
    constexpr int A_BYTES = 128 * SH * 2;
    constexpr int B_BYTES = 256 * SH * 2;
    constexpr int STAGE_BYTES = A_BYTES + B_BYTES;
    extern __shared__ char dsm[];
    uint32_t smem_u = (uint32_t)__cvta_generic_to_shared(dsm);

    const int tid = threadIdx.x;
    const int lane = tid & 31;
    const int warp = tid >> 5;
    const int wm = (warp >> 2) * 64;
    const int wn = (warp & 3) * 64;
    const int rowBase = blockIdx.y * 128;
    const int colBase = blockIdx.x * 256;
    const int KT = K / 64;

    const int lrow = lane & 7;
    const int sub = lane >> 3;
    const int subB = sub & 1;

    float acc[4][8][4];
#pragma unroll
    for (int i = 0; i < 4; i++)
#pragma unroll
        for (int j = 0; j < 8; j++)
#pragma unroll
            for (int q = 0; q < 4; q++) acc[i][j][q] = 0.0f;

    auto issue = [&](int stage, int kt) {
        const int k0 = kt * 64;
        uint32_t base = smem_u + stage * STAGE_BYTES;
#pragma unroll
        for (int i = 0; i < 4; i++) {
            int idx = tid + i * 256;
            int m = idx >> 3;
            int cq = idx & 7;
            const __half* gsrc = A + (size_t)(rowBase + m) * K + k0 + cq * 8;
            cp_async16(base + (m * SH + cq * 8) * 2, gsrc, (rowBase + m < M) ? 16 : 0);
        }
#pragma unroll
        for (int i = 0; i < 8; i++) {
            int idx = tid + i * 256;
            int n = idx >> 3;
            int cq = idx & 7;
            const __half* gsrc = Wt + (size_t)(colBase + n) * K + k0 + cq * 8;
            cp_async16(base + A_BYTES + (n * SH + cq * 8) * 2, gsrc, 16);
        }
    };

#pragma unroll
    for (int p = 0; p < 2; p++) {
        issue(p, p);
        asm volatile("cp.async.commit_group;\n" ::: "memory");
    }

    for (int kt = 0; kt < KT; kt++) {
        asm volatile("cp.async.wait_group 1;\n" ::: "memory");
        __syncthreads();
        const int stage = kt % 3;
        uint32_t As_u = smem_u + stage * STAGE_BYTES;
        uint32_t Bs_u = As_u + A_BYTES;

#pragma unroll
        for (int ks = 0; ks < 4; ks++) {
            const int kb = ks * 16;
            uint32_t a[4][4], b[8][2];
#pragma unroll
            for (int mt = 0; mt < 4; mt++) {
                int r = wm + mt * 16 + (sub & 1) * 8 + lrow;
                uint32_t addr = As_u + (r * SH + kb + (sub >> 1) * 8) * 2;
                asm volatile(
                    "ldmatrix.sync.aligned.m8n8.x4.shared.b16 {%0,%1,%2,%3}, [%4];"
                    : "=r"(a[mt][0]), "=r"(a[mt][1]), "=r"(a[mt][2]), "=r"(a[mt][3])
                    : "r"(addr));
            }
#pragma unroll
            for (int nt = 0; nt < 8; nt++) {
                int n = wn + nt * 8 + lrow;
                uint32_t addr = Bs_u + (n * SH + kb + subB * 8) * 2;
                asm volatile(
                    "ldmatrix.sync.aligned.m8n8.x2.shared.b16 {%0,%1}, [%2];"
                    : "=r"(b[nt][0]), "=r"(b[nt][1]) : "r"(addr));
            }
#pragma unroll
            for (int mt = 0; mt < 4; mt++)
#pragma unroll
                for (int nt = 0; nt < 8; nt++) {
                    asm volatile(
                        "mma.sync.aligned.m16n8k16.row.col.f32.f16.f16.f32 "
                        "{%0,%1,%2,%3}, {%4,%5,%6,%7}, {%8,%9}, {%0,%1,%2,%3};"
                        : "+f"(acc[mt][nt][0]), "+f"(acc[mt][nt][1]),
                          "+f"(acc[mt][nt][2]), "+f"(acc[mt][nt][3])
                        : "r"(a[mt][0]), "r"(a[mt][1]), "r"(a[mt][2]), "r"(a[mt][3]),
                          "r"(b[nt][0]), "r"(b[nt][1]));
                }
        }
        if (kt + 2 < KT) issue((kt + 2) % 3, kt + 2);
        asm volatile("cp.async.commit_group;\n" ::: "memory");
    }

    const int g = lane >> 2;
    const int tq = lane & 3;
#pragma unroll
    for (int mt = 0; mt < 4; mt++) {
        int r0 = rowBase + wm + mt * 16 + g;
        int r1 = r0 + 8;
#pragma unroll
        for (int nt = 0; nt < 8; nt++) {
            int c = colBase + wn + nt * 8 + 2 * tq;
            float bx = __ldg(&bias[c]);
            float by = __ldg(&bias[c + 1]);
            if (r0 < M)
                *(uint32_t*)(Cout + (size_t)r0 * N + c) =
                    packh2(fmaxf(acc[mt][nt][0] + bx, 0.f), fmaxf(acc[mt][nt][1] + by, 0.f));
            if (r1 < M)
                *(uint32_t*)(Cout + (size_t)r1 * N + c) =
                    packh2(fmaxf(acc[mt][nt][2] + bx, 0.f), fmaxf(acc[mt][nt][3] + by, 0.f));
        }
    }
}

// ============================================================================
// Fused GEMM2+GEMM3 (BK=64 mainloop): per 128-row slab,
//   h2 = relu(h1 @ W2t^T + b2)  kept in SMEM; hA = nsrc.*relu(h2@W3t^T+b3)
// ============================================================================
__global__ void __launch_bounds__(256, 1)
gemm_f16_23(const __half* __restrict__ A, const __half* __restrict__ W2t,
            const float* __restrict__ b2, const __half* __restrict__ W3t,
            const float* __restrict__ b3, const float* __restrict__ nsrc,
            __half* __restrict__ Cout, int M) {
    constexpr int K = 512;
    constexpr int SH = 72;
    constexpr int A_BYTES = 128 * SH * 2;
    constexpr int B_BYTES = 256 * SH * 2;
    constexpr int STAGE_BYTES = A_BYTES + B_BYTES;
    constexpr int W3_OFF = 3 * STAGE_BYTES;
    constexpr int S2 = 264;
    extern __shared__ char dsm[];
    uint32_t smem_u = (uint32_t)__cvta_generic_to_shared(dsm);
    uint32_t w3_u = smem_u + W3_OFF;
    uint32_t h2_u = smem_u;

    const int tid = threadIdx.x;
    const int lane = tid & 31;
    const int warp = tid >> 5;
    const int rowBase = blockIdx.y * 128;
    const int KT = K / 64;

    const int lrow = lane & 7;
    const int sub = lane >> 3;
    const int subB = sub & 1;
    const int g = lane >> 2;
    const int tq = lane & 3;

#pragma unroll
    for (int i = 0; i < 8; i++) {
        int idx = tid + i * 256;
        int n = idx >> 5;
        int cq = idx & 31;
        cp_async16(w3_u + (n * S2 + cq * 8) * 2, W3t + (size_t)n * 256 + cq * 8, 16);
    }
    asm volatile("cp.async.commit_group;\n" ::: "memory");

    const int wm = (warp >> 2) * 64;
    const int wn = (warp & 3) * 64;

    float acc[4][8][4];
#pragma unroll
    for (int i = 0; i < 4; i++)
#pragma unroll
        for (int j = 0; j < 8; j++)
#pragma unroll
            for (int q = 0; q < 4; q++) acc[i][j][q] = 0.0f;

    auto issue = [&](int stage, int kt) {
        const int k0 = kt * 64;
        uint32_t base = smem_u + stage * STAGE_BYTES;
#pragma unroll
        for (int i = 0; i < 4; i++) {
            int idx = tid + i * 256;
            int m = idx >> 3;
            int cq = idx & 7;
            const __half* gsrc = A + (size_t)(rowBase + m) * K + k0 + cq * 8;
            cp_async16(base + (m * SH + cq * 8) * 2, gsrc, (rowBase + m < M) ? 16 : 0);
        }
#pragma unroll
        for (int i = 0; i < 8; i++) {
            int idx = tid + i * 256;
            int n = idx >> 3;
            int cq = idx & 7;
            const __half* gsrc = W2t + (size_t)n * K + k0 + cq * 8;
            cp_async16(base + A_BYTES + (n * SH + cq * 8) * 2, gsrc, 16);
        }
    };

#pragma unroll
    for (int p = 0; p < 2; p++) {
        issue(p, p);
        asm volatile("cp.async.commit_group;\n" ::: "memory");
    }

    for (int kt = 0; kt < KT; kt++) {
        asm volatile("cp.async.wait_group 1;\n" ::: "memory");
        __syncthreads();
        const int stage = kt % 3;
        uint32_t As_u = smem_u + stage * STAGE_BYTES;
        uint32_t Bs_u = As_u + A_BYTES;

#pragma unroll
        for (int ks = 0; ks < 4; ks++) {
            const int kb = ks * 16;
            uint32_t a[4][4], b[8][2];
#pragma unroll
            for (int mt = 0; mt < 4; mt++) {
                int r = wm + mt * 16 + (sub & 1) * 8 + lrow;
                uint32_t addr = As_u + (r * SH + kb + (sub >> 1) * 8) * 2;
                asm volatile(
                    "ldmatrix.sync.aligned.m8n8.x4.shared.b16 {%0,%1,%2,%3}, [%4];"
                    : "=r"(a[mt][0]), "=r"(a[mt][1]), "=r"(a[mt][2]), "=r"(a[mt][3])
                    : "r"(addr));
            }
#pragma unroll
            for (int nt = 0; nt < 8; nt++) {
                int n = wn + nt * 8 + lrow;
                uint32_t addr = Bs_u + (n * SH + kb + subB * 8) * 2;
                asm volatile(
                    "ldmatrix.sync.aligned.m8n8.x2.shared.b16 {%0,%1}, [%2];"
                    : "=r"(b[nt][0]), "=r"(b[nt][1]) : "r"(addr));
            }
#pragma unroll
            for (int mt = 0; mt < 4; mt++)
#pragma unroll
                for (int nt = 0; nt < 8; nt++) {
                    asm volatile(
                        "mma.sync.aligned.m16n8k16.row.col.f32.f16.f16.f32 "
                        "{%0,%1,%2,%3}, {%4,%5,%6,%7}, {%8,%9}, {%0,%1,%2,%3};"
                        : "+f"(acc[mt][nt][0]), "+f"(acc[mt][nt][1]),
                          "+f"(acc[mt][nt][2]), "+f"(acc[mt][nt][3])
                        : "r"(a[mt][0]), "r"(a[mt][1]), "r"(a[mt][2]), "r"(a[mt][3]),
                          "r"(b[nt][0]), "r"(b[nt][1]));
                }
        }
        if (kt + 2 < KT) issue((kt + 2) % 3, kt + 2);
        asm volatile("cp.async.commit_group;\n" ::: "memory");
    }

    asm volatile("cp.async.wait_group 0;\n" ::: "memory");
    __syncthreads();
    __half* h2s = (__half*)dsm;
#pragma unroll
    for (int mt = 0; mt < 4; mt++) {
        int lr0 = wm + mt * 16 + g;
        int lr1 = lr0 + 8;
#pragma unroll
        for (int nt = 0; nt < 8; nt++) {
            int c = wn + nt * 8 + 2 * tq;
            float bx = __ldg(&b2[c]);
            float by = __ldg(&b2[c + 1]);
            *(uint32_t*)(h2s + lr0 * S2 + c) =
                packh2(fmaxf(acc[mt][nt][0] + bx, 0.f), fmaxf(acc[mt][nt][1] + by, 0.f));
            *(uint32_t*)(h2s + lr1 * S2 + c) =
                packh2(fmaxf(acc[mt][nt][2] + bx, 0.f), fmaxf(acc[mt][nt][3] + by, 0.f));
        }
    }
    __syncthreads();

    const int wm2 = (warp >> 1) * 32;
    const int wn2 = (warp & 1) * 32;

    float acc2[2][4][4];
#pragma unroll
    for (int i = 0; i < 2; i++)
#pragma unroll
        for (int j = 0; j < 4; j++)
#pragma unroll
            for (int q = 0; q < 4; q++) acc2[i][j][q] = 0.0f;

#pragma unroll
    for (int ks = 0; ks < 16; ks++) {
        const int kb = ks * 16;
        uint32_t a[2][4], b[4][2];
#pragma unroll
        for (int mt = 0; mt < 2; mt++) {
            int r = wm2 + mt * 16 + (sub & 1) * 8 + lrow;
            uint32_t addr = h2_u + (r * S2 + kb + (sub >> 1) * 8) * 2;
            asm volatile(
                "ldmatrix.sync.aligned.m8n8.x4.shared.b16 {%0,%1,%2,%3}, [%4];"
                : "=r"(a[mt][0]), "=r"(a[mt][1]), "=r"(a[mt][2]), "=r"(a[mt][3])
                : "r"(addr));
        }
#pragma unroll
        for (int nt = 0; nt < 4; nt++) {
            int n = wn2 + nt * 8 + lrow;
            uint32_t addr = w3_u + (n * S2 + kb + subB * 8) * 2;
            asm volatile(
                "ldmatrix.sync.aligned.m8n8.x2.shared.b16 {%0,%1}, [%2];"
                : "=r"(b[nt][0]), "=r"(b[nt][1]) : "r"(addr));
        }
#pragma unroll
        for (int mt = 0; mt < 2; mt++)
#pragma unroll
            for (int nt = 0; nt < 4; nt++) {
                asm volatile(
                    "mma.sync.aligned.m16n8k16.row.col.f32.f16.f16.f32 "
                    "{%0,%1,%2,%3}, {%4,%5,%6,%7}, {%8,%9}, {%0,%1,%2,%3};"
                    : "+f"(acc2[mt][nt][0]), "+f"(acc2[mt][nt][1]),
                      "+f"(acc2[mt][nt][2]), "+f"(acc2[mt][nt][3])
                    : "r"(a[mt][0]), "r"(a[mt][1]), "r"(a[mt][2]), "r"(a[mt][3]),
                      "r"(b[nt][0]), "r"(b[nt][1]));
            }
    }

#pragma unroll
    for (int mt = 0; mt < 2; mt++) {
        int r0 = rowBase + wm2 + mt * 16 + g;
        int r1 = r0 + 8;
        float w0 = (r0 < M) ? nsrc[r0] : 0.f;
        float w1 = (r1 < M) ? nsrc[r1] : 0.f;
#pragma unroll
        for (int nt = 0; nt < 4; nt++) {
            int c = wn2 + nt * 8 + 2 * tq;
            float bx = __ldg(&b3[c]);
            float by = __ldg(&b3[c + 1]);
            if (r0 < M)
                *(uint32_t*)(Cout + (size_t)r0 * 64 + c) =
                    packh2(w0 * fmaxf(acc2[mt][nt][0] + bx, 0.f),
                           w0 * fmaxf(acc2[mt][nt][1] + by, 0.f));
            if (r1 < M)
                *(uint32_t*)(Cout + (size_t)r1 * 64 + c) =
                    packh2(w1 * fmaxf(acc2[mt][nt][2] + bx, 0.f),
                           w1 * fmaxf(acc2[mt][nt][3] + by, 0.f));
        }
    }
}

// ---------------- host orchestration ---------------------------------------
extern "C" void kernel_launch(void* const* d_in, const int* in_sizes, int n_in,
                              void* d_out, int out_size) {
    const float* x   = (const float*)d_in[0];
    const int* src   = (const int*)d_in[1];
    const int* dst   = (const int*)d_in[2];
    const float* W1  = (const float*)d_in[3];
    const float* b1  = (const float*)d_in[4];
    const float* W2  = (const float*)d_in[5];
    const float* b2  = (const float*)d_in[6];
    const float* W3  = (const float*)d_in[7];
    const float* b3  = (const float*)d_in[8];
    const float* Wg1 = (const float*)d_in[9];
    const float* bg1 = (const float*)d_in[10];
    const float* Wg2 = (const float*)d_in[11];
    const float* bg2 = (const float*)d_in[12];
    const float* Wg3 = (const float*)d_in[13];
    const float* bg3 = (const float*)d_in[14];
    const float* Wg4 = (const float*)d_in[15];
    const float* bg4 = (const float*)d_in[16];
    float* out = (float*)d_out;

    float *h1, *h2, *hA, *hB, *degf, *nrm;
    int *cnt, *rowptr, *cursor, *bsum, *col;
    __half *w1t, *w2t, *w3t, *wgt;
    cudaGetSymbolAddress((void**)&h1, g_h1);
    cudaGetSymbolAddress((void**)&h2, g_h2);
    cudaGetSymbolAddress((void**)&hA, g_hA);
    cudaGetSymbolAddress((void**)&hB, g_hB);
    cudaGetSymbolAddress((void**)&degf, g_degf);
    cudaGetSymbolAddress((void**)&nrm, g_nrm);
    cudaGetSymbolAddress((void**)&cnt, g_cnt);
    cudaGetSymbolAddress((void**)&rowptr, g_rowptr);
    cudaGetSymbolAddress((void**)&cursor, g_cursor);
    cudaGetSymbolAddress((void**)&bsum, g_bsum);
    cudaGetSymbolAddress((void**)&col, g_col);
    cudaGetSymbolAddress((void**)&w1t, g_w1t);
    cudaGetSymbolAddress((void**)&w2t, g_w2t);
    cudaGetSymbolAddress((void**)&w3t, g_w3t);
    cudaGetSymbolAddress((void**)&wgt, g_wgt);

    __half* xh  = (__half*)h2;   // x fp16 staged in g_h2 (dead after GEMM1)
    __half* h1h = (__half*)h1;
    __half* hAh = (__half*)hA;
    __half* hBh = (__half*)hB;

    const float* nsrc = nrm;
    const float* ndst = nrm + NN;

    constexpr int SMEMW  = 3 * ((128 + 256) * 72 * 2);          // 165888
    constexpr int SMEM23 = 3 * ((128 + 256) * 72 * 2) + 64 * 264 * 2;  // 199680
    cudaFuncSetAttribute(gemm_f16w, cudaFuncAttributeMaxDynamicSharedMemorySize, SMEMW);
    cudaFuncSetAttribute(gemm_f16_23, cudaFuncAttributeMaxDynamicSharedMemorySize, SMEM23);

    // side stream + events, created once (host objects; no device allocation)
    static cudaStream_t s2 = nullptr;
    static cudaEvent_t evFork = nullptr, evW1 = nullptr, evB = nullptr;
    if (!s2) {
        cudaStreamCreateWithFlags(&s2, cudaStreamNonBlocking);
        cudaEventCreateWithFlags(&evFork, cudaEventDisableTiming);
        cudaEventCreateWithFlags(&evW1, cudaEventDisableTiming);
        cudaEventCreateWithFlags(&evB, cudaEventDisableTiming);
    }

    const int M = NN;
    const int NYT = (M + 127) / 128;
    const int fusedBlocks = (NN + 31) / 32;   // 3125

    // ---- fork side chain (weights + CSR) ----
    cudaEventRecord(evFork, 0);
    cudaStreamWaitEvent(s2, evFork, 0);
    wcvt_kernel<<<(512 * 512 + 255) / 256, 256, 0, s2>>>(W1, w1t, 512, 512, 512);
    cudaEventRecord(evW1, s2);
    wcvt_kernel<<<(512 * 256 + 255) / 256, 256, 0, s2>>>(W2, w2t, 512, 256, 256);
    zero_fi<<<(NN + 255) / 256, 256, 0, s2>>>(degf, cnt, NN);
    deg_hist_kernel<<<(NE + 255) / 256, 256, 0, s2>>>(src, dst, degf, cnt);
    scan1<<<NB_SCAN, 1024, 0, s2>>>(cnt, rowptr, bsum, degf, nrm);
    scan2<<<1, 128, 0, s2>>>(bsum);
    scan3<<<NB_SCAN, 1024, 0, s2>>>(rowptr, bsum, cursor);
    fill_csr<<<(NE + 255) / 256, 256, 0, s2>>>(src, dst, cursor, col);
    wcvt3g_kernel<<<(64 * 256 + 4 * 64 * 64 + 255) / 256, 256, 0, s2>>>(
        W3, w3t, Wg1, Wg2, Wg3, Wg4, wgt);
    cudaEventRecord(evB, s2);

    // ---- main chain ----
    cvt_f2h<<<(NN * 512 / 4 + 255) / 256, 256>>>(x, xh, NN * 512 / 4);
    cudaStreamWaitEvent(0, evW1, 0);
    gemm_f16w<<<dim3(2, NYT), 256, SMEMW>>>(xh, w1t, b1, h1h, M, 512, 512);
    cudaStreamWaitEvent(0, evB, 0);
    gemm_f16_23<<<dim3(1, NYT), 256, SMEM23>>>(h1h, w2t, b2, w3t, b3, nsrc, hAh, M);

    // GC layers: fused gather+GEMM, ping-pong hA <-> hB
    gcn_fused2<true><<<fusedBlocks, 256>>>(hAh, rowptr, col, wgt + 0 * 4096, bg1,
                                           ndst, nsrc, hBh, M, 64);
    gcn_fused2<true><<<fusedBlocks, 256>>>(hBh, rowptr, col, wgt + 1 * 4096, bg2,
                                           ndst, nsrc, hAh, M, 64);
    gcn_fused2<true><<<fusedBlocks, 256>>>(hAh, rowptr, col, wgt + 2 * 4096, bg3,
                                           ndst, nsrc, hBh, M, 64);
    gcn_fused2<false><<<fusedBlocks, 256>>>(hBh, rowptr, col, wgt + 3 * 4096, bg4,
                                            ndst, nullptr, out, M, 40);
}

// round 16
// speedup vs baseline: 1.1595x; 1.0232x over previous
#include <cuda_runtime.h>
#include <cuda_fp16.h>
#include <cstdint>

#define NN 100000
#define NE 1600000
#define NB_SCAN 98   // ceil(NN/1024)

// ---------------- scratch (device globals; no allocation allowed) ----------
__device__ float g_h1[(size_t)NN * 512];   // h1 as fp16 (aliased)
__device__ float g_h2[(size_t)NN * 256];   // xh (fp16) staged here (dead after GEMM1)
__device__ float g_hA[(size_t)NN * 64];    // fp16 node features (aliased)
__device__ float g_hB[(size_t)NN * 64];    // fp16 ping-pong (aliased)
__device__ float g_degf[NN];
__device__ float g_nrm[2 * NN];      // [0..NN)=norm_src, [NN..2NN)=norm_dst
__device__ int   g_cnt[NN];
__device__ int   g_rowptr[NN];
__device__ int   g_cursor[NN];
__device__ int   g_bsum[128];
__device__ int   g_col[NE];
__device__ __half g_w1t[512 * 512];
__device__ __half g_w2t[256 * 512];
__device__ __half g_w3t[64 * 256];
__device__ __half g_wgt[4][64 * 64];

// ---------------- utility kernels -------------------------------------------
__global__ void zero_fi(float* __restrict__ pf, int* __restrict__ pi, int n) {
    int i = blockIdx.x * blockDim.x + threadIdx.x;
    if (i < n) { pf[i] = 0.0f; pi[i] = 0; }
}
__global__ void deg_hist_kernel(const int* __restrict__ src, const int* __restrict__ dst,
                                float* __restrict__ degf, int* __restrict__ cnt) {
    int e = blockIdx.x * blockDim.x + threadIdx.x;
    if (e < NE) {
        atomicAdd(&degf[src[e]], 1.0f);
        atomicAdd(&cnt[dst[e]], 1);
    }
}

__device__ __forceinline__ uint32_t packh2(float lo, float hi) {
    uint32_t r;
    asm("cvt.rn.f16x2.f32 %0, %1, %2;" : "=r"(r) : "f"(hi), "f"(lo));
    return r;
}

__global__ void cvt_f2h(const float* __restrict__ in, __half* __restrict__ out, int n4) {
    int i = blockIdx.x * blockDim.x + threadIdx.x;
    if (i < n4) {
        float4 v = ((const float4*)in)[i];
        uint2 o;
        o.x = packh2(v.x, v.y);
        o.y = packh2(v.z, v.w);
        ((uint2*)out)[i] = o;
    }
}

__global__ void wcvt_kernel(const float* __restrict__ W, __half* __restrict__ Wt,
                            int K, int N, int Npad) {
    int i = blockIdx.x * blockDim.x + threadIdx.x;
    if (i < Npad * K) {
        int n = i / K, k = i % K;
        Wt[i] = (n < N) ? __float2half(W[(size_t)k * N + n]) : __half(0.f);
    }
}
__global__ void wcvt3g_kernel(const float* __restrict__ W3, __half* __restrict__ w3t,
                              const float* __restrict__ Wg1, const float* __restrict__ Wg2,
                              const float* __restrict__ Wg3, const float* __restrict__ Wg4,
                              __half* __restrict__ Wt) {
    int i = blockIdx.x * blockDim.x + threadIdx.x;
    if (i < 64 * 256) {
        int n = i / 256, k = i % 256;
        w3t[i] = __float2half(W3[(size_t)k * 64 + n]);
    } else if (i < 64 * 256 + 4 * 64 * 64) {
        int j = i - 64 * 256;
        int which = j >> 12;
        int r = j & 4095;
        int n = r >> 6, k = r & 63;
        const float* W = (which == 0) ? Wg1 : (which == 1) ? Wg2 : (which == 2) ? Wg3 : Wg4;
        int N = (which == 3) ? 40 : 64;
        Wt[j] = (n < N) ? __float2half(W[(size_t)k * N + n]) : __half(0.f);
    }
}

// ---------------- CSR build (scan1 also computes norms) ----------------------
__global__ void scan1(const int* __restrict__ cnt, int* __restrict__ excl,
                      int* __restrict__ bsum, const float* __restrict__ degf,
                      float* __restrict__ nrm) {
    __shared__ int sh[1024];
    int tid = threadIdx.x;
    int i = blockIdx.x * 1024 + tid;
    int v = (i < NN) ? cnt[i] : 0;
    if (i < NN) {
        nrm[i] = rsqrtf(fmaxf(degf[i], 1.0f));
        nrm[NN + i] = rsqrtf(fmaxf((float)v, 1.0f));
    }
    sh[tid] = v;
    __syncthreads();
    for (int off = 1; off < 1024; off <<= 1) {
        int t = (tid >= off) ? sh[tid - off] : 0;
        __syncthreads();
        sh[tid] += t;
        __syncthreads();
    }
    if (i < NN) excl[i] = sh[tid] - v;
    if (tid == 1023) bsum[blockIdx.x] = sh[1023];
}
__global__ void scan2(int* __restrict__ bsum) {
    __shared__ int sh[128];
    int tid = threadIdx.x;
    int v = (tid < NB_SCAN) ? bsum[tid] : 0;
    sh[tid] = v;
    __syncthreads();
    for (int off = 1; off < 128; off <<= 1) {
        int t = (tid >= off) ? sh[tid - off] : 0;
        __syncthreads();
        sh[tid] += t;
        __syncthreads();
    }
    if (tid < NB_SCAN) bsum[tid] = sh[tid] - v;
}
__global__ void scan3(int* __restrict__ excl, const int* __restrict__ bsum,
                      int* __restrict__ cursor) {
    int i = blockIdx.x * 1024 + threadIdx.x;
    if (i < NN) {
        int r = excl[i] + bsum[blockIdx.x];
        excl[i] = r;
        cursor[i] = r;
    }
}
__global__ void fill_csr(const int* __restrict__ src, const int* __restrict__ dst,
                         int* __restrict__ cursor, int* __restrict__ col) {
    int e = blockIdx.x * blockDim.x + threadIdx.x;
    if (e < NE) {
        int p = atomicAdd(&cursor[dst[e]], 1);
        col[p] = src[e];
    }
}

// ---------------- common async copy helper ----------------------------------
__device__ __forceinline__ void cp_async16(uint32_t saddr, const void* gaddr, int sz) {
    asm volatile("cp.async.cg.shared.global [%0], [%1], 16, %2;\n"
                 :: "r"(saddr), "l"(gaddr), "r"(sz));
}

// ============================================================================
// Fused GCN layer v2 (unchanged from R15).
// ============================================================================
template <bool OUT_HALF>
__global__ void __launch_bounds__(256, 4)
gcn_fused2(const __half* __restrict__ h, const int* __restrict__ rowptr,
           const int* __restrict__ col, const __half* __restrict__ Wt,
           const float* __restrict__ bias, const float* __restrict__ rs,
           const float* __restrict__ ws, void* __restrict__ Cout,
           int M, int N) {
    constexpr int SH = 72;
    __shared__ __align__(16) __half As[32 * SH];
    __shared__ __align__(16) __half Bs[64 * SH];
    uint32_t As_u = (uint32_t)__cvta_generic_to_shared(As);
    uint32_t Bs_u = (uint32_t)__cvta_generic_to_shared(Bs);

    const int tid = threadIdx.x;
    const int lane = tid & 31;
    const int warp = tid >> 5;
    const int nodeBase = blockIdx.x * 32;

#pragma unroll
    for (int i = 0; i < 2; i++) {
        int idx = tid + i * 256;
        int n = idx >> 3;
        int cq = idx & 7;
        cp_async16(Bs_u + (n * SH + cq * 8) * 2, Wt + (size_t)n * 64 + cq * 8, 16);
    }
    asm volatile("cp.async.commit_group;\n" ::: "memory");

    {
        int localRow = tid >> 3;
        int node = nodeBase + localRow;
        int c = tid & 7;
        float acc[8] = {0.f, 0.f, 0.f, 0.f, 0.f, 0.f, 0.f, 0.f};
        if (node < M) {
            int beg = __ldg(&rowptr[node]);
            int end = (node == NN - 1) ? NE : __ldg(&rowptr[node + 1]);
            int i = beg;
            for (; i + 3 < end; i += 4) {
                int s0 = __ldg(&col[i]);
                int s1 = __ldg(&col[i + 1]);
                int s2 = __ldg(&col[i + 2]);
                int s3 = __ldg(&col[i + 3]);
                uint4 v0 = ((const uint4*)(h + (size_t)s0 * 64))[c];
                uint4 v1 = ((const uint4*)(h + (size_t)s1 * 64))[c];
                uint4 v2 = ((const uint4*)(h + (size_t)s2 * 64))[c];
                uint4 v3 = ((const uint4*)(h + (size_t)s3 * 64))[c];
                const __half2* a0 = (const __half2*)&v0;
                const __half2* a1 = (const __half2*)&v1;
                const __half2* a2 = (const __half2*)&v2;
                const __half2* a3 = (const __half2*)&v3;
#pragma unroll
                for (int j = 0; j < 4; j++) {
                    float2 f0 = __half22float2(a0[j]);
                    float2 f1 = __half22float2(a1[j]);
                    float2 f2 = __half22float2(a2[j]);
                    float2 f3 = __half22float2(a3[j]);
                    acc[2 * j]     += (f0.x + f1.x) + (f2.x + f3.x);
                    acc[2 * j + 1] += (f0.y + f1.y) + (f2.y + f3.y);
                }
            }
            for (; i < end; i++) {
                int s = __ldg(&col[i]);
                uint4 v = ((const uint4*)(h + (size_t)s * 64))[c];
                const __half2* hv = (const __half2*)&v;
#pragma unroll
                for (int j = 0; j < 4; j++) {
                    float2 f = __half22float2(hv[j]);
                    acc[2 * j] += f.x;
                    acc[2 * j + 1] += f.y;
                }
            }
        }
        uint4 o;
        o.x = packh2(acc[0], acc[1]);
        o.y = packh2(acc[2], acc[3]);
        o.z = packh2(acc[4], acc[5]);
        o.w = packh2(acc[6], acc[7]);
        *(uint4*)(As + localRow * SH + c * 8) = o;
    }
    asm volatile("cp.async.wait_group 0;\n" ::: "memory");
    __syncthreads();

    const int wm = (warp >> 2) * 16;
    const int wn = (warp & 3) * 16;
    const int lrow = lane & 7;
    const int sub = lane >> 3;
    const int subB = sub & 1;

    float acc2[2][4];
#pragma unroll
    for (int j = 0; j < 2; j++)
#pragma unroll
        for (int q = 0; q < 4; q++) acc2[j][q] = 0.0f;

#pragma unroll
    for (int ks = 0; ks < 4; ks++) {
        const int kb = ks * 16;
        uint32_t a[4], b[2][2];
        {
            int r = wm + (sub & 1) * 8 + lrow;
            uint32_t addr = As_u + (r * SH + kb + (sub >> 1) * 8) * 2;
            asm volatile(
                "ldmatrix.sync.aligned.m8n8.x4.shared.b16 {%0,%1,%2,%3}, [%4];"
                : "=r"(a[0]), "=r"(a[1]), "=r"(a[2]), "=r"(a[3]) : "r"(addr));
        }
#pragma unroll
        for (int nt = 0; nt < 2; nt++) {
            int n = wn + nt * 8 + lrow;
            uint32_t addr = Bs_u + (n * SH + kb + subB * 8) * 2;
            asm volatile(
                "ldmatrix.sync.aligned.m8n8.x2.shared.b16 {%0,%1}, [%2];"
                : "=r"(b[nt][0]), "=r"(b[nt][1]) : "r"(addr));
        }
#pragma unroll
        for (int nt = 0; nt < 2; nt++) {
            asm volatile(
                "mma.sync.aligned.m16n8k16.row.col.f32.f16.f16.f32 "
                "{%0,%1,%2,%3}, {%4,%5,%6,%7}, {%8,%9}, {%0,%1,%2,%3};"
                : "+f"(acc2[nt][0]), "+f"(acc2[nt][1]),
                  "+f"(acc2[nt][2]), "+f"(acc2[nt][3])
                : "r"(a[0]), "r"(a[1]), "r"(a[2]), "r"(a[3]),
                  "r"(b[nt][0]), "r"(b[nt][1]));
        }
    }

    const int g = lane >> 2;
    const int tq = lane & 3;
    int r0 = nodeBase + wm + g;
    int r1 = r0 + 8;
    float rs0 = 1.f, rs1 = 1.f, ws0 = 1.f, ws1 = 1.f;
    if (r0 < M) { rs0 = rs[r0]; if (ws) ws0 = ws[r0]; }
    if (r1 < M) { rs1 = rs[r1]; if (ws) ws1 = ws[r1]; }
#pragma unroll
    for (int nt = 0; nt < 2; nt++) {
        int c = wn + nt * 8 + 2 * tq;
        float bx = (c < N) ? __ldg(&bias[c]) : 0.f;
        float by = (c + 1 < N) ? __ldg(&bias[c + 1]) : 0.f;
        if (r0 < M) {
            float vx = ws0 * fmaxf(acc2[nt][0] * rs0 + bx, 0.f);
            float vy = ws0 * fmaxf(acc2[nt][1] * rs0 + by, 0.f);
            if (OUT_HALF) {
                if (c + 1 < N)
                    *(uint32_t*)((__half*)Cout + (size_t)r0 * N + c) = packh2(vx, vy);
            } else {
                if (c + 1 < N)
                    *(float2*)((float*)Cout + (size_t)r0 * N + c) = make_float2(vx, vy);
                else if (c < N)
                    ((float*)Cout)[(size_t)r0 * N + c] = vx;
            }
        }
        if (r1 < M) {
            float vx = ws1 * fmaxf(acc2[nt][2] * rs1 + bx, 0.f);
            float vy = ws1 * fmaxf(acc2[nt][3] * rs1 + by, 0.f);
            if (OUT_HALF) {
                if (c + 1 < N)
                    *(uint32_t*)((__half*)Cout + (size_t)r1 * N + c) = packh2(vx, vy);
            } else {
                if (c + 1 < N)
                    *(float2*)((float*)Cout + (size_t)r1 * N + c) = make_float2(vx, vy);
                else if (c < N)
                    ((float*)Cout)[(size_t)r1 * N + c] = vx;
            }
        }
    }
}

// ============================================================================
// GEMM1: fp16 TC, CTA tile 128x128x64, warp tile 64x32 (2x4 warps), 3-stage,
// stride 72, occ 2 (regs <= 128). Grid (N/128, ceil(M/128)).
// ============================================================================
__global__ void __launch_bounds__(256, 2)
gemm_f16n(const __half* __restrict__ A, const __half* __restrict__ Wt,
          const float* __restrict__ bias, __half* __restrict__ Cout,
          int M, int N, int K) {
    constexpr int SH = 72;
    constexpr int A_BYTES = 128 * SH * 2;       // 18432
    constexpr int B_BYTES = 128 * SH * 2;       // 18432
    constexpr int STAGE_BYTES = A_BYTES + B_BYTES;   // 36864
    extern __shared__ char dsm[];
    uint32_t smem_u = (uint32_t)__cvta_generic_to_shared(dsm);

    const int tid = threadIdx.x;
    const int lane = tid & 31;
    const int warp = tid >> 5;
    const int wm = (warp >> 2) * 64;   // 2 row groups
    const int wn = (warp & 3) * 32;    // 4 col groups
    const int rowBase = blockIdx.y * 128;
    const int colBase = blockIdx.x * 128;
    const int KT = K / 64;

    const int lrow = lane & 7;
    const int sub = lane >> 3;
    const int subB = sub & 1;

    float acc[4][4][4];
#pragma unroll
    for (int i = 0; i < 4; i++)
#pragma unroll
        for (int j = 0; j < 4; j++)
#pragma unroll
            for (int q = 0; q < 4; q++) acc[i][j][q] = 0.0f;

    // loaders per K64 tile: A = 1024 chunks (4/thr), B = 1024 chunks (4/thr)
    auto issue = [&](int stage, int kt) {
        const int k0 = kt * 64;
        uint32_t base = smem_u + stage * STAGE_BYTES;
#pragma unroll
        for (int i = 0; i < 4; i++) {
            int idx = tid + i * 256;
            int m = idx >> 3;
            int cq = idx & 7;
            const __half* gsrc = A + (size_t)(rowBase + m) * K + k0 + cq * 8;
            cp_async16(base + (m * SH + cq * 8) * 2, gsrc, (rowBase + m < M) ? 16 : 0);
        }
#pragma unroll
        for (int i = 0; i < 4; i++) {
            int idx = tid + i * 256;
            int n = idx >> 3;
            int cq = idx & 7;
            const __half* gsrc = Wt + (size_t)(colBase + n) * K + k0 + cq * 8;
            cp_async16(base + A_BYTES + (n * SH + cq * 8) * 2, gsrc, 16);
        }
    };

#pragma unroll
    for (int p = 0; p < 2; p++) {
        issue(p, p);
        asm volatile("cp.async.commit_group;\n" ::: "memory");
    }

    for (int kt = 0; kt < KT; kt++) {
        asm volatile("cp.async.wait_group 1;\n" ::: "memory");
        __syncthreads();
        const int stage = kt % 3;
        uint32_t As_u = smem_u + stage * STAGE_BYTES;
        uint32_t Bs_u = As_u + A_BYTES;

#pragma unroll
        for (int ks = 0; ks < 4; ks++) {
            const int kb = ks * 16;
            uint32_t a[4][4], b[4][2];
#pragma unroll
            for (int mt = 0; mt < 4; mt++) {
                int r = wm + mt * 16 + (sub & 1) * 8 + lrow;
                uint32_t addr = As_u + (r * SH + kb + (sub >> 1) * 8) * 2;
                asm volatile(
                    "ldmatrix.sync.aligned.m8n8.x4.shared.b16 {%0,%1,%2,%3}, [%4];"
                    : "=r"(a[mt][0]), "=r"(a[mt][1]), "=r"(a[mt][2]), "=r"(a[mt][3])
                    : "r"(addr));
            }
#pragma unroll
            for (int nt = 0; nt < 4; nt++) {
                int n = wn + nt * 8 + lrow;
                uint32_t addr = Bs_u + (n * SH + kb + subB * 8) * 2;
                asm volatile(
                    "ldmatrix.sync.aligned.m8n8.x2.shared.b16 {%0,%1}, [%2];"
                    : "=r"(b[nt][0]), "=r"(b[nt][1]) : "r"(addr));
            }
#pragma unroll
            for (int mt = 0; mt < 4; mt++)
#pragma unroll
                for (int nt = 0; nt < 4; nt++) {
                    asm volatile(
                        "mma.sync.aligned.m16n8k16.row.col.f32.f16.f16.f32 "
                        "{%0,%1,%2,%3}, {%4,%5,%6,%7}, {%8,%9}, {%0,%1,%2,%3};"
                        : "+f"(acc[mt][nt][0]), "+f"(acc[mt][nt][1]),
                          "+f"(acc[mt][nt][2]), "+f"(acc[mt][nt][3])
                        : "r"(a[mt][0]), "r"(a[mt][1]), "r"(a[mt][2]), "r"(a[mt][3]),
                          "r"(b[nt][0]), "r"(b[nt][1]));
                }
        }
        if (kt + 2 < KT) issue((kt + 2) % 3, kt + 2);
        asm volatile("cp.async.commit_group;\n" ::: "memory");
    }

    const int g = lane >> 2;
    const int tq = lane & 3;
#pragma unroll
    for (int mt = 0; mt < 4; mt++) {
        int r0 = rowBase + wm + mt * 16 + g;
        int r1 = r0 + 8;
#pragma unroll
        for (int nt = 0; nt < 4; nt++) {
            int c = colBase + wn + nt * 8 + 2 * tq;
            float bx = __ldg(&bias[c]);
            float by = __ldg(&bias[c + 1]);
            if (r0 < M)
                *(uint32_t*)(Cout + (size_t)r0 * N + c) =
                    packh2(fmaxf(acc[mt][nt][0] + bx, 0.f), fmaxf(acc[mt][nt][1] + by, 0.f));
            if (r1 < M)
                *(uint32_t*)(Cout + (size_t)r1 * N + c) =
                    packh2(fmaxf(acc[mt][nt][2] + bx, 0.f), fmaxf(acc[mt][nt][3] + by, 0.f));
        }
    }
}

// ============================================================================
// Fused GEMM2+GEMM3 (BK=64 mainloop, unchanged from R14/R15).
// ============================================================================
__global__ void __launch_bounds__(256, 1)
gemm_f16_23(const __half* __restrict__ A, const __half* __restrict__ W2t,
            const float* __restrict__ b2, const __half* __restrict__ W3t,
            const float* __restrict__ b3, const float* __restrict__ nsrc,
            __half* __restrict__ Cout, int M) {
    constexpr int K = 512;
    constexpr int SH = 72;
    constexpr int A_BYTES = 128 * SH * 2;
    constexpr int B_BYTES = 256 * SH * 2;
    constexpr int STAGE_BYTES = A_BYTES + B_BYTES;
    constexpr int W3_OFF = 3 * STAGE_BYTES;
    constexpr int S2 = 264;
    extern __shared__ char dsm[];
    uint32_t smem_u = (uint32_t)__cvta_generic_to_shared(dsm);
    uint32_t w3_u = smem_u + W3_OFF;
    uint32_t h2_u = smem_u;

    const int tid = threadIdx.x;
    const int lane = tid & 31;
    const int warp = tid >> 5;
    const int rowBase = blockIdx.y * 128;
    const int KT = K / 64;

    const int lrow = lane & 7;
    const int sub = lane >> 3;
    const int subB = sub & 1;
    const int g = lane >> 2;
    const int tq = lane & 3;

#pragma unroll
    for (int i = 0; i < 8; i++) {
        int idx = tid + i * 256;
        int n = idx >> 5;
        int cq = idx & 31;
        cp_async16(w3_u + (n * S2 + cq * 8) * 2, W3t + (size_t)n * 256 + cq * 8, 16);
    }
    asm volatile("cp.async.commit_group;\n" ::: "memory");

    const int wm = (warp >> 2) * 64;
    const int wn = (warp & 3) * 64;

    float acc[4][8][4];
#pragma unroll
    for (int i = 0; i < 4; i++)
#pragma unroll
        for (int j = 0; j < 8; j++)
#pragma unroll
            for (int q = 0; q < 4; q++) acc[i][j][q] = 0.0f;

    auto issue = [&](int stage, int kt) {
        const int k0 = kt * 64;
        uint32_t base = smem_u + stage * STAGE_BYTES;
#pragma unroll
        for (int i = 0; i < 4; i++) {
            int idx = tid + i * 256;
            int m = idx >> 3;
            int cq = idx & 7;
            const __half* gsrc = A + (size_t)(rowBase + m) * K + k0 + cq * 8;
            cp_async16(base + (m * SH + cq * 8) * 2, gsrc, (rowBase + m < M) ? 16 : 0);
        }
#pragma unroll
        for (int i = 0; i < 8; i++) {
            int idx = tid + i * 256;
            int n = idx >> 3;
            int cq = idx & 7;
            const __half* gsrc = W2t + (size_t)n * K + k0 + cq * 8;
            cp_async16(base + A_BYTES + (n * SH + cq * 8) * 2, gsrc, 16);
        }
    };

#pragma unroll
    for (int p = 0; p < 2; p++) {
        issue(p, p);
        asm volatile("cp.async.commit_group;\n" ::: "memory");
    }

    for (int kt = 0; kt < KT; kt++) {
        asm volatile("cp.async.wait_group 1;\n" ::: "memory");
        __syncthreads();
        const int stage = kt % 3;
        uint32_t As_u = smem_u + stage * STAGE_BYTES;
        uint32_t Bs_u = As_u + A_BYTES;

#pragma unroll
        for (int ks = 0; ks < 4; ks++) {
            const int kb = ks * 16;
            uint32_t a[4][4], b[8][2];
#pragma unroll
            for (int mt = 0; mt < 4; mt++) {
                int r = wm + mt * 16 + (sub & 1) * 8 + lrow;
                uint32_t addr = As_u + (r * SH + kb + (sub >> 1) * 8) * 2;
                asm volatile(
                    "ldmatrix.sync.aligned.m8n8.x4.shared.b16 {%0,%1,%2,%3}, [%4];"
                    : "=r"(a[mt][0]), "=r"(a[mt][1]), "=r"(a[mt][2]), "=r"(a[mt][3])
                    : "r"(addr));
            }
#pragma unroll
            for (int nt = 0; nt < 8; nt++) {
                int n = wn + nt * 8 + lrow;
                uint32_t addr = Bs_u + (n * SH + kb + subB * 8) * 2;
                asm volatile(
                    "ldmatrix.sync.aligned.m8n8.x2.shared.b16 {%0,%1}, [%2];"
                    : "=r"(b[nt][0]), "=r"(b[nt][1]) : "r"(addr));
            }
#pragma unroll
            for (int mt = 0; mt < 4; mt++)
#pragma unroll
                for (int nt = 0; nt < 8; nt++) {
                    asm volatile(
                        "mma.sync.aligned.m16n8k16.row.col.f32.f16.f16.f32 "
                        "{%0,%1,%2,%3}, {%4,%5,%6,%7}, {%8,%9}, {%0,%1,%2,%3};"
                        : "+f"(acc[mt][nt][0]), "+f"(acc[mt][nt][1]),
                          "+f"(acc[mt][nt][2]), "+f"(acc[mt][nt][3])
                        : "r"(a[mt][0]), "r"(a[mt][1]), "r"(a[mt][2]), "r"(a[mt][3]),
                          "r"(b[nt][0]), "r"(b[nt][1]));
                }
        }
        if (kt + 2 < KT) issue((kt + 2) % 3, kt + 2);
        asm volatile("cp.async.commit_group;\n" ::: "memory");
    }

    asm volatile("cp.async.wait_group 0;\n" ::: "memory");
    __syncthreads();
    __half* h2s = (__half*)dsm;
#pragma unroll
    for (int mt = 0; mt < 4; mt++) {
        int lr0 = wm + mt * 16 + g;
        int lr1 = lr0 + 8;
#pragma unroll
        for (int nt = 0; nt < 8; nt++) {
            int c = wn + nt * 8 + 2 * tq;
            float bx = __ldg(&b2[c]);
            float by = __ldg(&b2[c + 1]);
            *(uint32_t*)(h2s + lr0 * S2 + c) =
                packh2(fmaxf(acc[mt][nt][0] + bx, 0.f), fmaxf(acc[mt][nt][1] + by, 0.f));
            *(uint32_t*)(h2s + lr1 * S2 + c) =
                packh2(fmaxf(acc[mt][nt][2] + bx, 0.f), fmaxf(acc[mt][nt][3] + by, 0.f));
        }
    }
    __syncthreads();

    const int wm2 = (warp >> 1) * 32;
    const int wn2 = (warp & 1) * 32;

    float acc2[2][4][4];
#pragma unroll
    for (int i = 0; i < 2; i++)
#pragma unroll
        for (int j = 0; j < 4; j++)
#pragma unroll
            for (int q = 0; q < 4; q++) acc2[i][j][q] = 0.0f;

#pragma unroll
    for (int ks = 0; ks < 16; ks++) {
        const int kb = ks * 16;
        uint32_t a[2][4], b[4][2];
#pragma unroll
        for (int mt = 0; mt < 2; mt++) {
            int r = wm2 + mt * 16 + (sub & 1) * 8 + lrow;
            uint32_t addr = h2_u + (r * S2 + kb + (sub >> 1) * 8) * 2;
            asm volatile(
                "ldmatrix.sync.aligned.m8n8.x4.shared.b16 {%0,%1,%2,%3}, [%4];"
                : "=r"(a[mt][0]), "=r"(a[mt][1]), "=r"(a[mt][2]), "=r"(a[mt][3])
                : "r"(addr));
        }
#pragma unroll
        for (int nt = 0; nt < 4; nt++) {
            int n = wn2 + nt * 8 + lrow;
            uint32_t addr = w3_u + (n * S2 + kb + subB * 8) * 2;
            asm volatile(
                "ldmatrix.sync.aligned.m8n8.x2.shared.b16 {%0,%1}, [%2];"
                : "=r"(b[nt][0]), "=r"(b[nt][1]) : "r"(addr));
        }
#pragma unroll
        for (int mt = 0; mt < 2; mt++)
#pragma unroll
            for (int nt = 0; nt < 4; nt++) {
                asm volatile(
                    "mma.sync.aligned.m16n8k16.row.col.f32.f16.f16.f32 "
                    "{%0,%1,%2,%3}, {%4,%5,%6,%7}, {%8,%9}, {%0,%1,%2,%3};"
                    : "+f"(acc2[mt][nt][0]), "+f"(acc2[mt][nt][1]),
                      "+f"(acc2[mt][nt][2]), "+f"(acc2[mt][nt][3])
                    : "r"(a[mt][0]), "r"(a[mt][1]), "r"(a[mt][2]), "r"(a[mt][3]),
                      "r"(b[nt][0]), "r"(b[nt][1]));
            }
    }

#pragma unroll
    for (int mt = 0; mt < 2; mt++) {
        int r0 = rowBase + wm2 + mt * 16 + g;
        int r1 = r0 + 8;
        float w0 = (r0 < M) ? nsrc[r0] : 0.f;
        float w1 = (r1 < M) ? nsrc[r1] : 0.f;
#pragma unroll
        for (int nt = 0; nt < 4; nt++) {
            int c = wn2 + nt * 8 + 2 * tq;
            float bx = __ldg(&b3[c]);
            float by = __ldg(&b3[c + 1]);
            if (r0 < M)
                *(uint32_t*)(Cout + (size_t)r0 * 64 + c) =
                    packh2(w0 * fmaxf(acc2[mt][nt][0] + bx, 0.f),
                           w0 * fmaxf(acc2[mt][nt][1] + by, 0.f));
            if (r1 < M)
                *(uint32_t*)(Cout + (size_t)r1 * 64 + c) =
                    packh2(w1 * fmaxf(acc2[mt][nt][2] + bx, 0.f),
                           w1 * fmaxf(acc2[mt][nt][3] + by, 0.f));
        }
    }
}

// ---------------- host orchestration ---------------------------------------
extern "C" void kernel_launch(void* const* d_in, const int* in_sizes, int n_in,
                              void* d_out, int out_size) {
    const float* x   = (const float*)d_in[0];
    const int* src   = (const int*)d_in[1];
    const int* dst   = (const int*)d_in[2];
    const float* W1  = (const float*)d_in[3];
    const float* b1  = (const float*)d_in[4];
    const float* W2  = (const float*)d_in[5];
    const float* b2  = (const float*)d_in[6];
    const float* W3  = (const float*)d_in[7];
    const float* b3  = (const float*)d_in[8];
    const float* Wg1 = (const float*)d_in[9];
    const float* bg1 = (const float*)d_in[10];
    const float* Wg2 = (const float*)d_in[11];
    const float* bg2 = (const float*)d_in[12];
    const float* Wg3 = (const float*)d_in[13];
    const float* bg3 = (const float*)d_in[14];
    const float* Wg4 = (const float*)d_in[15];
    const float* bg4 = (const float*)d_in[16];
    float* out = (float*)d_out;

    float *h1, *h2, *hA, *hB, *degf, *nrm;
    int *cnt, *rowptr, *cursor, *bsum, *col;
    __half *w1t, *w2t, *w3t, *wgt;
    cudaGetSymbolAddress((void**)&h1, g_h1);
    cudaGetSymbolAddress((void**)&h2, g_h2);
    cudaGetSymbolAddress((void**)&hA, g_hA);
    cudaGetSymbolAddress((void**)&hB, g_hB);
    cudaGetSymbolAddress((void**)&degf, g_degf);
    cudaGetSymbolAddress((void**)&nrm, g_nrm);
    cudaGetSymbolAddress((void**)&cnt, g_cnt);
    cudaGetSymbolAddress((void**)&rowptr, g_rowptr);
    cudaGetSymbolAddress((void**)&cursor, g_cursor);
    cudaGetSymbolAddress((void**)&bsum, g_bsum);
    cudaGetSymbolAddress((void**)&col, g_col);
    cudaGetSymbolAddress((void**)&w1t, g_w1t);
    cudaGetSymbolAddress((void**)&w2t, g_w2t);
    cudaGetSymbolAddress((void**)&w3t, g_w3t);
    cudaGetSymbolAddress((void**)&wgt, g_wgt);

    __half* xh  = (__half*)h2;   // x fp16 staged in g_h2 (dead after GEMM1)
    __half* h1h = (__half*)h1;
    __half* hAh = (__half*)hA;
    __half* hBh = (__half*)hB;

    const float* nsrc = nrm;
    const float* ndst = nrm + NN;

    constexpr int SMEMN  = 3 * ((128 + 128) * 72 * 2);          // 110592
    constexpr int SMEM23 = 3 * ((128 + 256) * 72 * 2) + 64 * 264 * 2;  // 199680
    cudaFuncSetAttribute(gemm_f16n, cudaFuncAttributeMaxDynamicSharedMemorySize, SMEMN);
    cudaFuncSetAttribute(gemm_f16_23, cudaFuncAttributeMaxDynamicSharedMemorySize, SMEM23);

    // side stream + events, created once (host objects; no device allocation)
    static cudaStream_t s2 = nullptr;
    static cudaEvent_t evFork = nullptr, evW1 = nullptr, evB = nullptr;
    if (!s2) {
        cudaStreamCreateWithFlags(&s2, cudaStreamNonBlocking);
        cudaEventCreateWithFlags(&evFork, cudaEventDisableTiming);
        cudaEventCreateWithFlags(&evW1, cudaEventDisableTiming);
        cudaEventCreateWithFlags(&evB, cudaEventDisableTiming);
    }

    const int M = NN;
    const int NYT = (M + 127) / 128;
    const int fusedBlocks = (NN + 31) / 32;   // 3125

    // ---- fork side chain (weights + CSR) ----
    cudaEventRecord(evFork, 0);
    cudaStreamWaitEvent(s2, evFork, 0);
    wcvt_kernel<<<(512 * 512 + 255) / 256, 256, 0, s2>>>(W1, w1t, 512, 512, 512);
    cudaEventRecord(evW1, s2);
    wcvt_kernel<<<(512 * 256 + 255) / 256, 256, 0, s2>>>(W2, w2t, 512, 256, 256);
    zero_fi<<<(NN + 255) / 256, 256, 0, s2>>>(degf, cnt, NN);
    deg_hist_kernel<<<(NE + 255) / 256, 256, 0, s2>>>(src, dst, degf, cnt);
    scan1<<<NB_SCAN, 1024, 0, s2>>>(cnt, rowptr, bsum, degf, nrm);
    scan2<<<1, 128, 0, s2>>>(bsum);
    scan3<<<NB_SCAN, 1024, 0, s2>>>(rowptr, bsum, cursor);
    fill_csr<<<(NE + 255) / 256, 256, 0, s2>>>(src, dst, cursor, col);
    wcvt3g_kernel<<<(64 * 256 + 4 * 64 * 64 + 255) / 256, 256, 0, s2>>>(
        W3, w3t, Wg1, Wg2, Wg3, Wg4, wgt);
    cudaEventRecord(evB, s2);

    // ---- main chain ----
    cvt_f2h<<<(NN * 512 / 4 + 255) / 256, 256>>>(x, xh, NN * 512 / 4);
    cudaStreamWaitEvent(0, evW1, 0);
    gemm_f16n<<<dim3(4, NYT), 256, SMEMN>>>(xh, w1t, b1, h1h, M, 512, 512);
    cudaStreamWaitEvent(0, evB, 0);
    gemm_f16_23<<<dim3(1, NYT), 256, SMEM23>>>(h1h, w2t, b2, w3t, b3, nsrc, hAh, M);

    // GC layers: fused gather+GEMM, ping-pong hA <-> hB
    gcn_fused2<true><<<fusedBlocks, 256>>>(hAh, rowptr, col, wgt + 0 * 4096, bg1,
                                           ndst, nsrc, hBh, M, 64);
    gcn_fused2<true><<<fusedBlocks, 256>>>(hBh, rowptr, col, wgt + 1 * 4096, bg2,
                                           ndst, nsrc, hAh, M, 64);
    gcn_fused2<true><<<fusedBlocks, 256>>>(hAh, rowptr, col, wgt + 2 * 4096, bg3,
                                           ndst, nsrc, hBh, M, 64);
    gcn_fused2<false><<<fusedBlocks, 256>>>(hBh, rowptr, col, wgt + 3 * 4096, bg4,
                                            ndst, nullptr, out, M, 40);
}